// round 4
// baseline (speedup 1.0000x reference)
#include <cuda_runtime.h>
#include <cuda_bf16.h>
#include <cstdint>
#include <cstddef>

// ===========================================================================
// FeedForward via mma.sync bf16 split-precision (C = AhBh + AhBl + AlBh)
// Plane-major activation layout; cp.async double-buffered GEMM pipeline.
//   features -> split planes: fs [M,256] hi/lo, fv[d] [M,128] hi/lo
//   pre (fp32): pre_s [M,768] @0, pre_v[d] [M,256] @ M*768 + d*M*256
//   h (bf16):   hs hi@0 [M,512], hs lo@M*512, hv_hi[d]@M*1024+d*M*256,
//               hv_lo[d]@M*1792+d*M*256
// ===========================================================================

#define MROWS 100000

// ------------------------------- scratch -----------------------------------
__device__ float g_pre[(size_t)MROWS * 1536];
__device__ __nv_bfloat16 g_hbuf[(size_t)MROWS * 2560];
__device__ __nv_bfloat16 g_feat[(size_t)MROWS * 1280];
#define NPART 512
__device__ float g_psum[NPART * 256];
__device__ float g_psq[NPART * 640];
__device__ float g_scale[640];
__device__ float g_shift[640];
#define WTOT 933888
__device__ __align__(256) __nv_bfloat16 g_wbuf[2 * WTOT];

// --------------------------- helpers ---------------------------------------
__device__ __forceinline__ uint32_t smem_to_u32(const void* p) {
    uint32_t a;
    asm("{ .reg .u64 t; cvta.to.shared.u64 t, %1; cvt.u32.u64 %0, t; }" : "=r"(a) : "l"(p));
    return a;
}
__device__ __forceinline__ void ldm4(uint32_t& r0, uint32_t& r1, uint32_t& r2, uint32_t& r3,
                                     uint32_t addr) {
    asm volatile("ldmatrix.sync.aligned.m8n8.x4.shared.b16 {%0,%1,%2,%3}, [%4];"
                 : "=r"(r0), "=r"(r1), "=r"(r2), "=r"(r3) : "r"(addr));
}
__device__ __forceinline__ void mma16816(float* c, const uint32_t* a, const uint32_t* b) {
    asm volatile(
        "mma.sync.aligned.m16n8k16.row.col.f32.bf16.bf16.f32 "
        "{%0,%1,%2,%3}, {%4,%5,%6,%7}, {%8,%9}, {%0,%1,%2,%3};"
        : "+f"(c[0]), "+f"(c[1]), "+f"(c[2]), "+f"(c[3])
        : "r"(a[0]), "r"(a[1]), "r"(a[2]), "r"(a[3]), "r"(b[0]), "r"(b[1]));
}
#define CP_ASYNC16(dst, src, sz) \
    asm volatile("cp.async.cg.shared.global [%0], [%1], 16, %2;" \
                 :: "r"(dst), "l"(src), "r"(sz) : "memory")
#define CP_COMMIT asm volatile("cp.async.commit_group;" ::: "memory")
#define CP_WAIT1 asm volatile("cp.async.wait_group 1;" ::: "memory")
#define CP_WAIT0 asm volatile("cp.async.wait_group 0;" ::: "memory")

// ---------------------------------------------------------------------------
// Weight prep: W[K,N] fp32 -> hi/lo bf16 [N,K] K-major, scale folded in.
// ---------------------------------------------------------------------------
__global__ void conv_w_kernel(const float* __restrict__ W, int K, int N, float scale,
                              __nv_bfloat16* __restrict__ hi, __nv_bfloat16* __restrict__ lo) {
    int idx = blockIdx.x * blockDim.x + threadIdx.x;
    if (idx >= N * K) return;
    int n = idx / K, k = idx % K;
    float v = W[k * N + n] * scale;
    __nv_bfloat16 h = __float2bfloat16(v);
    hi[idx] = h;
    lo[idx] = __float2bfloat16(v - __bfloat162float(h));
}

// ---------------------------------------------------------------------------
// Features -> split plane-major bf16
// ---------------------------------------------------------------------------
__global__ void conv_feat_kernel(const float* __restrict__ F, __nv_bfloat16* __restrict__ out,
                                 int M) {
    size_t idx = (size_t)blockIdx.x * blockDim.x + threadIdx.x;
    size_t total = (size_t)M * 640;
    if (idx >= total) return;
    int c = (int)(idx % 640);
    size_t r = idx / 640;
    float v;
    size_t hi_off, lo_off;
    if (c < 256) {
        v = F[r * 640 + c];
        hi_off = r * 256 + c;                      // fs_hi
        lo_off = (size_t)M * 256 + r * 256 + c;    // fs_lo
    } else {
        int t = c - 256;
        int d = t / 128, o = t % 128;
        v = F[r * 640 + 256 + o * 3 + d];
        hi_off = (size_t)M * 512 + (size_t)d * M * 128 + r * 128 + o;
        lo_off = (size_t)M * 896 + (size_t)d * M * 128 + r * 128 + o;
    }
    __nv_bfloat16 h = __float2bfloat16(v);
    out[hi_off] = h;
    out[lo_off] = __float2bfloat16(v - __bfloat162float(h));
}

// ---------------------------------------------------------------------------
// HMMA GEMM, 128x128 tile, BK=32, double-buffered cp.async.
// A given as split bf16 (Ah, Al), plane-major; B pre-split weights [N,K].
// C[gm*ldc + cOff + z*cPlane + gn*cStride] (+)= result
// ---------------------------------------------------------------------------
#define SA2 72
#define ABYTES (128 * SA2 * 2)          // 18432
#define STAGE_BYTES (2 * ABYTES)        // 36864 (A | B)
#define SMEM_BYTES (2 * STAGE_BYTES)    // 73728

__global__ __launch_bounds__(256) void tc_gemm(
    const __nv_bfloat16* __restrict__ Ah, const __nv_bfloat16* __restrict__ Al,
    int lda, size_t aPlane,
    const __nv_bfloat16* __restrict__ Bh, const __nv_bfloat16* __restrict__ Bl,
    float* __restrict__ C, int ldc, size_t cOff, size_t cPlane, int cStride,
    int M, int K, int accumulate)
{
    extern __shared__ char smem[];
    const uint32_t sb = smem_to_u32(smem);

    const int tid = threadIdx.x;
    const int wid = tid >> 5;
    const int lane = tid & 31;
    const int warp_m = wid & 3;
    const int warp_n = wid >> 2;
    const int bm = blockIdx.y * 128;
    const int bn = blockIdx.x * 128;
    const int z = blockIdx.z;
    Ah += (size_t)z * aPlane;
    Al += (size_t)z * aPlane;
    C  += cOff + (size_t)z * cPlane;

    // ldmatrix lane addressing
    const int quad = lane >> 3;
    const int rsel = (lane & 7) + ((quad & 1) << 3);
    const int ksel = (quad >> 1) << 3;           // bf16 cols 0 or 8

    float acc[2][8][4];
#pragma unroll
    for (int mi = 0; mi < 2; mi++)
#pragma unroll
        for (int nj = 0; nj < 8; nj++)
#pragma unroll
            for (int r = 0; r < 4; r++) acc[mi][nj][r] = 0.f;

    const int nkt = K / 32;

    auto prefetch = [&](int kt, int st) {
        const int k0 = kt * 32;
        const uint32_t base = sb + st * STAGE_BYTES;
        // A: 128 rows x 64 cols (Ah cols 0-31, Al cols 32-63), 8 chunks/row
#pragma unroll
        for (int i = 0; i < 4; i++) {
            int t = tid + i * 256;
            int row = t >> 3, c = t & 7;
            int gm = bm + row;
            const __nv_bfloat16* src =
                ((c < 4) ? Ah : Al) + (size_t)gm * lda + k0 + (c & 3) * 8;
            uint32_t dst = base + (uint32_t)(row * SA2 + c * 8) * 2;
            int sz = (gm < M) ? 16 : 0;
            CP_ASYNC16(dst, src, sz);
        }
        // B: 128 n-rows x 64 cols (Bh 0-31, Bl 32-63)
#pragma unroll
        for (int i = 0; i < 4; i++) {
            int t = tid + i * 256;
            int row = t >> 3, c = t & 7;
            const __nv_bfloat16* src =
                ((c < 4) ? Bh : Bl) + (size_t)(bn + row) * K + k0 + (c & 3) * 8;
            uint32_t dst = base + ABYTES + (uint32_t)(row * SA2 + c * 8) * 2;
            CP_ASYNC16(dst, src, 16);
        }
    };

    prefetch(0, 0);
    CP_COMMIT;

    for (int kt = 0; kt < nkt; kt++) {
        if (kt + 1 < nkt) prefetch(kt + 1, (kt + 1) & 1);
        CP_COMMIT;
        if (kt + 1 < nkt) { CP_WAIT1; } else { CP_WAIT0; }
        __syncthreads();

        const uint32_t sbase = sb + (kt & 1) * STAGE_BYTES;
        const uint32_t aBase = sbase + (uint32_t)((warp_m * 32 + rsel) * SA2 + ksel) * 2;
        const uint32_t bBase = sbase + ABYTES + (uint32_t)((warp_n * 64 + rsel) * SA2 + ksel) * 2;

#pragma unroll
        for (int ks = 0; ks < 2; ks++) {
            const uint32_t kof = ks * 32;      // 16 bf16 cols
            uint32_t aH0[4], aH1[4], aL0[4], aL1[4];
            uint32_t b[8][2];
            // Ah fragments
            ldm4(aH0[0], aH0[1], aH0[2], aH0[3], aBase + kof);
            ldm4(aH1[0], aH1[1], aH1[2], aH1[3], aBase + 16 * SA2 * 2 + kof);
            // Bh fragments
#pragma unroll
            for (int j2 = 0; j2 < 4; j2++) {
                uint32_t r0, r1, r2, r3;
                ldm4(r0, r1, r2, r3, bBase + (uint32_t)(j2 * 16 * SA2) * 2 + kof);
                b[2 * j2][0] = r0; b[2 * j2 + 1][0] = r1;
                b[2 * j2][1] = r2; b[2 * j2 + 1][1] = r3;
            }
            // term 1: Ah*Bh
#pragma unroll
            for (int nj = 0; nj < 8; nj++) {
                mma16816(acc[0][nj], aH0, b[nj]);
                mma16816(acc[1][nj], aH1, b[nj]);
            }
            // Al fragments, term 2: Al*Bh
            ldm4(aL0[0], aL0[1], aL0[2], aL0[3], aBase + 64 + kof);
            ldm4(aL1[0], aL1[1], aL1[2], aL1[3], aBase + 16 * SA2 * 2 + 64 + kof);
#pragma unroll
            for (int nj = 0; nj < 8; nj++) {
                mma16816(acc[0][nj], aL0, b[nj]);
                mma16816(acc[1][nj], aL1, b[nj]);
            }
            // Bl fragments, term 3: Ah*Bl
#pragma unroll
            for (int j2 = 0; j2 < 4; j2++) {
                uint32_t r0, r1, r2, r3;
                ldm4(r0, r1, r2, r3, bBase + (uint32_t)(j2 * 16 * SA2) * 2 + 64 + kof);
                b[2 * j2][0] = r0; b[2 * j2 + 1][0] = r1;
                b[2 * j2][1] = r2; b[2 * j2 + 1][1] = r3;
            }
#pragma unroll
            for (int nj = 0; nj < 8; nj++) {
                mma16816(acc[0][nj], aH0, b[nj]);
                mma16816(acc[1][nj], aH1, b[nj]);
            }
        }
        __syncthreads();
    }

    // ---- epilogue ----
    const int tq = lane >> 2;
    const int tr = lane & 3;
#pragma unroll
    for (int mi = 0; mi < 2; mi++) {
#pragma unroll
        for (int half = 0; half < 2; half++) {
            int gm = bm + warp_m * 32 + mi * 16 + tq + half * 8;
            if (gm >= M) continue;
            if (cStride == 1) {
                float* Crow = C + (size_t)gm * ldc + bn + warp_n * 64;
#pragma unroll
                for (int nj = 0; nj < 8; nj++) {
                    int cn = nj * 8 + tr * 2;
                    float2 v = make_float2(acc[mi][nj][half * 2], acc[mi][nj][half * 2 + 1]);
                    if (accumulate) {
                        float2 o = *(float2*)&Crow[cn];
                        v.x += o.x; v.y += o.y;
                    }
                    *(float2*)&Crow[cn] = v;
                }
            } else {
                float* Crow = C + (size_t)gm * ldc;
#pragma unroll
                for (int nj = 0; nj < 8; nj++) {
                    int gn0 = bn + warp_n * 64 + nj * 8 + tr * 2;
                    float v0 = acc[mi][nj][half * 2];
                    float v1 = acc[mi][nj][half * 2 + 1];
                    if (accumulate) {
                        v0 += Crow[(size_t)gn0 * 3];
                        v1 += Crow[(size_t)(gn0 + 1) * 3];
                    }
                    Crow[(size_t)gn0 * 3] = v0;
                    Crow[(size_t)(gn0 + 1) * 3] = v1;
                }
            }
        }
    }
}

// ---------------------------------------------------------------------------
// Gate: pre (plane-major fp32) -> h (split bf16 planes)
// ---------------------------------------------------------------------------
__global__ void gate_kernel(const float* __restrict__ pre, __nv_bfloat16* __restrict__ h, int M)
{
    size_t idx = (size_t)blockIdx.x * blockDim.x + threadIdx.x;
    size_t total = (size_t)M * 1280;
    if (idx >= total) return;
    int c = (int)(idx % 1280);
    size_t r = idx / 1280;
    float v;
    size_t hi_off, lo_off;
    if (c < 512) {
        float s = pre[r * 768 + c];
        v = s / (1.f + __expf(-s));
        hi_off = r * 512 + c;
        lo_off = (size_t)M * 512 + r * 512 + c;
    } else {
        int t = c - 512;
        int d = t / 256, o = t % 256;
        float g = 1.f / (1.f + __expf(-pre[r * 768 + 512 + o]));
        v = pre[(size_t)M * 768 + (size_t)d * M * 256 + r * 256 + o] * g;
        hi_off = (size_t)M * 1024 + (size_t)d * M * 256 + r * 256 + o;
        lo_off = (size_t)M * 1792 + (size_t)d * M * 256 + r * 256 + o;
    }
    __nv_bfloat16 hh = __float2bfloat16(v);
    h[hi_off] = hh;
    h[lo_off] = __float2bfloat16(v - __bfloat162float(hh));
}

// ---------------------------------------------------------------------------
// Batch-norm (deterministic two-stage reduction) — operates on interleaved out
// ---------------------------------------------------------------------------
__global__ void bn_partial_kernel(const float* __restrict__ out,
                                  float* __restrict__ psum, float* __restrict__ psq, int M)
{
    int c = threadIdx.x;
    float s = 0.f, sq = 0.f;
    for (int r = blockIdx.x; r < M; r += gridDim.x) {
        float x = out[(size_t)r * 640 + c];
        s += x; sq += x * x;
    }
    psq[blockIdx.x * 640 + c] = sq;
    if (c < 256) psum[blockIdx.x * 256 + c] = s;
}

__global__ void bn_final_kernel(const float* __restrict__ psum, const float* __restrict__ psq,
                                const float* __restrict__ w, const float* __restrict__ b,
                                float* __restrict__ scale, float* __restrict__ shift, int M)
{
    __shared__ float ssq[640];
    __shared__ float ssum[256];
    int c = threadIdx.x;
    float sq = 0.f;
    for (int p = 0; p < NPART; p++) sq += psq[p * 640 + c];
    ssq[c] = sq;
    if (c < 256) {
        float s = 0.f;
        for (int p = 0; p < NPART; p++) s += psum[p * 256 + c];
        ssum[c] = s;
    }
    __syncthreads();
    float invN = 1.f / (float)M;
    if (c < 256) {
        float m = ssum[c] * invN;
        float var = ssq[c] * invN - m * m;
        float inv = rsqrtf(var + 1e-5f);
        float sc = inv * w[c];
        scale[c] = sc;
        shift[c] = b[c] - m * sc;
    } else if (c < 256 + 128) {
        int ch = c - 256;
        float t = ssq[256 + 3 * ch] + ssq[256 + 3 * ch + 1] + ssq[256 + 3 * ch + 2];
        float mean = t * invN * (1.f / 3.f);
        float inv = rsqrtf(mean + 1e-5f);
        float sc = inv * w[256 + ch];
#pragma unroll
        for (int d2 = 0; d2 < 3; d2++) {
            scale[256 + 3 * ch + d2] = sc;
            shift[256 + 3 * ch + d2] = 0.f;
        }
    }
}

__global__ void bn_apply_kernel(float* __restrict__ out,
                                const float* __restrict__ scale,
                                const float* __restrict__ shift, int M)
{
    size_t idx = (size_t)blockIdx.x * blockDim.x + threadIdx.x;
    size_t total = (size_t)M * 640;
    if (idx >= total) return;
    int c = (int)(idx % 640);
    out[idx] = out[idx] * __ldg(&scale[c]) + __ldg(&shift[c]);
}

// ---------------------------------------------------------------------------
extern "C" void kernel_launch(void* const* d_in, const int* in_sizes, int n_in,
                              void* d_out, int out_size)
{
    const float* features = (const float*)d_in[0];
    const float* W10 = (const float*)d_in[1];
    const float* W11 = (const float*)d_in[2];
    const float* W20 = (const float*)d_in[3];
    const float* W21 = (const float*)d_in[4];
    const float* W30 = (const float*)d_in[5];
    const float* W31 = (const float*)d_in[6];
    const float* B0  = (const float*)d_in[7];
    const float* B1  = (const float*)d_in[8];
    const float* bw  = (const float*)d_in[9];
    const float* bb  = (const float*)d_in[10];
    float* out = (float*)d_out;

    float *pre, *psum, *psq, *sc, *sh;
    __nv_bfloat16 *wb, *h, *ft;
    cudaGetSymbolAddress((void**)&pre, g_pre);
    cudaGetSymbolAddress((void**)&h, g_hbuf);
    cudaGetSymbolAddress((void**)&ft, g_feat);
    cudaGetSymbolAddress((void**)&psum, g_psum);
    cudaGetSymbolAddress((void**)&psq, g_psq);
    cudaGetSymbolAddress((void**)&sc, g_scale);
    cudaGetSymbolAddress((void**)&sh, g_shift);
    cudaGetSymbolAddress((void**)&wb, g_wbuf);

    const size_t M = MROWS;
    const float s256 = 0.0625f;
    const float s128 = 0.08838834764831845f;
    const float s512 = 0.04419417382415922f;

    const int o10 = 0, o11 = 196608, o20 = 229376, o21 = 622592;
    const int o30 = 688128, o31 = 819200, ob0 = 851968, ob1 = 917504;
    __nv_bfloat16* lo = wb + WTOT;

    // ---- preconvert weights + features ----
    {
        struct { const float* W; int K, N, off; float s; } cw[8] = {
            {W10, 256, 768, o10, s256}, {W11, 128, 256, o11, s128},
            {W20, 512, 768, o20, s512}, {W21, 256, 256, o21, s256},
            {W30, 512, 256, o30, s512}, {W31, 256, 128, o31, s256},
            {B0,  256, 256, ob0, s256}, {B1,  128, 128, ob1, s128}};
        for (int i = 0; i < 8; i++) {
            int tot = cw[i].K * cw[i].N;
            conv_w_kernel<<<(tot + 255) / 256, 256>>>(cw[i].W, cw[i].K, cw[i].N, cw[i].s,
                                                      wb + cw[i].off, lo + cw[i].off);
        }
        size_t tot = M * 640;
        conv_feat_kernel<<<(unsigned)((tot + 255) / 256), 256>>>(features, ft, (int)M);
    }

    const int gy = (int)((M + 127) / 128);
    cudaFuncSetAttribute(tc_gemm, cudaFuncAttributeMaxDynamicSharedMemorySize, SMEM_BYTES);

    // plane pointers
    __nv_bfloat16* fs_h = ft;                 // [M,256]
    __nv_bfloat16* fs_l = ft + M * 256;
    __nv_bfloat16* fv_h = ft + M * 512;       // 3 planes [M,128]
    __nv_bfloat16* fv_l = ft + M * 896;
    __nv_bfloat16* hs_h = h;                  // [M,512]
    __nv_bfloat16* hs_l = h + M * 512;
    __nv_bfloat16* hv_h = h + M * 1024;       // 3 planes [M,256]
    __nv_bfloat16* hv_l = h + M * 1792;

    // ---- layer 1 ----
    tc_gemm<<<dim3(6, gy, 1), 256, SMEM_BYTES>>>(fs_h, fs_l, 256, 0, wb + o10, lo + o10,
                                                 pre, 768, 0, 0, 1, (int)M, 256, 0);
    tc_gemm<<<dim3(2, gy, 3), 256, SMEM_BYTES>>>(fv_h, fv_l, 128, M * 128, wb + o11, lo + o11,
                                                 pre, 256, M * 768, M * 256, 1, (int)M, 128, 0);
    {
        size_t total = M * 1280;
        gate_kernel<<<(unsigned)((total + 255) / 256), 256>>>(pre, h, (int)M);
    }
    // ---- layer 2 ----
    tc_gemm<<<dim3(6, gy, 1), 256, SMEM_BYTES>>>(hs_h, hs_l, 512, 0, wb + o20, lo + o20,
                                                 pre, 768, 0, 0, 1, (int)M, 512, 0);
    tc_gemm<<<dim3(2, gy, 3), 256, SMEM_BYTES>>>(hv_h, hv_l, 256, M * 256, wb + o21, lo + o21,
                                                 pre, 256, M * 768, M * 256, 1, (int)M, 256, 0);
    {
        size_t total = M * 1280;
        gate_kernel<<<(unsigned)((total + 255) / 256), 256>>>(pre, h, (int)M);
    }
    // ---- layer 3 + bypass ----
    tc_gemm<<<dim3(2, gy, 1), 256, SMEM_BYTES>>>(hs_h, hs_l, 512, 0, wb + o30, lo + o30,
                                                 out, 640, 0, 0, 1, (int)M, 512, 0);
    tc_gemm<<<dim3(1, gy, 3), 256, SMEM_BYTES>>>(hv_h, hv_l, 256, M * 256, wb + o31, lo + o31,
                                                 out, 640, 256, 1, 3, (int)M, 256, 0);
    tc_gemm<<<dim3(2, gy, 1), 256, SMEM_BYTES>>>(fs_h, fs_l, 256, 0, wb + ob0, lo + ob0,
                                                 out, 640, 0, 0, 1, (int)M, 256, 1);
    tc_gemm<<<dim3(1, gy, 3), 256, SMEM_BYTES>>>(fv_h, fv_l, 128, M * 128, wb + ob1, lo + ob1,
                                                 out, 640, 256, 1, 3, (int)M, 128, 1);

    // ---- batch norm ----
    bn_partial_kernel<<<NPART, 640>>>(out, psum, psq, (int)M);
    bn_final_kernel<<<1, 640>>>(psum, psq, bw, bb, sc, sh, (int)M);
    {
        size_t total = M * 640;
        bn_apply_kernel<<<(unsigned)((total + 255) / 256), 256>>>(out, sc, sh, (int)M);
    }
}

// round 5
// speedup vs baseline: 1.4551x; 1.4551x over previous
#include <cuda_runtime.h>
#include <cuda_bf16.h>
#include <cstdint>
#include <cstddef>

// ===========================================================================
// FeedForward via mma.sync bf16 split-precision: C = AhBh + AhBl + AlBh
// R3 GEMM skeleton (K'=96 smem expansion, single-buffered, uniform MMA stream)
// + presplit plane-major bf16 activations (no conversion in GEMM hot loop).
//   feat planes: fs_hi [M,256]@0, fs_lo @M*256, fv_hi[d] [M,128]@M*512+d*M*128,
//                fv_lo[d] @M*896+d*M*128
//   pre (fp32):  pre_s [M,768]@0, pre_v[d] [M,256] @M*768+d*M*256
//   h planes:    hs_hi [M,512]@0, hs_lo @M*512, hv_hi[d] [M,256]@M*1024+d*M*256,
//                hv_lo[d] @M*1792+d*M*256
// ===========================================================================

#define MROWS 100000

// ------------------------------- scratch -----------------------------------
__device__ float g_pre[(size_t)MROWS * 1536];
__device__ __nv_bfloat16 g_hbuf[(size_t)MROWS * 2560];
__device__ __nv_bfloat16 g_feat[(size_t)MROWS * 1280];
#define NPART 512
__device__ float g_psum[NPART * 256];
__device__ float g_psq[NPART * 640];
__device__ float g_scale[640];
__device__ float g_shift[640];
#define WTOT 933888
__device__ __align__(256) __nv_bfloat16 g_wbuf[2 * WTOT];

// --------------------------- helpers ---------------------------------------
__device__ __forceinline__ uint32_t smem_to_u32(const void* p) {
    uint32_t a;
    asm("{ .reg .u64 t; cvta.to.shared.u64 t, %1; cvt.u32.u64 %0, t; }" : "=r"(a) : "l"(p));
    return a;
}
__device__ __forceinline__ void ldm4(uint32_t& r0, uint32_t& r1, uint32_t& r2, uint32_t& r3,
                                     uint32_t addr) {
    asm volatile("ldmatrix.sync.aligned.m8n8.x4.shared.b16 {%0,%1,%2,%3}, [%4];"
                 : "=r"(r0), "=r"(r1), "=r"(r2), "=r"(r3) : "r"(addr));
}
__device__ __forceinline__ void mma16816(float* c, const uint32_t* a, const uint32_t* b) {
    asm volatile(
        "mma.sync.aligned.m16n8k16.row.col.f32.bf16.bf16.f32 "
        "{%0,%1,%2,%3}, {%4,%5,%6,%7}, {%8,%9}, {%0,%1,%2,%3};"
        : "+f"(c[0]), "+f"(c[1]), "+f"(c[2]), "+f"(c[3])
        : "r"(a[0]), "r"(a[1]), "r"(a[2]), "r"(a[3]), "r"(b[0]), "r"(b[1]));
}

// ---------------------------------------------------------------------------
// Weight prep: W[K,N] fp32 -> hi/lo bf16 [N,K] K-major, scale folded in.
// ---------------------------------------------------------------------------
__global__ void conv_w_kernel(const float* __restrict__ W, int K, int N, float scale,
                              __nv_bfloat16* __restrict__ hi, __nv_bfloat16* __restrict__ lo) {
    int idx = blockIdx.x * blockDim.x + threadIdx.x;
    if (idx >= N * K) return;
    int n = idx / K, k = idx % K;
    float v = W[k * N + n] * scale;
    __nv_bfloat16 h = __float2bfloat16(v);
    hi[idx] = h;
    lo[idx] = __float2bfloat16(v - __bfloat162float(h));
}

// ---------------------------------------------------------------------------
// Features -> split plane-major bf16
// ---------------------------------------------------------------------------
__global__ void conv_feat_kernel(const float* __restrict__ F, __nv_bfloat16* __restrict__ out,
                                 int M) {
    size_t idx = (size_t)blockIdx.x * blockDim.x + threadIdx.x;
    size_t total = (size_t)M * 640;
    if (idx >= total) return;
    int c = (int)(idx % 640);
    size_t r = idx / 640;
    float v;
    size_t hi_off, lo_off;
    if (c < 256) {
        v = F[r * 640 + c];
        hi_off = r * 256 + c;
        lo_off = (size_t)M * 256 + r * 256 + c;
    } else {
        int t = c - 256;
        int d = t / 128, o = t % 128;
        v = F[r * 640 + 256 + o * 3 + d];
        hi_off = (size_t)M * 512 + (size_t)d * M * 128 + r * 128 + o;
        lo_off = (size_t)M * 896 + (size_t)d * M * 128 + r * 128 + o;
    }
    __nv_bfloat16 h = __float2bfloat16(v);
    out[hi_off] = h;
    out[lo_off] = __float2bfloat16(v - __bfloat162float(h));
}

// ---------------------------------------------------------------------------
// HMMA GEMM (R3 skeleton): block 128x128, BK=32 -> K'=96 smem expansion.
// A presplit bf16 planes (Ah/Al, K-major, row stride lda); B presplit [N,K].
// C[gm*ldc + cOff + z*cPlane + gn*cStride] (+)= result
// ---------------------------------------------------------------------------
#define SA 104   // smem row stride in bf16 (208 B, conflict-free ldmatrix)
#define ATILE (128 * SA)
#define SMEM_BYTES (2 * ATILE * 2)   // 53248

__global__ __launch_bounds__(256) void tc_gemm(
    const __nv_bfloat16* __restrict__ Ah, const __nv_bfloat16* __restrict__ Al,
    int lda, size_t aPlane,
    const __nv_bfloat16* __restrict__ Bh, const __nv_bfloat16* __restrict__ Bl,
    float* __restrict__ C, int ldc, size_t cOff, size_t cPlane, int cStride,
    int M, int K, int accumulate)
{
    extern __shared__ __nv_bfloat16 smem[];
    __nv_bfloat16* As = smem;           // [128][SA], cols: 0-31 Ah, 32-63 Ah, 64-95 Al
    __nv_bfloat16* Bs = smem + ATILE;   // [128][SA], cols: 0-31 Bh, 32-63 Bl, 64-95 Bh
    const uint32_t sA = smem_to_u32(As);
    const uint32_t sB = smem_to_u32(Bs);

    const int tid = threadIdx.x;
    const int wid = tid >> 5;
    const int lane = tid & 31;
    const int warp_m = wid & 3;
    const int warp_n = wid >> 2;
    const int bm = blockIdx.y * 128;
    const int bn = blockIdx.x * 128;
    const int z = blockIdx.z;
    Ah += (size_t)z * aPlane;
    Al += (size_t)z * aPlane;
    C  += cOff + (size_t)z * cPlane;

    const int quad = lane >> 3;
    const int rsel = (lane & 7) + ((quad & 1) << 3);
    const int ksel = (quad >> 1) << 3;
    const uint32_t aAddr0 = sA + (uint32_t)((warp_m * 32 + rsel) * SA + ksel) * 2;
    const uint32_t aAddr1 = aAddr0 + 16 * SA * 2;
    const uint32_t bAddr0 = sB + (uint32_t)((warp_n * 64 + rsel) * SA + ksel) * 2;

    float acc[2][8][4];
#pragma unroll
    for (int mi = 0; mi < 2; mi++)
#pragma unroll
        for (int nj = 0; nj < 8; nj++)
#pragma unroll
            for (int r = 0; r < 4; r++) acc[mi][nj][r] = 0.f;

    const int nkt = K / 32;
    for (int kt = 0; kt < nkt; kt++) {
        const int k0 = kt * 32;
        __syncthreads();   // protect smem reuse from previous iter's ldmatrix
        // ---- A tile: copy presplit bf16 (128 rows x 32 cols each of Ah, Al)
#pragma unroll
        for (int i = 0; i < 2; i++) {
            int t = tid + i * 256;          // 512 uint4 slots
            int row = t >> 2, c8 = t & 3;   // col = c8*8
            int gm = bm + row;
            uint4 vh = make_uint4(0u, 0u, 0u, 0u), vl = vh;
            if (gm < M) {
                size_t base = (size_t)gm * lda + k0 + c8 * 8;
                vh = *(const uint4*)&Ah[base];
                vl = *(const uint4*)&Al[base];
            }
            __nv_bfloat16* rp = As + row * SA + c8 * 8;
            *(uint4*)(rp)      = vh;   // Ah
            *(uint4*)(rp + 32) = vh;   // Ah (dup)
            *(uint4*)(rp + 64) = vl;   // Al
        }
        // ---- B tile: Bh -> cols 0-31 & 64-95, Bl -> 32-63
#pragma unroll
        for (int i = 0; i < 2; i++) {
            int t = tid + i * 256;
            int n = t >> 2, c8 = t & 3;
            size_t base = (size_t)(bn + n) * K + k0 + c8 * 8;
            uint4 vh = *(const uint4*)&Bh[base];
            uint4 vl = *(const uint4*)&Bl[base];
            __nv_bfloat16* rp = Bs + n * SA + c8 * 8;
            *(uint4*)(rp)      = vh;
            *(uint4*)(rp + 32) = vl;
            *(uint4*)(rp + 64) = vh;
        }
        __syncthreads();

        // ---- compute: 6 k16 steps over K'=96 (uniform, dependency-free)
#pragma unroll
        for (int ks = 0; ks < 6; ks++) {
            uint32_t af0[4], af1[4];
            ldm4(af0[0], af0[1], af0[2], af0[3], aAddr0 + ks * 32);
            ldm4(af1[0], af1[1], af1[2], af1[3], aAddr1 + ks * 32);
            uint32_t bf[8][2];
#pragma unroll
            for (int j2 = 0; j2 < 4; j2++) {
                uint32_t r0, r1, r2, r3;
                ldm4(r0, r1, r2, r3, bAddr0 + (uint32_t)(j2 * 16 * SA) * 2 + ks * 32);
                bf[2 * j2][0] = r0; bf[2 * j2 + 1][0] = r1;
                bf[2 * j2][1] = r2; bf[2 * j2 + 1][1] = r3;
            }
#pragma unroll
            for (int mi = 0; mi < 2; mi++)
#pragma unroll
                for (int nj = 0; nj < 8; nj++)
                    mma16816(acc[mi][nj], mi ? af1 : af0, bf[nj]);
        }
    }

    // ---- epilogue ----
    const int tq = lane >> 2;
    const int tr = lane & 3;
#pragma unroll
    for (int mi = 0; mi < 2; mi++) {
#pragma unroll
        for (int half = 0; half < 2; half++) {
            int gm = bm + warp_m * 32 + mi * 16 + tq + half * 8;
            if (gm >= M) continue;
            if (cStride == 1) {
                float* Crow = C + (size_t)gm * ldc + bn + warp_n * 64;
#pragma unroll
                for (int nj = 0; nj < 8; nj++) {
                    int cn = nj * 8 + tr * 2;
                    float2 v = make_float2(acc[mi][nj][half * 2], acc[mi][nj][half * 2 + 1]);
                    if (accumulate) {
                        float2 o = *(float2*)&Crow[cn];
                        v.x += o.x; v.y += o.y;
                    }
                    *(float2*)&Crow[cn] = v;
                }
            } else {
                float* Crow = C + (size_t)gm * ldc;
#pragma unroll
                for (int nj = 0; nj < 8; nj++) {
                    int gn0 = bn + warp_n * 64 + nj * 8 + tr * 2;
                    float v0 = acc[mi][nj][half * 2];
                    float v1 = acc[mi][nj][half * 2 + 1];
                    if (accumulate) {
                        v0 += Crow[(size_t)gn0 * 3];
                        v1 += Crow[(size_t)(gn0 + 1) * 3];
                    }
                    Crow[(size_t)gn0 * 3] = v0;
                    Crow[(size_t)(gn0 + 1) * 3] = v1;
                }
            }
        }
    }
}

// ---------------------------------------------------------------------------
// Gate: pre (plane-major fp32) -> h (split bf16 planes)
// ---------------------------------------------------------------------------
__global__ void gate_kernel(const float* __restrict__ pre, __nv_bfloat16* __restrict__ h, int M)
{
    size_t idx = (size_t)blockIdx.x * blockDim.x + threadIdx.x;
    size_t total = (size_t)M * 1280;
    if (idx >= total) return;
    int c = (int)(idx % 1280);
    size_t r = idx / 1280;
    float v;
    size_t hi_off, lo_off;
    if (c < 512) {
        float s = pre[r * 768 + c];
        v = s / (1.f + __expf(-s));
        hi_off = r * 512 + c;
        lo_off = (size_t)M * 512 + r * 512 + c;
    } else {
        int t = c - 512;
        int d = t / 256, o = t % 256;
        float g = 1.f / (1.f + __expf(-pre[r * 768 + 512 + o]));
        v = pre[(size_t)M * 768 + (size_t)d * M * 256 + r * 256 + o] * g;
        hi_off = (size_t)M * 1024 + (size_t)d * M * 256 + r * 256 + o;
        lo_off = (size_t)M * 1792 + (size_t)d * M * 256 + r * 256 + o;
    }
    __nv_bfloat16 hh = __float2bfloat16(v);
    h[hi_off] = hh;
    h[lo_off] = __float2bfloat16(v - __bfloat162float(hh));
}

// ---------------------------------------------------------------------------
// Batch-norm (deterministic two-stage reduction)
// ---------------------------------------------------------------------------
__global__ void bn_partial_kernel(const float* __restrict__ out,
                                  float* __restrict__ psum, float* __restrict__ psq, int M)
{
    int c = threadIdx.x;
    float s = 0.f, sq = 0.f;
    for (int r = blockIdx.x; r < M; r += gridDim.x) {
        float x = out[(size_t)r * 640 + c];
        s += x; sq += x * x;
    }
    psq[blockIdx.x * 640 + c] = sq;
    if (c < 256) psum[blockIdx.x * 256 + c] = s;
}

__global__ void bn_final_kernel(const float* __restrict__ psum, const float* __restrict__ psq,
                                const float* __restrict__ w, const float* __restrict__ b,
                                float* __restrict__ scale, float* __restrict__ shift, int M)
{
    __shared__ float ssq[640];
    __shared__ float ssum[256];
    int c = threadIdx.x;
    float sq = 0.f;
    for (int p = 0; p < NPART; p++) sq += psq[p * 640 + c];
    ssq[c] = sq;
    if (c < 256) {
        float s = 0.f;
        for (int p = 0; p < NPART; p++) s += psum[p * 256 + c];
        ssum[c] = s;
    }
    __syncthreads();
    float invN = 1.f / (float)M;
    if (c < 256) {
        float m = ssum[c] * invN;
        float var = ssq[c] * invN - m * m;
        float inv = rsqrtf(var + 1e-5f);
        float sc = inv * w[c];
        scale[c] = sc;
        shift[c] = b[c] - m * sc;
    } else if (c < 256 + 128) {
        int ch = c - 256;
        float t = ssq[256 + 3 * ch] + ssq[256 + 3 * ch + 1] + ssq[256 + 3 * ch + 2];
        float mean = t * invN * (1.f / 3.f);
        float inv = rsqrtf(mean + 1e-5f);
        float sc = inv * w[256 + ch];
#pragma unroll
        for (int d2 = 0; d2 < 3; d2++) {
            scale[256 + 3 * ch + d2] = sc;
            shift[256 + 3 * ch + d2] = 0.f;
        }
    }
}

__global__ void bn_apply_kernel(float* __restrict__ out,
                                const float* __restrict__ scale,
                                const float* __restrict__ shift, int M)
{
    size_t idx = (size_t)blockIdx.x * blockDim.x + threadIdx.x;
    size_t total = (size_t)M * 640;
    if (idx >= total) return;
    int c = (int)(idx % 640);
    out[idx] = out[idx] * __ldg(&scale[c]) + __ldg(&shift[c]);
}

// ---------------------------------------------------------------------------
extern "C" void kernel_launch(void* const* d_in, const int* in_sizes, int n_in,
                              void* d_out, int out_size)
{
    const float* features = (const float*)d_in[0];
    const float* W10 = (const float*)d_in[1];
    const float* W11 = (const float*)d_in[2];
    const float* W20 = (const float*)d_in[3];
    const float* W21 = (const float*)d_in[4];
    const float* W30 = (const float*)d_in[5];
    const float* W31 = (const float*)d_in[6];
    const float* B0  = (const float*)d_in[7];
    const float* B1  = (const float*)d_in[8];
    const float* bw  = (const float*)d_in[9];
    const float* bb  = (const float*)d_in[10];
    float* out = (float*)d_out;

    float *pre, *psum, *psq, *sc, *sh;
    __nv_bfloat16 *wb, *h, *ft;
    cudaGetSymbolAddress((void**)&pre, g_pre);
    cudaGetSymbolAddress((void**)&h, g_hbuf);
    cudaGetSymbolAddress((void**)&ft, g_feat);
    cudaGetSymbolAddress((void**)&psum, g_psum);
    cudaGetSymbolAddress((void**)&psq, g_psq);
    cudaGetSymbolAddress((void**)&sc, g_scale);
    cudaGetSymbolAddress((void**)&sh, g_shift);
    cudaGetSymbolAddress((void**)&wb, g_wbuf);

    const size_t M = MROWS;
    const float s256 = 0.0625f;
    const float s128 = 0.08838834764831845f;
    const float s512 = 0.04419417382415922f;

    const int o10 = 0, o11 = 196608, o20 = 229376, o21 = 622592;
    const int o30 = 688128, o31 = 819200, ob0 = 851968, ob1 = 917504;
    __nv_bfloat16* lo = wb + WTOT;

    // ---- preconvert weights + features ----
    {
        struct { const float* W; int K, N, off; float s; } cw[8] = {
            {W10, 256, 768, o10, s256}, {W11, 128, 256, o11, s128},
            {W20, 512, 768, o20, s512}, {W21, 256, 256, o21, s256},
            {W30, 512, 256, o30, s512}, {W31, 256, 128, o31, s256},
            {B0,  256, 256, ob0, s256}, {B1,  128, 128, ob1, s128}};
        for (int i = 0; i < 8; i++) {
            int tot = cw[i].K * cw[i].N;
            conv_w_kernel<<<(tot + 255) / 256, 256>>>(cw[i].W, cw[i].K, cw[i].N, cw[i].s,
                                                      wb + cw[i].off, lo + cw[i].off);
        }
        size_t tot = M * 640;
        conv_feat_kernel<<<(unsigned)((tot + 255) / 256), 256>>>(features, ft, (int)M);
    }

    const int gy = (int)((M + 127) / 128);
    cudaFuncSetAttribute(tc_gemm, cudaFuncAttributeMaxDynamicSharedMemorySize, SMEM_BYTES);

    __nv_bfloat16* fs_h = ft;
    __nv_bfloat16* fs_l = ft + M * 256;
    __nv_bfloat16* fv_h = ft + M * 512;
    __nv_bfloat16* fv_l = ft + M * 896;
    __nv_bfloat16* hs_h = h;
    __nv_bfloat16* hs_l = h + M * 512;
    __nv_bfloat16* hv_h = h + M * 1024;
    __nv_bfloat16* hv_l = h + M * 1792;

    // ---- layer 1 ----
    tc_gemm<<<dim3(6, gy, 1), 256, SMEM_BYTES>>>(fs_h, fs_l, 256, 0, wb + o10, lo + o10,
                                                 pre, 768, 0, 0, 1, (int)M, 256, 0);
    tc_gemm<<<dim3(2, gy, 3), 256, SMEM_BYTES>>>(fv_h, fv_l, 128, M * 128, wb + o11, lo + o11,
                                                 pre, 256, M * 768, M * 256, 1, (int)M, 128, 0);
    {
        size_t total = M * 1280;
        gate_kernel<<<(unsigned)((total + 255) / 256), 256>>>(pre, h, (int)M);
    }
    // ---- layer 2 ----
    tc_gemm<<<dim3(6, gy, 1), 256, SMEM_BYTES>>>(hs_h, hs_l, 512, 0, wb + o20, lo + o20,
                                                 pre, 768, 0, 0, 1, (int)M, 512, 0);
    tc_gemm<<<dim3(2, gy, 3), 256, SMEM_BYTES>>>(hv_h, hv_l, 256, M * 256, wb + o21, lo + o21,
                                                 pre, 256, M * 768, M * 256, 1, (int)M, 256, 0);
    {
        size_t total = M * 1280;
        gate_kernel<<<(unsigned)((total + 255) / 256), 256>>>(pre, h, (int)M);
    }
    // ---- layer 3 + bypass ----
    tc_gemm<<<dim3(2, gy, 1), 256, SMEM_BYTES>>>(hs_h, hs_l, 512, 0, wb + o30, lo + o30,
                                                 out, 640, 0, 0, 1, (int)M, 512, 0);
    tc_gemm<<<dim3(1, gy, 3), 256, SMEM_BYTES>>>(hv_h, hv_l, 256, M * 256, wb + o31, lo + o31,
                                                 out, 640, 256, 1, 3, (int)M, 256, 0);
    tc_gemm<<<dim3(2, gy, 1), 256, SMEM_BYTES>>>(fs_h, fs_l, 256, 0, wb + ob0, lo + ob0,
                                                 out, 640, 0, 0, 1, (int)M, 256, 1);
    tc_gemm<<<dim3(1, gy, 3), 256, SMEM_BYTES>>>(fv_h, fv_l, 128, M * 128, wb + ob1, lo + ob1,
                                                 out, 640, 256, 1, 3, (int)M, 128, 1);

    // ---- batch norm ----
    bn_partial_kernel<<<NPART, 640>>>(out, psum, psq, (int)M);
    bn_final_kernel<<<1, 640>>>(psum, psq, bw, bb, sc, sh, (int)M);
    {
        size_t total = M * 640;
        bn_apply_kernel<<<(unsigned)((total + 255) / 256), 256>>>(out, sc, sh, (int)M);
    }
}

// round 6
// speedup vs baseline: 1.8582x; 1.2770x over previous
#include <cuda_runtime.h>
#include <cuda_bf16.h>
#include <cstdint>
#include <cstddef>

// ===========================================================================
// FeedForward via mma.sync bf16 split-precision: C = AhBh + AhBl + AlBh
// R5 uniform MMA stream + no-dup smem layout (offset tables) + cp.async
// double buffering + layer3/bypass K-concatenation merge.
// ===========================================================================

#define MROWS 100000

// ------------------------------- scratch -----------------------------------
__device__ float g_pre[(size_t)MROWS * 1536];
__device__ __nv_bfloat16 g_hbuf[(size_t)MROWS * 2560];
__device__ __nv_bfloat16 g_feat[(size_t)MROWS * 1280];
#define NPART 512
__device__ float g_psum[NPART * 256];
__device__ float g_psq[NPART * 640];
__device__ float g_scale[640];
__device__ float g_shift[640];
#define WTOT 933888
__device__ __align__(256) __nv_bfloat16 g_wbuf[2 * WTOT];

// --------------------------- helpers ---------------------------------------
__device__ __forceinline__ uint32_t smem_to_u32(const void* p) {
    uint32_t a;
    asm("{ .reg .u64 t; cvta.to.shared.u64 t, %1; cvt.u32.u64 %0, t; }" : "=r"(a) : "l"(p));
    return a;
}
__device__ __forceinline__ void ldm4(uint32_t& r0, uint32_t& r1, uint32_t& r2, uint32_t& r3,
                                     uint32_t addr) {
    asm volatile("ldmatrix.sync.aligned.m8n8.x4.shared.b16 {%0,%1,%2,%3}, [%4];"
                 : "=r"(r0), "=r"(r1), "=r"(r2), "=r"(r3) : "r"(addr));
}
__device__ __forceinline__ void mma16816(float* c, const uint32_t* a, const uint32_t* b) {
    asm volatile(
        "mma.sync.aligned.m16n8k16.row.col.f32.bf16.bf16.f32 "
        "{%0,%1,%2,%3}, {%4,%5,%6,%7}, {%8,%9}, {%0,%1,%2,%3};"
        : "+f"(c[0]), "+f"(c[1]), "+f"(c[2]), "+f"(c[3])
        : "r"(a[0]), "r"(a[1]), "r"(a[2]), "r"(a[3]), "r"(b[0]), "r"(b[1]));
}
#define CP_ASYNC16(dst, src, sz) \
    asm volatile("cp.async.cg.shared.global [%0], [%1], 16, %2;" \
                 :: "r"(dst), "l"(src), "r"(sz) : "memory")
#define CP_COMMIT asm volatile("cp.async.commit_group;" ::: "memory")
#define CP_WAIT1 asm volatile("cp.async.wait_group 1;" ::: "memory")
#define CP_WAIT0 asm volatile("cp.async.wait_group 0;" ::: "memory")

// ---------------------------------------------------------------------------
// Weight prep: W[K,N] fp32 -> hi/lo bf16 [N,*] K-major with dest row stride
// ldout and column offset kOff (supports concatenated merged weights).
// ---------------------------------------------------------------------------
__global__ void conv_w_kernel(const float* __restrict__ W, int K, int N, float scale,
                              __nv_bfloat16* __restrict__ hi, __nv_bfloat16* __restrict__ lo,
                              int ldout, int kOff) {
    int idx = blockIdx.x * blockDim.x + threadIdx.x;
    if (idx >= N * K) return;
    int n = idx / K, k = idx % K;
    float v = W[k * N + n] * scale;
    __nv_bfloat16 h = __float2bfloat16(v);
    size_t dst = (size_t)n * ldout + kOff + k;
    hi[dst] = h;
    lo[dst] = __float2bfloat16(v - __bfloat162float(h));
}

// ---------------------------------------------------------------------------
// Features -> split plane-major bf16
// ---------------------------------------------------------------------------
__global__ void conv_feat_kernel(const float* __restrict__ F, __nv_bfloat16* __restrict__ out,
                                 int M) {
    size_t idx = (size_t)blockIdx.x * blockDim.x + threadIdx.x;
    size_t total = (size_t)M * 640;
    if (idx >= total) return;
    int c = (int)(idx % 640);
    size_t r = idx / 640;
    float v;
    size_t hi_off, lo_off;
    if (c < 256) {
        v = F[r * 640 + c];
        hi_off = r * 256 + c;
        lo_off = (size_t)M * 256 + r * 256 + c;
    } else {
        int t = c - 256;
        int d = t / 128, o = t % 128;
        v = F[r * 640 + 256 + o * 3 + d];
        hi_off = (size_t)M * 512 + (size_t)d * M * 128 + r * 128 + o;
        lo_off = (size_t)M * 896 + (size_t)d * M * 128 + r * 128 + o;
    }
    __nv_bfloat16 h = __float2bfloat16(v);
    out[hi_off] = h;
    out[lo_off] = __float2bfloat16(v - __bfloat162float(h));
}

// ---------------------------------------------------------------------------
// HMMA GEMM: block 128x128, BK=32. No-dup smem [Ah|Al], [Bh|Bl] (SA=72),
// uniform 6-step loop via offset tables. cp.async double buffered.
// A piecewise over K: k < K1 from (Ah,Al,lda,aPlane), else (A2h,A2l,lda2,aPlane2).
// C[gm*ldc + cOff + z*cPlane + gn*cStride] = result
// ---------------------------------------------------------------------------
#define SA 72
#define OPBYTES (128 * SA * 2)          // 18432 per operand
#define STAGE_BYTES (2 * OPBYTES)       // 36864
#define SMEM_BYTES (2 * STAGE_BYTES)    // 73728

__global__ __launch_bounds__(256) void tc_gemm(
    const __nv_bfloat16* __restrict__ Ah, const __nv_bfloat16* __restrict__ Al,
    int lda, size_t aPlane,
    const __nv_bfloat16* __restrict__ A2h, const __nv_bfloat16* __restrict__ A2l,
    int lda2, size_t aPlane2, int K1,
    const __nv_bfloat16* __restrict__ Bh, const __nv_bfloat16* __restrict__ Bl,
    float* __restrict__ C, int ldc, size_t cOff, size_t cPlane, int cStride,
    int M, int K)
{
    extern __shared__ char smem[];
    const uint32_t sb = smem_to_u32(smem);

    const int tid = threadIdx.x;
    const int wid = tid >> 5;
    const int lane = tid & 31;
    const int warp_m = wid & 3;
    const int warp_n = wid >> 2;
    const int bm = blockIdx.y * 128;
    const int bn = blockIdx.x * 128;
    const int z = blockIdx.z;
    Ah  += (size_t)z * aPlane;
    Al  += (size_t)z * aPlane;
    A2h += (size_t)z * aPlane2;
    A2l += (size_t)z * aPlane2;
    C   += cOff + (size_t)z * cPlane;

    const int quad = lane >> 3;
    const int rsel = (lane & 7) + ((quad & 1) << 3);
    const int ksel = (quad >> 1) << 3;

    float acc[2][8][4];
#pragma unroll
    for (int mi = 0; mi < 2; mi++)
#pragma unroll
        for (int nj = 0; nj < 8; nj++)
#pragma unroll
            for (int r = 0; r < 4; r++) acc[mi][nj][r] = 0.f;

    const int nkt = K / 32;

    auto prefetch = [&](int kt, int st) {
        int k0 = kt * 32;
        const __nv_bfloat16 *pAh, *pAl;
        int plda, kk;
        if (k0 < K1) { pAh = Ah;  pAl = Al;  plda = lda;  kk = k0; }
        else         { pAh = A2h; pAl = A2l; plda = lda2; kk = k0 - K1; }
        const uint32_t base = sb + st * STAGE_BYTES;
        // A: 128 rows x 8 chunks (hi c0-3, lo c4-7), 16B each
#pragma unroll
        for (int i = 0; i < 4; i++) {
            int t = tid + i * 256;
            int row = t >> 3, c = t & 7;
            int gm = bm + row;
            const __nv_bfloat16* src =
                ((c < 4) ? pAh : pAl) + (size_t)gm * plda + kk + (c & 3) * 8;
            uint32_t dst = base + (uint32_t)(row * SA) * 2 + c * 16;
            int sz = (gm < M) ? 16 : 0;
            CP_ASYNC16(dst, src, sz);
        }
        // B: 128 n-rows x 8 chunks (hi c0-3, lo c4-7)
#pragma unroll
        for (int i = 0; i < 4; i++) {
            int t = tid + i * 256;
            int row = t >> 3, c = t & 7;
            const __nv_bfloat16* src =
                ((c < 4) ? Bh : Bl) + (size_t)(bn + row) * K + k0 + (c & 3) * 8;
            uint32_t dst = base + OPBYTES + (uint32_t)(row * SA) * 2 + c * 16;
            CP_ASYNC16(dst, src, 16);
        }
    };

    prefetch(0, 0);
    CP_COMMIT;

    // byte offsets per k16-step: A = [Ah|Ah|Al], B = [Bh|Bl|Bh]
    const int aofs[6] = {0, 32, 0, 32, 64, 96};
    const int bofs[6] = {0, 32, 64, 96, 0, 32};

    for (int kt = 0; kt < nkt; kt++) {
        if (kt + 1 < nkt) { prefetch(kt + 1, (kt + 1) & 1); CP_COMMIT; }
        if (kt + 1 < nkt) { CP_WAIT1; } else { CP_WAIT0; }
        __syncthreads();

        const uint32_t sbase = sb + (kt & 1) * STAGE_BYTES;
        const uint32_t aAddr0 = sbase + (uint32_t)((warp_m * 32 + rsel) * SA + ksel) * 2;
        const uint32_t aAddr1 = aAddr0 + 16 * SA * 2;
        const uint32_t bAddr0 = sbase + OPBYTES + (uint32_t)((warp_n * 64 + rsel) * SA + ksel) * 2;

#pragma unroll
        for (int ks = 0; ks < 6; ks++) {
            uint32_t af0[4], af1[4];
            ldm4(af0[0], af0[1], af0[2], af0[3], aAddr0 + aofs[ks]);
            ldm4(af1[0], af1[1], af1[2], af1[3], aAddr1 + aofs[ks]);
            uint32_t bf[8][2];
#pragma unroll
            for (int j2 = 0; j2 < 4; j2++) {
                uint32_t r0, r1, r2, r3;
                ldm4(r0, r1, r2, r3, bAddr0 + (uint32_t)(j2 * 16 * SA) * 2 + bofs[ks]);
                bf[2 * j2][0] = r0; bf[2 * j2 + 1][0] = r1;
                bf[2 * j2][1] = r2; bf[2 * j2 + 1][1] = r3;
            }
#pragma unroll
            for (int mi = 0; mi < 2; mi++)
#pragma unroll
                for (int nj = 0; nj < 8; nj++)
                    mma16816(acc[mi][nj], mi ? af1 : af0, bf[nj]);
        }
        __syncthreads();
    }

    // ---- epilogue ----
    const int tq = lane >> 2;
    const int tr = lane & 3;
#pragma unroll
    for (int mi = 0; mi < 2; mi++) {
#pragma unroll
        for (int half = 0; half < 2; half++) {
            int gm = bm + warp_m * 32 + mi * 16 + tq + half * 8;
            if (gm >= M) continue;
            if (cStride == 1) {
                float* Crow = C + (size_t)gm * ldc + bn + warp_n * 64;
#pragma unroll
                for (int nj = 0; nj < 8; nj++) {
                    int cn = nj * 8 + tr * 2;
                    float2 v = make_float2(acc[mi][nj][half * 2], acc[mi][nj][half * 2 + 1]);
                    *(float2*)&Crow[cn] = v;
                }
            } else {
                float* Crow = C + (size_t)gm * ldc;
#pragma unroll
                for (int nj = 0; nj < 8; nj++) {
                    int gn0 = bn + warp_n * 64 + nj * 8 + tr * 2;
                    Crow[(size_t)gn0 * 3] = acc[mi][nj][half * 2];
                    Crow[(size_t)(gn0 + 1) * 3] = acc[mi][nj][half * 2 + 1];
                }
            }
        }
    }
}

// ---------------------------------------------------------------------------
// Gate (vectorized): pre (plane-major fp32) -> h (split bf16 planes)
// quads: q<128 scalar (silu), else vec (v*sigmoid(g)); 4 elems per thread
// ---------------------------------------------------------------------------
__global__ void gate_kernel(const float* __restrict__ pre, __nv_bfloat16* __restrict__ h, int M)
{
    size_t idx = (size_t)blockIdx.x * blockDim.x + threadIdx.x;
    size_t total = (size_t)M * 320;
    if (idx >= total) return;
    int q = (int)(idx % 320);
    size_t r = idx / 320;
    float v0, v1, v2, v3;
    size_t hi_off, lo_off;   // element offsets (multiples of 4)
    if (q < 128) {
        float4 s = *(const float4*)&pre[r * 768 + q * 4];
        v0 = s.x / (1.f + __expf(-s.x));
        v1 = s.y / (1.f + __expf(-s.y));
        v2 = s.z / (1.f + __expf(-s.z));
        v3 = s.w / (1.f + __expf(-s.w));
        hi_off = r * 512 + q * 4;
        lo_off = (size_t)M * 512 + hi_off;
    } else {
        int t = q - 128;
        int d = t / 64, o4 = (t % 64) * 4;
        float4 g = *(const float4*)&pre[r * 768 + 512 + o4];
        float4 v = *(const float4*)&pre[(size_t)M * 768 + (size_t)d * M * 256 + r * 256 + o4];
        v0 = v.x / (1.f + __expf(-g.x));
        v1 = v.y / (1.f + __expf(-g.y));
        v2 = v.z / (1.f + __expf(-g.z));
        v3 = v.w / (1.f + __expf(-g.w));
        hi_off = (size_t)M * 1024 + (size_t)d * M * 256 + r * 256 + o4;
        lo_off = (size_t)M * 768 + hi_off;   // lo planes start M*1792 = hi + M*768
    }
    __nv_bfloat162 h01 = __floats2bfloat162_rn(v0, v1);
    __nv_bfloat162 h23 = __floats2bfloat162_rn(v2, v3);
    float2 f01 = __bfloat1622float2(h01);
    float2 f23 = __bfloat1622float2(h23);
    __nv_bfloat162 l01 = __floats2bfloat162_rn(v0 - f01.x, v1 - f01.y);
    __nv_bfloat162 l23 = __floats2bfloat162_rn(v2 - f23.x, v3 - f23.y);
    *(uint2*)&h[hi_off] = make_uint2(*(uint32_t*)&h01, *(uint32_t*)&h23);
    *(uint2*)&h[lo_off] = make_uint2(*(uint32_t*)&l01, *(uint32_t*)&l23);
}

// ---------------------------------------------------------------------------
// Batch-norm (deterministic two-stage reduction)
// ---------------------------------------------------------------------------
__global__ void bn_partial_kernel(const float* __restrict__ out,
                                  float* __restrict__ psum, float* __restrict__ psq, int M)
{
    int c = threadIdx.x;
    float s = 0.f, sq = 0.f;
    for (int r = blockIdx.x; r < M; r += gridDim.x) {
        float x = out[(size_t)r * 640 + c];
        s += x; sq += x * x;
    }
    psq[blockIdx.x * 640 + c] = sq;
    if (c < 256) psum[blockIdx.x * 256 + c] = s;
}

__global__ void bn_final_kernel(const float* __restrict__ psum, const float* __restrict__ psq,
                                const float* __restrict__ w, const float* __restrict__ b,
                                float* __restrict__ scale, float* __restrict__ shift, int M)
{
    __shared__ float ssq[640];
    __shared__ float ssum[256];
    int c = threadIdx.x;
    float sq = 0.f;
    for (int p = 0; p < NPART; p++) sq += psq[p * 640 + c];
    ssq[c] = sq;
    if (c < 256) {
        float s = 0.f;
        for (int p = 0; p < NPART; p++) s += psum[p * 256 + c];
        ssum[c] = s;
    }
    __syncthreads();
    float invN = 1.f / (float)M;
    if (c < 256) {
        float m = ssum[c] * invN;
        float var = ssq[c] * invN - m * m;
        float inv = rsqrtf(var + 1e-5f);
        float sc = inv * w[c];
        scale[c] = sc;
        shift[c] = b[c] - m * sc;
    } else if (c < 256 + 128) {
        int ch = c - 256;
        float t = ssq[256 + 3 * ch] + ssq[256 + 3 * ch + 1] + ssq[256 + 3 * ch + 2];
        float mean = t * invN * (1.f / 3.f);
        float inv = rsqrtf(mean + 1e-5f);
        float sc = inv * w[256 + ch];
#pragma unroll
        for (int d2 = 0; d2 < 3; d2++) {
            scale[256 + 3 * ch + d2] = sc;
            shift[256 + 3 * ch + d2] = 0.f;
        }
    }
}

__global__ void bn_apply_kernel(float* __restrict__ out,
                                const float* __restrict__ scale,
                                const float* __restrict__ shift, int M)
{
    size_t idx = (size_t)blockIdx.x * blockDim.x + threadIdx.x;
    size_t total = (size_t)M * 160;
    if (idx >= total) return;
    int c4 = (int)(idx % 160) * 4;
    size_t r = idx / 160;
    float4 x = *(float4*)&out[r * 640 + c4];
    float4 s = *(const float4*)&scale[c4];
    float4 t = *(const float4*)&shift[c4];
    x.x = x.x * s.x + t.x;
    x.y = x.y * s.y + t.y;
    x.z = x.z * s.z + t.z;
    x.w = x.w * s.w + t.w;
    *(float4*)&out[r * 640 + c4] = x;
}

// ---------------------------------------------------------------------------
extern "C" void kernel_launch(void* const* d_in, const int* in_sizes, int n_in,
                              void* d_out, int out_size)
{
    const float* features = (const float*)d_in[0];
    const float* W10 = (const float*)d_in[1];
    const float* W11 = (const float*)d_in[2];
    const float* W20 = (const float*)d_in[3];
    const float* W21 = (const float*)d_in[4];
    const float* W30 = (const float*)d_in[5];
    const float* W31 = (const float*)d_in[6];
    const float* B0  = (const float*)d_in[7];
    const float* B1  = (const float*)d_in[8];
    const float* bw  = (const float*)d_in[9];
    const float* bb  = (const float*)d_in[10];
    float* out = (float*)d_out;

    float *pre, *psum, *psq, *sc, *sh;
    __nv_bfloat16 *wb, *h, *ft;
    cudaGetSymbolAddress((void**)&pre, g_pre);
    cudaGetSymbolAddress((void**)&h, g_hbuf);
    cudaGetSymbolAddress((void**)&ft, g_feat);
    cudaGetSymbolAddress((void**)&psum, g_psum);
    cudaGetSymbolAddress((void**)&psq, g_psq);
    cudaGetSymbolAddress((void**)&sc, g_scale);
    cudaGetSymbolAddress((void**)&sh, g_shift);
    cudaGetSymbolAddress((void**)&wb, g_wbuf);

    const size_t M = MROWS;
    const float s256 = 0.0625f;
    const float s128 = 0.08838834764831845f;
    const float s512 = 0.04419417382415922f;

    // weight offsets (elements); L3 merged: [W30|B0] ld=768, [W31|B1] ld=384
    const int o10 = 0;           // [768,256]
    const int o11 = 196608;      // [256,128]
    const int o20 = 229376;      // [768,512]
    const int o21 = 622592;      // [256,256]
    const int oL3s = 688128;     // [256,768]
    const int oL3v = 884736;     // [128,384]
    __nv_bfloat16* lo = wb + WTOT;

    // ---- preconvert weights + features ----
    {
        struct { const float* W; int K, N, off, ld, kOff; float s; } cw[8] = {
            {W10, 256, 768, o10,  256, 0,   s256},
            {W11, 128, 256, o11,  128, 0,   s128},
            {W20, 512, 768, o20,  512, 0,   s512},
            {W21, 256, 256, o21,  256, 0,   s256},
            {W30, 512, 256, oL3s, 768, 0,   s512},
            {B0,  256, 256, oL3s, 768, 512, s256},
            {W31, 256, 128, oL3v, 384, 0,   s256},
            {B1,  128, 128, oL3v, 384, 256, s128}};
        for (int i = 0; i < 8; i++) {
            int tot = cw[i].K * cw[i].N;
            conv_w_kernel<<<(tot + 255) / 256, 256>>>(cw[i].W, cw[i].K, cw[i].N, cw[i].s,
                                                      wb + cw[i].off, lo + cw[i].off,
                                                      cw[i].ld, cw[i].kOff);
        }
        size_t tot = M * 640;
        conv_feat_kernel<<<(unsigned)((tot + 255) / 256), 256>>>(features, ft, (int)M);
    }

    const int gy = (int)((M + 127) / 128);
    cudaFuncSetAttribute(tc_gemm, cudaFuncAttributeMaxDynamicSharedMemorySize, SMEM_BYTES);

    __nv_bfloat16* fs_h = ft;
    __nv_bfloat16* fs_l = ft + M * 256;
    __nv_bfloat16* fv_h = ft + M * 512;
    __nv_bfloat16* fv_l = ft + M * 896;
    __nv_bfloat16* hs_h = h;
    __nv_bfloat16* hs_l = h + M * 512;
    __nv_bfloat16* hv_h = h + M * 1024;
    __nv_bfloat16* hv_l = h + M * 1792;

    // ---- layer 1 ----
    tc_gemm<<<dim3(6, gy, 1), 256, SMEM_BYTES>>>(
        fs_h, fs_l, 256, 0, fs_h, fs_l, 256, 0, 256,
        wb + o10, lo + o10, pre, 768, 0, 0, 1, (int)M, 256);
    tc_gemm<<<dim3(2, gy, 3), 256, SMEM_BYTES>>>(
        fv_h, fv_l, 128, M * 128, fv_h, fv_l, 128, M * 128, 128,
        wb + o11, lo + o11, pre, 256, M * 768, M * 256, 1, (int)M, 128);
    {
        size_t total = M * 320;
        gate_kernel<<<(unsigned)((total + 255) / 256), 256>>>(pre, h, (int)M);
    }
    // ---- layer 2 ----
    tc_gemm<<<dim3(6, gy, 1), 256, SMEM_BYTES>>>(
        hs_h, hs_l, 512, 0, hs_h, hs_l, 512, 0, 512,
        wb + o20, lo + o20, pre, 768, 0, 0, 1, (int)M, 512);
    tc_gemm<<<dim3(2, gy, 3), 256, SMEM_BYTES>>>(
        hv_h, hv_l, 256, M * 256, hv_h, hv_l, 256, M * 256, 256,
        wb + o21, lo + o21, pre, 256, M * 768, M * 256, 1, (int)M, 256);
    {
        size_t total = M * 320;
        gate_kernel<<<(unsigned)((total + 255) / 256), 256>>>(pre, h, (int)M);
    }
    // ---- layer 3 + bypass (merged via K-concat) ----
    tc_gemm<<<dim3(2, gy, 1), 256, SMEM_BYTES>>>(
        hs_h, hs_l, 512, 0, fs_h, fs_l, 256, 0, 512,
        wb + oL3s, lo + oL3s, out, 640, 0, 0, 1, (int)M, 768);
    tc_gemm<<<dim3(1, gy, 3), 256, SMEM_BYTES>>>(
        hv_h, hv_l, 256, M * 256, fv_h, fv_l, 128, M * 128, 256,
        wb + oL3v, lo + oL3v, out, 640, 256, 1, 3, (int)M, 384);

    // ---- batch norm ----
    bn_partial_kernel<<<NPART, 640>>>(out, psum, psq, (int)M);
    bn_final_kernel<<<1, 640>>>(psum, psq, bw, bb, sc, sh, (int)M);
    {
        size_t total = M * 160;
        bn_apply_kernel<<<(unsigned)((total + 255) / 256), 256>>>(out, sc, sh, (int)M);
    }
}

// round 7
// speedup vs baseline: 2.7066x; 1.4566x over previous
#include <cuda_runtime.h>
#include <cuda_fp16.h>
#include <cstdint>
#include <cstddef>

// ===========================================================================
// FeedForward via mma.sync fp16 2-term split: C = A*(Bh + Bl)
//   A: activations, single fp16 plane, GEMM scale (1/sqrt(Kin)) folded in.
//   B: weights, fp16 hi/lo split, UNSCALED (keeps Bl in normal fp16 range).
// R6 skeleton: no-dup smem + offset tables, cp.async double buffer, L3 merge.
// ===========================================================================

#define MROWS 100000

// ------------------------------- scratch -----------------------------------
__device__ float g_pre[(size_t)MROWS * 1536];
__device__ __half g_hbuf[(size_t)MROWS * 1280];   // hs [M,512] | hv[d] [M,256]
__device__ __half g_feat[(size_t)MROWS * 640];    // fs [M,256] | fv[d] [M,128]
#define NPART 512
__device__ float g_psum[NPART * 256];
__device__ float g_psq[NPART * 640];
__device__ float g_scale[640];
__device__ float g_shift[640];
#define WTOT 933888
__device__ __align__(256) __half g_wbuf[2 * WTOT];

// --------------------------- helpers ---------------------------------------
__device__ __forceinline__ uint32_t smem_to_u32(const void* p) {
    uint32_t a;
    asm("{ .reg .u64 t; cvta.to.shared.u64 t, %1; cvt.u32.u64 %0, t; }" : "=r"(a) : "l"(p));
    return a;
}
__device__ __forceinline__ void ldm4(uint32_t& r0, uint32_t& r1, uint32_t& r2, uint32_t& r3,
                                     uint32_t addr) {
    asm volatile("ldmatrix.sync.aligned.m8n8.x4.shared.b16 {%0,%1,%2,%3}, [%4];"
                 : "=r"(r0), "=r"(r1), "=r"(r2), "=r"(r3) : "r"(addr));
}
__device__ __forceinline__ void mma16816(float* c, const uint32_t* a, const uint32_t* b) {
    asm volatile(
        "mma.sync.aligned.m16n8k16.row.col.f32.f16.f16.f32 "
        "{%0,%1,%2,%3}, {%4,%5,%6,%7}, {%8,%9}, {%0,%1,%2,%3};"
        : "+f"(c[0]), "+f"(c[1]), "+f"(c[2]), "+f"(c[3])
        : "r"(a[0]), "r"(a[1]), "r"(a[2]), "r"(a[3]), "r"(b[0]), "r"(b[1]));
}
#define CP_ASYNC16(dst, src, sz) \
    asm volatile("cp.async.cg.shared.global [%0], [%1], 16, %2;" \
                 :: "r"(dst), "l"(src), "r"(sz) : "memory")
#define CP_COMMIT asm volatile("cp.async.commit_group;" ::: "memory")
#define CP_WAIT1 asm volatile("cp.async.wait_group 1;" ::: "memory")
#define CP_WAIT0 asm volatile("cp.async.wait_group 0;" ::: "memory")

// ---------------------------------------------------------------------------
// Weight prep: W[K,N] fp32 -> hi/lo fp16 [N,*] K-major (UNSCALED), dest row
// stride ldout, column offset kOff (merged concatenated weights).
// ---------------------------------------------------------------------------
__global__ void conv_w_kernel(const float* __restrict__ W, int K, int N,
                              __half* __restrict__ hi, __half* __restrict__ lo,
                              int ldout, int kOff) {
    int idx = blockIdx.x * blockDim.x + threadIdx.x;
    if (idx >= N * K) return;
    int n = idx / K, k = idx % K;
    float v = W[k * N + n];
    __half h = __float2half_rn(v);
    size_t dst = (size_t)n * ldout + kOff + k;
    hi[dst] = h;
    lo[dst] = __float2half_rn(v - __half2float(h));
}

// ---------------------------------------------------------------------------
// Features -> plane-major fp16, scale folded (s: *s256, v: *s128)
// ---------------------------------------------------------------------------
__global__ void conv_feat_kernel(const float* __restrict__ F, __half* __restrict__ out,
                                 int M) {
    size_t idx = (size_t)blockIdx.x * blockDim.x + threadIdx.x;
    size_t total = (size_t)M * 640;
    if (idx >= total) return;
    int c = (int)(idx % 640);
    size_t r = idx / 640;
    const float s256 = 0.0625f;
    const float s128 = 0.08838834764831845f;
    float v;
    size_t off;
    if (c < 256) {
        v = F[r * 640 + c] * s256;
        off = r * 256 + c;
    } else {
        int t = c - 256;
        int d = t / 128, o = t % 128;
        v = F[r * 640 + 256 + o * 3 + d] * s128;
        off = (size_t)M * 256 + (size_t)d * M * 128 + r * 128 + o;
    }
    out[off] = __float2half_rn(v);
}

// ---------------------------------------------------------------------------
// HMMA GEMM: block 128x128, BK=32. A single fp16 plane (32 cols),
// B split [Bh|Bl] (64 cols). Uniform 4-step loop. cp.async double buffered.
// A piecewise over K (K1 boundary) for the merged layer3+bypass GEMMs.
// ---------------------------------------------------------------------------
#define SAA 40                      // A smem row stride (halfs), 80 B
#define SAB 72                      // B smem row stride (halfs), 144 B
#define ABY (128 * SAA * 2)         // 10240
#define BBY (128 * SAB * 2)         // 18432
#define STAGE_BYTES (ABY + BBY)     // 28672
#define SMEM_BYTES (2 * STAGE_BYTES)// 57344

__global__ __launch_bounds__(256) void tc_gemm(
    const __half* __restrict__ A, int lda, size_t aPlane,
    const __half* __restrict__ A2, int lda2, size_t aPlane2, int K1,
    const __half* __restrict__ Bh, const __half* __restrict__ Bl,
    float* __restrict__ C, int ldc, size_t cOff, size_t cPlane, int cStride,
    int M, int K)
{
    extern __shared__ char smem[];
    const uint32_t sb = smem_to_u32(smem);

    const int tid = threadIdx.x;
    const int wid = tid >> 5;
    const int lane = tid & 31;
    const int warp_m = wid & 3;
    const int warp_n = wid >> 2;
    const int bm = blockIdx.y * 128;
    const int bn = blockIdx.x * 128;
    const int z = blockIdx.z;
    A  += (size_t)z * aPlane;
    A2 += (size_t)z * aPlane2;
    C  += cOff + (size_t)z * cPlane;

    const int quad = lane >> 3;
    const int rsel = (lane & 7) + ((quad & 1) << 3);
    const int ksel = (quad >> 1) << 3;

    float acc[2][8][4];
#pragma unroll
    for (int mi = 0; mi < 2; mi++)
#pragma unroll
        for (int nj = 0; nj < 8; nj++)
#pragma unroll
            for (int r = 0; r < 4; r++) acc[mi][nj][r] = 0.f;

    const int nkt = K / 32;

    auto prefetch = [&](int kt, int st) {
        int k0 = kt * 32;
        const __half* pA;
        int plda, kk;
        if (k0 < K1) { pA = A;  plda = lda;  kk = k0; }
        else         { pA = A2; plda = lda2; kk = k0 - K1; }
        const uint32_t base = sb + st * STAGE_BYTES;
        // A: 128 rows x 4 chunks of 16B
#pragma unroll
        for (int i = 0; i < 2; i++) {
            int t = tid + i * 256;
            int row = t >> 2, c = t & 3;
            int gm = bm + row;
            const __half* src = pA + (size_t)gm * plda + kk + c * 8;
            uint32_t dst = base + (uint32_t)(row * SAA) * 2 + c * 16;
            int sz = (gm < M) ? 16 : 0;
            CP_ASYNC16(dst, src, sz);
        }
        // B: 128 n-rows x 8 chunks (hi c0-3, lo c4-7)
#pragma unroll
        for (int i = 0; i < 4; i++) {
            int t = tid + i * 256;
            int row = t >> 3, c = t & 7;
            const __half* src =
                ((c < 4) ? Bh : Bl) + (size_t)(bn + row) * K + k0 + (c & 3) * 8;
            uint32_t dst = base + ABY + (uint32_t)(row * SAB) * 2 + c * 16;
            CP_ASYNC16(dst, src, 16);
        }
    };

    prefetch(0, 0);
    CP_COMMIT;

    // byte offsets per k16-step: A = [A|A], B = [Bh|Bl]
    const int aofs[4] = {0, 32, 0, 32};
    const int bofs[4] = {0, 32, 64, 96};

    for (int kt = 0; kt < nkt; kt++) {
        if (kt + 1 < nkt) { prefetch(kt + 1, (kt + 1) & 1); CP_COMMIT; }
        if (kt + 1 < nkt) { CP_WAIT1; } else { CP_WAIT0; }
        __syncthreads();

        const uint32_t sbase = sb + (kt & 1) * STAGE_BYTES;
        const uint32_t aAddr0 = sbase + (uint32_t)((warp_m * 32 + rsel) * SAA + ksel) * 2;
        const uint32_t aAddr1 = aAddr0 + 16 * SAA * 2;
        const uint32_t bAddr0 = sbase + ABY + (uint32_t)((warp_n * 64 + rsel) * SAB + ksel) * 2;

#pragma unroll
        for (int ks = 0; ks < 4; ks++) {
            uint32_t af0[4], af1[4];
            ldm4(af0[0], af0[1], af0[2], af0[3], aAddr0 + aofs[ks]);
            ldm4(af1[0], af1[1], af1[2], af1[3], aAddr1 + aofs[ks]);
            uint32_t bf[8][2];
#pragma unroll
            for (int j2 = 0; j2 < 4; j2++) {
                uint32_t r0, r1, r2, r3;
                ldm4(r0, r1, r2, r3, bAddr0 + (uint32_t)(j2 * 16 * SAB) * 2 + bofs[ks]);
                bf[2 * j2][0] = r0; bf[2 * j2 + 1][0] = r1;
                bf[2 * j2][1] = r2; bf[2 * j2 + 1][1] = r3;
            }
#pragma unroll
            for (int mi = 0; mi < 2; mi++)
#pragma unroll
                for (int nj = 0; nj < 8; nj++)
                    mma16816(acc[mi][nj], mi ? af1 : af0, bf[nj]);
        }
        __syncthreads();
    }

    // ---- epilogue ----
    const int tq = lane >> 2;
    const int tr = lane & 3;
#pragma unroll
    for (int mi = 0; mi < 2; mi++) {
#pragma unroll
        for (int half = 0; half < 2; half++) {
            int gm = bm + warp_m * 32 + mi * 16 + tq + half * 8;
            if (gm >= M) continue;
            if (cStride == 1) {
                float* Crow = C + (size_t)gm * ldc + bn + warp_n * 64;
#pragma unroll
                for (int nj = 0; nj < 8; nj++) {
                    int cn = nj * 8 + tr * 2;
                    *(float2*)&Crow[cn] =
                        make_float2(acc[mi][nj][half * 2], acc[mi][nj][half * 2 + 1]);
                }
            } else {
                float* Crow = C + (size_t)gm * ldc;
#pragma unroll
                for (int nj = 0; nj < 8; nj++) {
                    int gn0 = bn + warp_n * 64 + nj * 8 + tr * 2;
                    Crow[(size_t)gn0 * 3] = acc[mi][nj][half * 2];
                    Crow[(size_t)(gn0 + 1) * 3] = acc[mi][nj][half * 2 + 1];
                }
            }
        }
    }
}

// ---------------------------------------------------------------------------
// Gate: pre (plane-major fp32) -> h (fp16, next-layer scale folded)
// ---------------------------------------------------------------------------
__global__ void gate_kernel(const float* __restrict__ pre, __half* __restrict__ h, int M)
{
    size_t idx = (size_t)blockIdx.x * blockDim.x + threadIdx.x;
    size_t total = (size_t)M * 320;
    if (idx >= total) return;
    int q = (int)(idx % 320);
    size_t r = idx / 320;
    const float s512 = 0.04419417382415922f;
    const float s256 = 0.0625f;
    float v0, v1, v2, v3;
    size_t off;
    if (q < 128) {
        float4 s = *(const float4*)&pre[r * 768 + q * 4];
        v0 = s.x / (1.f + __expf(-s.x)) * s512;
        v1 = s.y / (1.f + __expf(-s.y)) * s512;
        v2 = s.z / (1.f + __expf(-s.z)) * s512;
        v3 = s.w / (1.f + __expf(-s.w)) * s512;
        off = r * 512 + q * 4;
    } else {
        int t = q - 128;
        int d = t / 64, o4 = (t % 64) * 4;
        float4 g = *(const float4*)&pre[r * 768 + 512 + o4];
        float4 v = *(const float4*)&pre[(size_t)M * 768 + (size_t)d * M * 256 + r * 256 + o4];
        v0 = v.x / (1.f + __expf(-g.x)) * s256;
        v1 = v.y / (1.f + __expf(-g.y)) * s256;
        v2 = v.z / (1.f + __expf(-g.z)) * s256;
        v3 = v.w / (1.f + __expf(-g.w)) * s256;
        off = (size_t)M * 512 + (size_t)d * M * 256 + r * 256 + o4;
    }
    __half2 p01 = __floats2half2_rn(v0, v1);
    __half2 p23 = __floats2half2_rn(v2, v3);
    *(uint2*)&h[off] = make_uint2(*(uint32_t*)&p01, *(uint32_t*)&p23);
}

// ---------------------------------------------------------------------------
// Batch-norm (deterministic two-stage reduction)
// ---------------------------------------------------------------------------
__global__ void bn_partial_kernel(const float* __restrict__ out,
                                  float* __restrict__ psum, float* __restrict__ psq, int M)
{
    int c = threadIdx.x;
    float s = 0.f, sq = 0.f;
    for (int r = blockIdx.x; r < M; r += gridDim.x) {
        float x = out[(size_t)r * 640 + c];
        s += x; sq += x * x;
    }
    psq[blockIdx.x * 640 + c] = sq;
    if (c < 256) psum[blockIdx.x * 256 + c] = s;
}

__global__ void bn_final_kernel(const float* __restrict__ psum, const float* __restrict__ psq,
                                const float* __restrict__ w, const float* __restrict__ b,
                                float* __restrict__ scale, float* __restrict__ shift, int M)
{
    __shared__ float ssq[640];
    __shared__ float ssum[256];
    int c = threadIdx.x;
    float sq = 0.f;
    for (int p = 0; p < NPART; p++) sq += psq[p * 640 + c];
    ssq[c] = sq;
    if (c < 256) {
        float s = 0.f;
        for (int p = 0; p < NPART; p++) s += psum[p * 256 + c];
        ssum[c] = s;
    }
    __syncthreads();
    float invN = 1.f / (float)M;
    if (c < 256) {
        float m = ssum[c] * invN;
        float var = ssq[c] * invN - m * m;
        float inv = rsqrtf(var + 1e-5f);
        float sc = inv * w[c];
        scale[c] = sc;
        shift[c] = b[c] - m * sc;
    } else if (c < 256 + 128) {
        int ch = c - 256;
        float t = ssq[256 + 3 * ch] + ssq[256 + 3 * ch + 1] + ssq[256 + 3 * ch + 2];
        float mean = t * invN * (1.f / 3.f);
        float inv = rsqrtf(mean + 1e-5f);
        float sc = inv * w[256 + ch];
#pragma unroll
        for (int d2 = 0; d2 < 3; d2++) {
            scale[256 + 3 * ch + d2] = sc;
            shift[256 + 3 * ch + d2] = 0.f;
        }
    }
}

__global__ void bn_apply_kernel(float* __restrict__ out,
                                const float* __restrict__ scale,
                                const float* __restrict__ shift, int M)
{
    size_t idx = (size_t)blockIdx.x * blockDim.x + threadIdx.x;
    size_t total = (size_t)M * 160;
    if (idx >= total) return;
    int c4 = (int)(idx % 160) * 4;
    size_t r = idx / 160;
    float4 x = *(float4*)&out[r * 640 + c4];
    float4 s = *(const float4*)&scale[c4];
    float4 t = *(const float4*)&shift[c4];
    x.x = x.x * s.x + t.x;
    x.y = x.y * s.y + t.y;
    x.z = x.z * s.z + t.z;
    x.w = x.w * s.w + t.w;
    *(float4*)&out[r * 640 + c4] = x;
}

// ---------------------------------------------------------------------------
extern "C" void kernel_launch(void* const* d_in, const int* in_sizes, int n_in,
                              void* d_out, int out_size)
{
    const float* features = (const float*)d_in[0];
    const float* W10 = (const float*)d_in[1];
    const float* W11 = (const float*)d_in[2];
    const float* W20 = (const float*)d_in[3];
    const float* W21 = (const float*)d_in[4];
    const float* W30 = (const float*)d_in[5];
    const float* W31 = (const float*)d_in[6];
    const float* B0  = (const float*)d_in[7];
    const float* B1  = (const float*)d_in[8];
    const float* bw  = (const float*)d_in[9];
    const float* bb  = (const float*)d_in[10];
    float* out = (float*)d_out;

    float *pre, *psum, *psq, *sc, *sh;
    __half *wb, *h, *ft;
    cudaGetSymbolAddress((void**)&pre, g_pre);
    cudaGetSymbolAddress((void**)&h, g_hbuf);
    cudaGetSymbolAddress((void**)&ft, g_feat);
    cudaGetSymbolAddress((void**)&psum, g_psum);
    cudaGetSymbolAddress((void**)&psq, g_psq);
    cudaGetSymbolAddress((void**)&sc, g_scale);
    cudaGetSymbolAddress((void**)&sh, g_shift);
    cudaGetSymbolAddress((void**)&wb, g_wbuf);

    const size_t M = MROWS;

    // weight offsets (elements); L3 merged: [W30|B0] ld=768, [W31|B1] ld=384
    const int o10 = 0;           // [768,256]
    const int o11 = 196608;      // [256,128]
    const int o20 = 229376;      // [768,512]
    const int o21 = 622592;      // [256,256]
    const int oL3s = 688128;     // [256,768]
    const int oL3v = 884736;     // [128,384]
    __half* lo = wb + WTOT;

    // ---- preconvert weights (unscaled) + features (scale folded) ----
    {
        struct { const float* W; int K, N, off, ld, kOff; } cw[8] = {
            {W10, 256, 768, o10,  256, 0},
            {W11, 128, 256, o11,  128, 0},
            {W20, 512, 768, o20,  512, 0},
            {W21, 256, 256, o21,  256, 0},
            {W30, 512, 256, oL3s, 768, 0},
            {B0,  256, 256, oL3s, 768, 512},
            {W31, 256, 128, oL3v, 384, 0},
            {B1,  128, 128, oL3v, 384, 256}};
        for (int i = 0; i < 8; i++) {
            int tot = cw[i].K * cw[i].N;
            conv_w_kernel<<<(tot + 255) / 256, 256>>>(cw[i].W, cw[i].K, cw[i].N,
                                                      wb + cw[i].off, lo + cw[i].off,
                                                      cw[i].ld, cw[i].kOff);
        }
        size_t tot = M * 640;
        conv_feat_kernel<<<(unsigned)((tot + 255) / 256), 256>>>(features, ft, (int)M);
    }

    const int gy = (int)((M + 127) / 128);
    cudaFuncSetAttribute(tc_gemm, cudaFuncAttributeMaxDynamicSharedMemorySize, SMEM_BYTES);

    __half* fs = ft;                 // [M,256], *s256
    __half* fv = ft + M * 256;       // 3 planes [M,128], *s128
    __half* hs = h;                  // [M,512], *s512
    __half* hv = h + M * 512;        // 3 planes [M,256], *s256

    // ---- layer 1 ----
    tc_gemm<<<dim3(6, gy, 1), 256, SMEM_BYTES>>>(
        fs, 256, 0, fs, 256, 0, 256,
        wb + o10, lo + o10, pre, 768, 0, 0, 1, (int)M, 256);
    tc_gemm<<<dim3(2, gy, 3), 256, SMEM_BYTES>>>(
        fv, 128, M * 128, fv, 128, M * 128, 128,
        wb + o11, lo + o11, pre, 256, M * 768, M * 256, 1, (int)M, 128);
    {
        size_t total = M * 320;
        gate_kernel<<<(unsigned)((total + 255) / 256), 256>>>(pre, h, (int)M);
    }
    // ---- layer 2 ----
    tc_gemm<<<dim3(6, gy, 1), 256, SMEM_BYTES>>>(
        hs, 512, 0, hs, 512, 0, 512,
        wb + o20, lo + o20, pre, 768, 0, 0, 1, (int)M, 512);
    tc_gemm<<<dim3(2, gy, 3), 256, SMEM_BYTES>>>(
        hv, 256, M * 256, hv, 256, M * 256, 256,
        wb + o21, lo + o21, pre, 256, M * 768, M * 256, 1, (int)M, 256);
    {
        size_t total = M * 320;
        gate_kernel<<<(unsigned)((total + 255) / 256), 256>>>(pre, h, (int)M);
    }
    // ---- layer 3 + bypass (merged via K-concat) ----
    tc_gemm<<<dim3(2, gy, 1), 256, SMEM_BYTES>>>(
        hs, 512, 0, fs, 256, 0, 512,
        wb + oL3s, lo + oL3s, out, 640, 0, 0, 1, (int)M, 768);
    tc_gemm<<<dim3(1, gy, 3), 256, SMEM_BYTES>>>(
        hv, 256, M * 256, fv, 128, M * 128, 256,
        wb + oL3v, lo + oL3v, out, 640, 256, 1, 3, (int)M, 384);

    // ---- batch norm ----
    bn_partial_kernel<<<NPART, 640>>>(out, psum, psq, (int)M);
    bn_final_kernel<<<1, 640>>>(psum, psq, bw, bb, sc, sh, (int)M);
    {
        size_t total = M * 160;
        bn_apply_kernel<<<(unsigned)((total + 255) / 256), 256>>>(out, sc, sh, (int)M);
    }
}

// round 8
// speedup vs baseline: 3.4077x; 1.2591x over previous
#include <cuda_runtime.h>
#include <cuda_fp16.h>
#include <cstdint>
#include <cstddef>

// ===========================================================================
// FeedForward via pure fp16 mma.sync (single term): C = A*B
//   A: activations fp16, GEMM scale (1/sqrt(Kin)) folded in.
//   B: weights fp16 [N,K] K-major, unscaled.
// R7 skeleton: plane-major activations, cp.async double buffer, L3 merge.
// ===========================================================================

#define MROWS 100000

// ------------------------------- scratch -----------------------------------
__device__ float g_pre[(size_t)MROWS * 1536];
__device__ __half g_hbuf[(size_t)MROWS * 1280];   // hs [M,512] | hv[d] [M,256]
__device__ __half g_feat[(size_t)MROWS * 640];    // fs [M,256] | fv[d] [M,128]
#define NPART 512
__device__ float g_psum[NPART * 256];
__device__ float g_psq[NPART * 640];
__device__ float g_scale[640];
__device__ float g_shift[640];
#define WTOT 933888
__device__ __align__(256) __half g_wbuf[WTOT];

// --------------------------- helpers ---------------------------------------
__device__ __forceinline__ uint32_t smem_to_u32(const void* p) {
    uint32_t a;
    asm("{ .reg .u64 t; cvta.to.shared.u64 t, %1; cvt.u32.u64 %0, t; }" : "=r"(a) : "l"(p));
    return a;
}
__device__ __forceinline__ void ldm4(uint32_t& r0, uint32_t& r1, uint32_t& r2, uint32_t& r3,
                                     uint32_t addr) {
    asm volatile("ldmatrix.sync.aligned.m8n8.x4.shared.b16 {%0,%1,%2,%3}, [%4];"
                 : "=r"(r0), "=r"(r1), "=r"(r2), "=r"(r3) : "r"(addr));
}
__device__ __forceinline__ void mma16816(float* c, const uint32_t* a, const uint32_t* b) {
    asm volatile(
        "mma.sync.aligned.m16n8k16.row.col.f32.f16.f16.f32 "
        "{%0,%1,%2,%3}, {%4,%5,%6,%7}, {%8,%9}, {%0,%1,%2,%3};"
        : "+f"(c[0]), "+f"(c[1]), "+f"(c[2]), "+f"(c[3])
        : "r"(a[0]), "r"(a[1]), "r"(a[2]), "r"(a[3]), "r"(b[0]), "r"(b[1]));
}
#define CP_ASYNC16(dst, src, sz) \
    asm volatile("cp.async.cg.shared.global [%0], [%1], 16, %2;" \
                 :: "r"(dst), "l"(src), "r"(sz) : "memory")
#define CP_COMMIT asm volatile("cp.async.commit_group;" ::: "memory")
#define CP_WAIT1 asm volatile("cp.async.wait_group 1;" ::: "memory")
#define CP_WAIT0 asm volatile("cp.async.wait_group 0;" ::: "memory")

// ---------------------------------------------------------------------------
// Weight prep: W[K,N] fp32 -> fp16 [N,*] K-major (unscaled), dest stride ldout,
// column offset kOff (merged concatenated weights).
// ---------------------------------------------------------------------------
__global__ void conv_w_kernel(const float* __restrict__ W, int K, int N,
                              __half* __restrict__ hi, int ldout, int kOff) {
    int idx = blockIdx.x * blockDim.x + threadIdx.x;
    if (idx >= N * K) return;
    int n = idx / K, k = idx % K;
    hi[(size_t)n * ldout + kOff + k] = __float2half_rn(W[k * N + n]);
}

// ---------------------------------------------------------------------------
// Features -> plane-major fp16, scale folded (s: *s256, v: *s128)
// ---------------------------------------------------------------------------
__global__ void conv_feat_kernel(const float* __restrict__ F, __half* __restrict__ out,
                                 int M) {
    size_t idx = (size_t)blockIdx.x * blockDim.x + threadIdx.x;
    size_t total = (size_t)M * 640;
    if (idx >= total) return;
    int c = (int)(idx % 640);
    size_t r = idx / 640;
    const float s256 = 0.0625f;
    const float s128 = 0.08838834764831845f;
    float v;
    size_t off;
    if (c < 256) {
        v = F[r * 640 + c] * s256;
        off = r * 256 + c;
    } else {
        int t = c - 256;
        int d = t / 128, o = t % 128;
        v = F[r * 640 + 256 + o * 3 + d] * s128;
        off = (size_t)M * 256 + (size_t)d * M * 128 + r * 128 + o;
    }
    out[off] = __float2half_rn(v);
}

// ---------------------------------------------------------------------------
// HMMA GEMM: block 128x128, BK=32, pure fp16 operands, 2 k16 steps/tile.
// cp.async double buffered. A piecewise over K (K1 boundary) for L3 merge.
// ---------------------------------------------------------------------------
#define SAA 40                      // smem row stride (halfs), 80 B
#define OPBY (128 * SAA * 2)        // 10240 per operand
#define STAGE_BYTES (2 * OPBY)      // 20480
#define SMEM_BYTES (2 * STAGE_BYTES)// 40960

__global__ __launch_bounds__(256) void tc_gemm(
    const __half* __restrict__ A, int lda, size_t aPlane,
    const __half* __restrict__ A2, int lda2, size_t aPlane2, int K1,
    const __half* __restrict__ B,
    float* __restrict__ C, int ldc, size_t cOff, size_t cPlane, int cStride,
    int M, int K)
{
    extern __shared__ char smem[];
    const uint32_t sb = smem_to_u32(smem);

    const int tid = threadIdx.x;
    const int wid = tid >> 5;
    const int lane = tid & 31;
    const int warp_m = wid & 3;
    const int warp_n = wid >> 2;
    const int bm = blockIdx.y * 128;
    const int bn = blockIdx.x * 128;
    const int z = blockIdx.z;
    A  += (size_t)z * aPlane;
    A2 += (size_t)z * aPlane2;
    C  += cOff + (size_t)z * cPlane;

    const int quad = lane >> 3;
    const int rsel = (lane & 7) + ((quad & 1) << 3);
    const int ksel = (quad >> 1) << 3;

    float acc[2][8][4];
#pragma unroll
    for (int mi = 0; mi < 2; mi++)
#pragma unroll
        for (int nj = 0; nj < 8; nj++)
#pragma unroll
            for (int r = 0; r < 4; r++) acc[mi][nj][r] = 0.f;

    const int nkt = K / 32;

    auto prefetch = [&](int kt, int st) {
        int k0 = kt * 32;
        const __half* pA;
        int plda, kk;
        if (k0 < K1) { pA = A;  plda = lda;  kk = k0; }
        else         { pA = A2; plda = lda2; kk = k0 - K1; }
        const uint32_t base = sb + st * STAGE_BYTES;
        // A: 128 rows x 4 chunks of 16B
#pragma unroll
        for (int i = 0; i < 2; i++) {
            int t = tid + i * 256;
            int row = t >> 2, c = t & 3;
            int gm = bm + row;
            const __half* src = pA + (size_t)gm * plda + kk + c * 8;
            uint32_t dst = base + (uint32_t)(row * SAA) * 2 + c * 16;
            int sz = (gm < M) ? 16 : 0;
            CP_ASYNC16(dst, src, sz);
        }
        // B: 128 n-rows x 4 chunks of 16B
#pragma unroll
        for (int i = 0; i < 2; i++) {
            int t = tid + i * 256;
            int row = t >> 2, c = t & 3;
            const __half* src = B + (size_t)(bn + row) * K + k0 + c * 8;
            uint32_t dst = base + OPBY + (uint32_t)(row * SAA) * 2 + c * 16;
            CP_ASYNC16(dst, src, 16);
        }
    };

    prefetch(0, 0);
    CP_COMMIT;

    for (int kt = 0; kt < nkt; kt++) {
        if (kt + 1 < nkt) { prefetch(kt + 1, (kt + 1) & 1); CP_COMMIT; }
        if (kt + 1 < nkt) { CP_WAIT1; } else { CP_WAIT0; }
        __syncthreads();

        const uint32_t sbase = sb + (kt & 1) * STAGE_BYTES;
        const uint32_t aAddr0 = sbase + (uint32_t)((warp_m * 32 + rsel) * SAA + ksel) * 2;
        const uint32_t aAddr1 = aAddr0 + 16 * SAA * 2;
        const uint32_t bAddr0 = sbase + OPBY + (uint32_t)((warp_n * 64 + rsel) * SAA + ksel) * 2;

#pragma unroll
        for (int ks = 0; ks < 2; ks++) {
            const uint32_t kof = ks * 32;
            uint32_t af0[4], af1[4];
            ldm4(af0[0], af0[1], af0[2], af0[3], aAddr0 + kof);
            ldm4(af1[0], af1[1], af1[2], af1[3], aAddr1 + kof);
            uint32_t bf[8][2];
#pragma unroll
            for (int j2 = 0; j2 < 4; j2++) {
                uint32_t r0, r1, r2, r3;
                ldm4(r0, r1, r2, r3, bAddr0 + (uint32_t)(j2 * 16 * SAA) * 2 + kof);
                bf[2 * j2][0] = r0; bf[2 * j2 + 1][0] = r1;
                bf[2 * j2][1] = r2; bf[2 * j2 + 1][1] = r3;
            }
#pragma unroll
            for (int mi = 0; mi < 2; mi++)
#pragma unroll
                for (int nj = 0; nj < 8; nj++)
                    mma16816(acc[mi][nj], mi ? af1 : af0, bf[nj]);
        }
        __syncthreads();
    }

    // ---- epilogue ----
    const int tq = lane >> 2;
    const int tr = lane & 3;
#pragma unroll
    for (int mi = 0; mi < 2; mi++) {
#pragma unroll
        for (int half = 0; half < 2; half++) {
            int gm = bm + warp_m * 32 + mi * 16 + tq + half * 8;
            if (gm >= M) continue;
            if (cStride == 1) {
                float* Crow = C + (size_t)gm * ldc + bn + warp_n * 64;
#pragma unroll
                for (int nj = 0; nj < 8; nj++) {
                    int cn = nj * 8 + tr * 2;
                    *(float2*)&Crow[cn] =
                        make_float2(acc[mi][nj][half * 2], acc[mi][nj][half * 2 + 1]);
                }
            } else {
                float* Crow = C + (size_t)gm * ldc;
#pragma unroll
                for (int nj = 0; nj < 8; nj++) {
                    int gn0 = bn + warp_n * 64 + nj * 8 + tr * 2;
                    Crow[(size_t)gn0 * 3] = acc[mi][nj][half * 2];
                    Crow[(size_t)(gn0 + 1) * 3] = acc[mi][nj][half * 2 + 1];
                }
            }
        }
    }
}

// ---------------------------------------------------------------------------
// Gate: pre (plane-major fp32) -> h (fp16, next-layer scale folded)
// ---------------------------------------------------------------------------
__global__ void gate_kernel(const float* __restrict__ pre, __half* __restrict__ h, int M)
{
    size_t idx = (size_t)blockIdx.x * blockDim.x + threadIdx.x;
    size_t total = (size_t)M * 320;
    if (idx >= total) return;
    int q = (int)(idx % 320);
    size_t r = idx / 320;
    const float s512 = 0.04419417382415922f;
    const float s256 = 0.0625f;
    float v0, v1, v2, v3;
    size_t off;
    if (q < 128) {
        float4 s = *(const float4*)&pre[r * 768 + q * 4];
        v0 = s.x / (1.f + __expf(-s.x)) * s512;
        v1 = s.y / (1.f + __expf(-s.y)) * s512;
        v2 = s.z / (1.f + __expf(-s.z)) * s512;
        v3 = s.w / (1.f + __expf(-s.w)) * s512;
        off = r * 512 + q * 4;
    } else {
        int t = q - 128;
        int d = t / 64, o4 = (t % 64) * 4;
        float4 g = *(const float4*)&pre[r * 768 + 512 + o4];
        float4 v = *(const float4*)&pre[(size_t)M * 768 + (size_t)d * M * 256 + r * 256 + o4];
        v0 = v.x / (1.f + __expf(-g.x)) * s256;
        v1 = v.y / (1.f + __expf(-g.y)) * s256;
        v2 = v.z / (1.f + __expf(-g.z)) * s256;
        v3 = v.w / (1.f + __expf(-g.w)) * s256;
        off = (size_t)M * 512 + (size_t)d * M * 256 + r * 256 + o4;
    }
    __half2 p01 = __floats2half2_rn(v0, v1);
    __half2 p23 = __floats2half2_rn(v2, v3);
    *(uint2*)&h[off] = make_uint2(*(uint32_t*)&p01, *(uint32_t*)&p23);
}

// ---------------------------------------------------------------------------
// Batch-norm (deterministic two-stage reduction)
// ---------------------------------------------------------------------------
__global__ void bn_partial_kernel(const float* __restrict__ out,
                                  float* __restrict__ psum, float* __restrict__ psq, int M)
{
    int c = threadIdx.x;
    float s = 0.f, sq = 0.f;
    for (int r = blockIdx.x; r < M; r += gridDim.x) {
        float x = out[(size_t)r * 640 + c];
        s += x; sq += x * x;
    }
    psq[blockIdx.x * 640 + c] = sq;
    if (c < 256) psum[blockIdx.x * 256 + c] = s;
}

__global__ void bn_final_kernel(const float* __restrict__ psum, const float* __restrict__ psq,
                                const float* __restrict__ w, const float* __restrict__ b,
                                float* __restrict__ scale, float* __restrict__ shift, int M)
{
    __shared__ float ssq[640];
    __shared__ float ssum[256];
    int c = threadIdx.x;
    float sq = 0.f;
    for (int p = 0; p < NPART; p++) sq += psq[p * 640 + c];
    ssq[c] = sq;
    if (c < 256) {
        float s = 0.f;
        for (int p = 0; p < NPART; p++) s += psum[p * 256 + c];
        ssum[c] = s;
    }
    __syncthreads();
    float invN = 1.f / (float)M;
    if (c < 256) {
        float m = ssum[c] * invN;
        float var = ssq[c] * invN - m * m;
        float inv = rsqrtf(var + 1e-5f);
        float sc = inv * w[c];
        scale[c] = sc;
        shift[c] = b[c] - m * sc;
    } else if (c < 256 + 128) {
        int ch = c - 256;
        float t = ssq[256 + 3 * ch] + ssq[256 + 3 * ch + 1] + ssq[256 + 3 * ch + 2];
        float mean = t * invN * (1.f / 3.f);
        float inv = rsqrtf(mean + 1e-5f);
        float sc = inv * w[256 + ch];
#pragma unroll
        for (int d2 = 0; d2 < 3; d2++) {
            scale[256 + 3 * ch + d2] = sc;
            shift[256 + 3 * ch + d2] = 0.f;
        }
    }
}

__global__ void bn_apply_kernel(float* __restrict__ out,
                                const float* __restrict__ scale,
                                const float* __restrict__ shift, int M)
{
    size_t idx = (size_t)blockIdx.x * blockDim.x + threadIdx.x;
    size_t total = (size_t)M * 160;
    if (idx >= total) return;
    int c4 = (int)(idx % 160) * 4;
    size_t r = idx / 160;
    float4 x = *(float4*)&out[r * 640 + c4];
    float4 s = *(const float4*)&scale[c4];
    float4 t = *(const float4*)&shift[c4];
    x.x = x.x * s.x + t.x;
    x.y = x.y * s.y + t.y;
    x.z = x.z * s.z + t.z;
    x.w = x.w * s.w + t.w;
    *(float4*)&out[r * 640 + c4] = x;
}

// ---------------------------------------------------------------------------
extern "C" void kernel_launch(void* const* d_in, const int* in_sizes, int n_in,
                              void* d_out, int out_size)
{
    const float* features = (const float*)d_in[0];
    const float* W10 = (const float*)d_in[1];
    const float* W11 = (const float*)d_in[2];
    const float* W20 = (const float*)d_in[3];
    const float* W21 = (const float*)d_in[4];
    const float* W30 = (const float*)d_in[5];
    const float* W31 = (const float*)d_in[6];
    const float* B0  = (const float*)d_in[7];
    const float* B1  = (const float*)d_in[8];
    const float* bw  = (const float*)d_in[9];
    const float* bb  = (const float*)d_in[10];
    float* out = (float*)d_out;

    float *pre, *psum, *psq, *sc, *sh;
    __half *wb, *h, *ft;
    cudaGetSymbolAddress((void**)&pre, g_pre);
    cudaGetSymbolAddress((void**)&h, g_hbuf);
    cudaGetSymbolAddress((void**)&ft, g_feat);
    cudaGetSymbolAddress((void**)&psum, g_psum);
    cudaGetSymbolAddress((void**)&psq, g_psq);
    cudaGetSymbolAddress((void**)&sc, g_scale);
    cudaGetSymbolAddress((void**)&sh, g_shift);
    cudaGetSymbolAddress((void**)&wb, g_wbuf);

    const size_t M = MROWS;

    // weight offsets (elements); L3 merged: [W30|B0] ld=768, [W31|B1] ld=384
    const int o10 = 0;           // [768,256]
    const int o11 = 196608;      // [256,128]
    const int o20 = 229376;      // [768,512]
    const int o21 = 622592;      // [256,256]
    const int oL3s = 688128;     // [256,768]
    const int oL3v = 884736;     // [128,384]

    // ---- preconvert weights (unscaled fp16) + features (scale folded) ----
    {
        struct { const float* W; int K, N, off, ld, kOff; } cw[8] = {
            {W10, 256, 768, o10,  256, 0},
            {W11, 128, 256, o11,  128, 0},
            {W20, 512, 768, o20,  512, 0},
            {W21, 256, 256, o21,  256, 0},
            {W30, 512, 256, oL3s, 768, 0},
            {B0,  256, 256, oL3s, 768, 512},
            {W31, 256, 128, oL3v, 384, 0},
            {B1,  128, 128, oL3v, 384, 256}};
        for (int i = 0; i < 8; i++) {
            int tot = cw[i].K * cw[i].N;
            conv_w_kernel<<<(tot + 255) / 256, 256>>>(cw[i].W, cw[i].K, cw[i].N,
                                                      wb + cw[i].off, cw[i].ld, cw[i].kOff);
        }
        size_t tot = M * 640;
        conv_feat_kernel<<<(unsigned)((tot + 255) / 256), 256>>>(features, ft, (int)M);
    }

    const int gy = (int)((M + 127) / 128);
    cudaFuncSetAttribute(tc_gemm, cudaFuncAttributeMaxDynamicSharedMemorySize, SMEM_BYTES);

    __half* fs = ft;                 // [M,256], *s256
    __half* fv = ft + M * 256;       // 3 planes [M,128], *s128
    __half* hs = h;                  // [M,512], *s512
    __half* hv = h + M * 512;        // 3 planes [M,256], *s256

    // ---- layer 1 ----
    tc_gemm<<<dim3(6, gy, 1), 256, SMEM_BYTES>>>(
        fs, 256, 0, fs, 256, 0, 256,
        wb + o10, pre, 768, 0, 0, 1, (int)M, 256);
    tc_gemm<<<dim3(2, gy, 3), 256, SMEM_BYTES>>>(
        fv, 128, M * 128, fv, 128, M * 128, 128,
        wb + o11, pre, 256, M * 768, M * 256, 1, (int)M, 128);
    {
        size_t total = M * 320;
        gate_kernel<<<(unsigned)((total + 255) / 256), 256>>>(pre, h, (int)M);
    }
    // ---- layer 2 ----
    tc_gemm<<<dim3(6, gy, 1), 256, SMEM_BYTES>>>(
        hs, 512, 0, hs, 512, 0, 512,
        wb + o20, pre, 768, 0, 0, 1, (int)M, 512);
    tc_gemm<<<dim3(2, gy, 3), 256, SMEM_BYTES>>>(
        hv, 256, M * 256, hv, 256, M * 256, 256,
        wb + o21, pre, 256, M * 768, M * 256, 1, (int)M, 256);
    {
        size_t total = M * 320;
        gate_kernel<<<(unsigned)((total + 255) / 256), 256>>>(pre, h, (int)M);
    }
    // ---- layer 3 + bypass (merged via K-concat) ----
    tc_gemm<<<dim3(2, gy, 1), 256, SMEM_BYTES>>>(
        hs, 512, 0, fs, 256, 0, 512,
        wb + oL3s, out, 640, 0, 0, 1, (int)M, 768);
    tc_gemm<<<dim3(1, gy, 3), 256, SMEM_BYTES>>>(
        hv, 256, M * 256, fv, 128, M * 128, 256,
        wb + oL3v, out, 640, 256, 1, 3, (int)M, 384);

    // ---- batch norm ----
    bn_partial_kernel<<<NPART, 640>>>(out, psum, psq, (int)M);
    bn_final_kernel<<<1, 640>>>(psum, psq, bw, bb, sc, sh, (int)M);
    {
        size_t total = M * 160;
        bn_apply_kernel<<<(unsigned)((total + 255) / 256), 256>>>(out, sc, sh, (int)M);
    }
}

// round 10
// speedup vs baseline: 3.4248x; 1.0050x over previous
#include <cuda_runtime.h>
#include <cuda_fp16.h>
#include <cstdint>
#include <cstddef>

// ===========================================================================
// FeedForward via pure fp16 mma.sync, gate fused into GEMM epilogue.
//   mode 0: C fp32 (layer3+bypass -> out)
//   mode 1: scalar gate: cols<512 silu*scale -> hs fp16; cols>=512 sigmoid -> g fp32
//   mode 2: vec gate: acc * g[gm,gn] * scale -> hv fp16 plane
// Ping-pong h buffers (h0/h1) so no launch reads what a later launch writes.
// ===========================================================================

#define MROWS 100000

// ------------------------------- scratch -----------------------------------
__device__ __half g_hbuf[(size_t)MROWS * 2560];   // h0 [M,1280] | h1 [M,1280]
__device__ __half g_feat[(size_t)MROWS * 640];    // fs [M,256] | fv[d] [M,128]
__device__ float g_gate[(size_t)MROWS * 256];     // sigmoid gate values
#define NPART 512
__device__ float g_psum[NPART * 256];
__device__ float g_psq[NPART * 640];
__device__ float g_scale[640];
__device__ float g_shift[640];
#define WTOT 933888
__device__ __align__(256) __half g_wbuf[WTOT];

// --------------------------- helpers ---------------------------------------
__device__ __forceinline__ uint32_t smem_to_u32(const void* p) {
    uint32_t a;
    asm("{ .reg .u64 t; cvta.to.shared.u64 t, %1; cvt.u32.u64 %0, t; }" : "=r"(a) : "l"(p));
    return a;
}
__device__ __forceinline__ void ldm4(uint32_t& r0, uint32_t& r1, uint32_t& r2, uint32_t& r3,
                                     uint32_t addr) {
    asm volatile("ldmatrix.sync.aligned.m8n8.x4.shared.b16 {%0,%1,%2,%3}, [%4];"
                 : "=r"(r0), "=r"(r1), "=r"(r2), "=r"(r3) : "r"(addr));
}
__device__ __forceinline__ void mma16816(float* c, const uint32_t* a, const uint32_t* b) {
    asm volatile(
        "mma.sync.aligned.m16n8k16.row.col.f32.f16.f16.f32 "
        "{%0,%1,%2,%3}, {%4,%5,%6,%7}, {%8,%9}, {%0,%1,%2,%3};"
        : "+f"(c[0]), "+f"(c[1]), "+f"(c[2]), "+f"(c[3])
        : "r"(a[0]), "r"(a[1]), "r"(a[2]), "r"(a[3]), "r"(b[0]), "r"(b[1]));
}
#define CP_ASYNC16(dst, src, sz) \
    asm volatile("cp.async.cg.shared.global [%0], [%1], 16, %2;" \
                 :: "r"(dst), "l"(src), "r"(sz) : "memory")
#define CP_COMMIT asm volatile("cp.async.commit_group;" ::: "memory")
#define CP_WAIT1 asm volatile("cp.async.wait_group 1;" ::: "memory")
#define CP_WAIT0 asm volatile("cp.async.wait_group 0;" ::: "memory")

// ---------------------------------------------------------------------------
// Weight prep: W[K,N] fp32 -> fp16 [N,*] K-major (unscaled)
// ---------------------------------------------------------------------------
__global__ void conv_w_kernel(const float* __restrict__ W, int K, int N,
                              __half* __restrict__ hi, int ldout, int kOff) {
    int idx = blockIdx.x * blockDim.x + threadIdx.x;
    if (idx >= N * K) return;
    int n = idx / K, k = idx % K;
    hi[(size_t)n * ldout + kOff + k] = __float2half_rn(W[k * N + n]);
}

// ---------------------------------------------------------------------------
// Features -> plane-major fp16, scale folded (s: *s256, v: *s128)
// ---------------------------------------------------------------------------
__global__ void conv_feat_kernel(const float* __restrict__ F, __half* __restrict__ out,
                                 int M) {
    size_t idx = (size_t)blockIdx.x * blockDim.x + threadIdx.x;
    size_t total = (size_t)M * 640;
    if (idx >= total) return;
    int c = (int)(idx % 640);
    size_t r = idx / 640;
    const float s256 = 0.0625f;
    const float s128 = 0.08838834764831845f;
    float v;
    size_t off;
    if (c < 256) {
        v = F[r * 640 + c] * s256;
        off = r * 256 + c;
    } else {
        int t = c - 256;
        int d = t / 128, o = t % 128;
        v = F[r * 640 + 256 + o * 3 + d] * s128;
        off = (size_t)M * 256 + (size_t)d * M * 128 + r * 128 + o;
    }
    out[off] = __float2half_rn(v);
}

// ---------------------------------------------------------------------------
// HMMA GEMM: block 128x128, BK=32, pure fp16 operands, fused epilogue modes.
// ---------------------------------------------------------------------------
#define SAA 40                      // smem row stride (halfs), 80 B
#define OPBY (128 * SAA * 2)        // 10240 per operand
#define STAGE_BYTES (2 * OPBY)      // 20480
#define SMEM_BYTES (2 * STAGE_BYTES)// 40960

__global__ __launch_bounds__(256) void tc_gemm(
    const __half* __restrict__ A, int lda, size_t aPlane,
    const __half* __restrict__ A2, int lda2, size_t aPlane2, int K1,
    const __half* __restrict__ B,
    float* __restrict__ C, int ldc, size_t cOff, size_t cPlane, int cStride,
    __half* __restrict__ Hout, size_t hPlane,
    float* __restrict__ G,
    int M, int K, int mode, float eScale)
{
    extern __shared__ char smem[];
    const uint32_t sb = smem_to_u32(smem);

    const int tid = threadIdx.x;
    const int wid = tid >> 5;
    const int lane = tid & 31;
    const int warp_m = wid & 3;
    const int warp_n = wid >> 2;
    const int bm = blockIdx.y * 128;
    const int bn = blockIdx.x * 128;
    const int z = blockIdx.z;
    A    += (size_t)z * aPlane;
    A2   += (size_t)z * aPlane2;
    C    += cOff + (size_t)z * cPlane;
    Hout += (size_t)z * hPlane;

    const int quad = lane >> 3;
    const int rsel = (lane & 7) + ((quad & 1) << 3);
    const int ksel = (quad >> 1) << 3;

    float acc[2][8][4];
#pragma unroll
    for (int mi = 0; mi < 2; mi++)
#pragma unroll
        for (int nj = 0; nj < 8; nj++)
#pragma unroll
            for (int r = 0; r < 4; r++) acc[mi][nj][r] = 0.f;

    const int nkt = K / 32;

    auto prefetch = [&](int kt, int st) {
        int k0 = kt * 32;
        const __half* pA;
        int plda, kk;
        if (k0 < K1) { pA = A;  plda = lda;  kk = k0; }
        else         { pA = A2; plda = lda2; kk = k0 - K1; }
        const uint32_t base = sb + st * STAGE_BYTES;
#pragma unroll
        for (int i = 0; i < 2; i++) {
            int t = tid + i * 256;
            int row = t >> 2, c = t & 3;
            int gm = bm + row;
            const __half* src = pA + (size_t)gm * plda + kk + c * 8;
            uint32_t dst = base + (uint32_t)(row * SAA) * 2 + c * 16;
            int sz = (gm < M) ? 16 : 0;
            CP_ASYNC16(dst, src, sz);
        }
#pragma unroll
        for (int i = 0; i < 2; i++) {
            int t = tid + i * 256;
            int row = t >> 2, c = t & 3;
            const __half* src = B + (size_t)(bn + row) * K + k0 + c * 8;
            uint32_t dst = base + OPBY + (uint32_t)(row * SAA) * 2 + c * 16;
            CP_ASYNC16(dst, src, 16);
        }
    };

    prefetch(0, 0);
    CP_COMMIT;

    for (int kt = 0; kt < nkt; kt++) {
        if (kt + 1 < nkt) { prefetch(kt + 1, (kt + 1) & 1); CP_COMMIT; }
        if (kt + 1 < nkt) { CP_WAIT1; } else { CP_WAIT0; }
        __syncthreads();

        const uint32_t sbase = sb + (kt & 1) * STAGE_BYTES;
        const uint32_t aAddr0 = sbase + (uint32_t)((warp_m * 32 + rsel) * SAA + ksel) * 2;
        const uint32_t aAddr1 = aAddr0 + 16 * SAA * 2;
        const uint32_t bAddr0 = sbase + OPBY + (uint32_t)((warp_n * 64 + rsel) * SAA + ksel) * 2;

#pragma unroll
        for (int ks = 0; ks < 2; ks++) {
            const uint32_t kof = ks * 32;
            uint32_t af0[4], af1[4];
            ldm4(af0[0], af0[1], af0[2], af0[3], aAddr0 + kof);
            ldm4(af1[0], af1[1], af1[2], af1[3], aAddr1 + kof);
            uint32_t bf[8][2];
#pragma unroll
            for (int j2 = 0; j2 < 4; j2++) {
                uint32_t r0, r1, r2, r3;
                ldm4(r0, r1, r2, r3, bAddr0 + (uint32_t)(j2 * 16 * SAA) * 2 + kof);
                bf[2 * j2][0] = r0; bf[2 * j2 + 1][0] = r1;
                bf[2 * j2][1] = r2; bf[2 * j2 + 1][1] = r3;
            }
#pragma unroll
            for (int mi = 0; mi < 2; mi++)
#pragma unroll
                for (int nj = 0; nj < 8; nj++)
                    mma16816(acc[mi][nj], mi ? af1 : af0, bf[nj]);
        }
        __syncthreads();
    }

    // ---- epilogue ----
    const int tq = lane >> 2;
    const int tr = lane & 3;
#pragma unroll
    for (int mi = 0; mi < 2; mi++) {
#pragma unroll
        for (int half = 0; half < 2; half++) {
            int gm = bm + warp_m * 32 + mi * 16 + tq + half * 8;
            if (gm >= M) continue;
            if (mode == 0) {
                if (cStride == 1) {
                    float* Crow = C + (size_t)gm * ldc + bn + warp_n * 64;
#pragma unroll
                    for (int nj = 0; nj < 8; nj++) {
                        int cn = nj * 8 + tr * 2;
                        *(float2*)&Crow[cn] =
                            make_float2(acc[mi][nj][half * 2], acc[mi][nj][half * 2 + 1]);
                    }
                } else {
                    float* Crow = C + (size_t)gm * ldc;
#pragma unroll
                    for (int nj = 0; nj < 8; nj++) {
                        int gn0 = bn + warp_n * 64 + nj * 8 + tr * 2;
                        Crow[(size_t)gn0 * 3] = acc[mi][nj][half * 2];
                        Crow[(size_t)(gn0 + 1) * 3] = acc[mi][nj][half * 2 + 1];
                    }
                }
            } else if (mode == 1) {
                // scalar gate: cols<512 silu*eScale -> Hout (ld 512); else sigmoid -> G (ld 256)
#pragma unroll
                for (int nj = 0; nj < 8; nj++) {
                    int gnc = bn + warp_n * 64 + nj * 8 + tr * 2;
                    float v0 = acc[mi][nj][half * 2];
                    float v1 = acc[mi][nj][half * 2 + 1];
                    if (gnc < 512) {
                        float s0 = v0 / (1.f + __expf(-v0)) * eScale;
                        float s1 = v1 / (1.f + __expf(-v1)) * eScale;
                        __half2 p = __floats2half2_rn(s0, s1);
                        *(__half2*)&Hout[(size_t)gm * 512 + gnc] = p;
                    } else {
                        float g0 = 1.f / (1.f + __expf(-v0));
                        float g1 = 1.f / (1.f + __expf(-v1));
                        *(float2*)&G[(size_t)gm * 256 + (gnc - 512)] = make_float2(g0, g1);
                    }
                }
            } else {
                // vec gate: acc * G * eScale -> Hout plane (ld 256)
#pragma unroll
                for (int nj = 0; nj < 8; nj++) {
                    int gn = bn + warp_n * 64 + nj * 8 + tr * 2;
                    float2 gg = *(const float2*)&G[(size_t)gm * 256 + gn];
                    float v0 = acc[mi][nj][half * 2] * gg.x * eScale;
                    float v1 = acc[mi][nj][half * 2 + 1] * gg.y * eScale;
                    *(__half2*)&Hout[(size_t)gm * 256 + gn] = __floats2half2_rn(v0, v1);
                }
            }
        }
    }
}

// ---------------------------------------------------------------------------
// Batch-norm (deterministic two-stage reduction)
// ---------------------------------------------------------------------------
__global__ void bn_partial_kernel(const float* __restrict__ out,
                                  float* __restrict__ psum, float* __restrict__ psq, int M)
{
    int c = threadIdx.x;
    float s = 0.f, sq = 0.f;
    for (int r = blockIdx.x; r < M; r += gridDim.x) {
        float x = out[(size_t)r * 640 + c];
        s += x; sq += x * x;
    }
    psq[blockIdx.x * 640 + c] = sq;
    if (c < 256) psum[blockIdx.x * 256 + c] = s;
}

__global__ void bn_final_kernel(const float* __restrict__ psum, const float* __restrict__ psq,
                                const float* __restrict__ w, const float* __restrict__ b,
                                float* __restrict__ scale, float* __restrict__ shift, int M)
{
    __shared__ float ssq[640];
    __shared__ float ssum[256];
    int c = threadIdx.x;
    float sq = 0.f;
    for (int p = 0; p < NPART; p++) sq += psq[p * 640 + c];
    ssq[c] = sq;
    if (c < 256) {
        float s = 0.f;
        for (int p = 0; p < NPART; p++) s += psum[p * 256 + c];
        ssum[c] = s;
    }
    __syncthreads();
    float invN = 1.f / (float)M;
    if (c < 256) {
        float m = ssum[c] * invN;
        float var = ssq[c] * invN - m * m;
        float inv = rsqrtf(var + 1e-5f);
        float sc = inv * w[c];
        scale[c] = sc;
        shift[c] = b[c] - m * sc;
    } else if (c < 256 + 128) {
        int ch = c - 256;
        float t = ssq[256 + 3 * ch] + ssq[256 + 3 * ch + 1] + ssq[256 + 3 * ch + 2];
        float mean = t * invN * (1.f / 3.f);
        float inv = rsqrtf(mean + 1e-5f);
        float sc = inv * w[256 + ch];
#pragma unroll
        for (int d2 = 0; d2 < 3; d2++) {
            scale[256 + 3 * ch + d2] = sc;
            shift[256 + 3 * ch + d2] = 0.f;
        }
    }
}

__global__ void bn_apply_kernel(float* __restrict__ out,
                                const float* __restrict__ scale,
                                const float* __restrict__ shift, int M)
{
    size_t idx = (size_t)blockIdx.x * blockDim.x + threadIdx.x;
    size_t total = (size_t)M * 160;
    if (idx >= total) return;
    int c4 = (int)(idx % 160) * 4;
    size_t r = idx / 160;
    float4 x = *(float4*)&out[r * 640 + c4];
    float4 s = *(const float4*)&scale[c4];
    float4 t = *(const float4*)&shift[c4];
    x.x = x.x * s.x + t.x;
    x.y = x.y * s.y + t.y;
    x.z = x.z * s.z + t.z;
    x.w = x.w * s.w + t.w;
    *(float4*)&out[r * 640 + c4] = x;
}

// ---------------------------------------------------------------------------
extern "C" void kernel_launch(void* const* d_in, const int* in_sizes, int n_in,
                              void* d_out, int out_size)
{
    const float* features = (const float*)d_in[0];
    const float* W10 = (const float*)d_in[1];
    const float* W11 = (const float*)d_in[2];
    const float* W20 = (const float*)d_in[3];
    const float* W21 = (const float*)d_in[4];
    const float* W30 = (const float*)d_in[5];
    const float* W31 = (const float*)d_in[6];
    const float* B0  = (const float*)d_in[7];
    const float* B1  = (const float*)d_in[8];
    const float* bw  = (const float*)d_in[9];
    const float* bb  = (const float*)d_in[10];
    float* out = (float*)d_out;

    float *gg, *psum, *psq, *sc, *sh;
    __half *wb, *h, *ft;
    cudaGetSymbolAddress((void**)&gg, g_gate);
    cudaGetSymbolAddress((void**)&h, g_hbuf);
    cudaGetSymbolAddress((void**)&ft, g_feat);
    cudaGetSymbolAddress((void**)&psum, g_psum);
    cudaGetSymbolAddress((void**)&psq, g_psq);
    cudaGetSymbolAddress((void**)&sc, g_scale);
    cudaGetSymbolAddress((void**)&sh, g_shift);
    cudaGetSymbolAddress((void**)&wb, g_wbuf);

    const size_t M = MROWS;
    const float s512 = 0.04419417382415922f;
    const float s256 = 0.0625f;

    const int o10 = 0;           // [768,256]
    const int o11 = 196608;      // [256,128]
    const int o20 = 229376;      // [768,512]
    const int o21 = 622592;      // [256,256]
    const int oL3s = 688128;     // [256,768]
    const int oL3v = 884736;     // [128,384]

    // ---- preconvert weights (unscaled fp16) + features (scale folded) ----
    {
        struct { const float* W; int K, N, off, ld, kOff; } cw[8] = {
            {W10, 256, 768, o10,  256, 0},
            {W11, 128, 256, o11,  128, 0},
            {W20, 512, 768, o20,  512, 0},
            {W21, 256, 256, o21,  256, 0},
            {W30, 512, 256, oL3s, 768, 0},
            {B0,  256, 256, oL3s, 768, 512},
            {W31, 256, 128, oL3v, 384, 0},
            {B1,  128, 128, oL3v, 384, 256}};
        for (int i = 0; i < 8; i++) {
            int tot = cw[i].K * cw[i].N;
            conv_w_kernel<<<(tot + 255) / 256, 256>>>(cw[i].W, cw[i].K, cw[i].N,
                                                      wb + cw[i].off, cw[i].ld, cw[i].kOff);
        }
        size_t tot = M * 640;
        conv_feat_kernel<<<(unsigned)((tot + 255) / 256), 256>>>(features, ft, (int)M);
    }

    const int gy = (int)((M + 127) / 128);
    cudaFuncSetAttribute(tc_gemm, cudaFuncAttributeMaxDynamicSharedMemorySize, SMEM_BYTES);

    __half* fs = ft;                    // [M,256], *s256
    __half* fv = ft + M * 256;          // 3 planes [M,128], *s128
    // ping-pong h buffers
    __half* hs0 = h;                    // [M,512]
    __half* hv0 = h + M * 512;          // 3 planes [M,256]
    __half* hs1 = h + M * 1280;         // [M,512]
    __half* hv1 = h + M * 1792;         // 3 planes [M,256]

    // ---- layer 1 (gate fused): ft -> h0 ----
    tc_gemm<<<dim3(6, gy, 1), 256, SMEM_BYTES>>>(
        fs, 256, 0, fs, 256, 0, 256, wb + o10,
        out, 0, 0, 0, 1, hs0, 0, gg, (int)M, 256, 1, s512);
    tc_gemm<<<dim3(2, gy, 3), 256, SMEM_BYTES>>>(
        fv, 128, M * 128, fv, 128, M * 128, 128, wb + o11,
        out, 0, 0, 0, 1, hv0, M * 256, gg, (int)M, 128, 2, s256);
    // ---- layer 2 (gate fused): h0 -> h1 ----
    tc_gemm<<<dim3(6, gy, 1), 256, SMEM_BYTES>>>(
        hs0, 512, 0, hs0, 512, 0, 512, wb + o20,
        out, 0, 0, 0, 1, hs1, 0, gg, (int)M, 512, 1, s512);
    tc_gemm<<<dim3(2, gy, 3), 256, SMEM_BYTES>>>(
        hv0, 256, M * 256, hv0, 256, M * 256, 256, wb + o21,
        out, 0, 0, 0, 1, hv1, M * 256, gg, (int)M, 256, 2, s256);
    // ---- layer 3 + bypass (merged via K-concat): h1 (+ft) -> out ----
    tc_gemm<<<dim3(2, gy, 1), 256, SMEM_BYTES>>>(
        hs1, 512, 0, fs, 256, 0, 512, wb + oL3s,
        out, 640, 0, 0, 1, hs1, 0, gg, (int)M, 768, 0, 1.f);
    tc_gemm<<<dim3(1, gy, 3), 256, SMEM_BYTES>>>(
        hv1, 256, M * 256, fv, 128, M * 128, 256, wb + oL3v,
        out, 640, 256, 1, 3, hv1, 0, gg, (int)M, 384, 0, 1.f);

    // ---- batch norm ----
    bn_partial_kernel<<<NPART, 640>>>(out, psum, psq, (int)M);
    bn_final_kernel<<<1, 640>>>(psum, psq, bw, bb, sc, sh, (int)M);
    {
        size_t total = M * 160;
        bn_apply_kernel<<<(unsigned)((total + 255) / 256), 256>>>(out, sc, sh, (int)M);
    }
}

// round 11
// speedup vs baseline: 3.9846x; 1.1634x over previous
#include <cuda_runtime.h>
#include <cuda_fp16.h>
#include <cstdint>
#include <cstddef>

// ===========================================================================
// FeedForward via pure fp16 mma.sync, gate fused into GEMM epilogue.
//   mode 0: C fp32 planar (layer3+bypass -> g_o scratch)
//   mode 1: scalar gate: cols<512 silu*scale -> hs fp16; cols>=512 sigmoid -> g
//   mode 2: vec gate: acc * g[gm,gn] * scale -> hv fp16 plane
// BK=64 mainloop (4 k16 steps per sync round). Planar BN; bn_apply interleaves.
// ===========================================================================

#define MROWS 100000

// ------------------------------- scratch -----------------------------------
__device__ __half g_hbuf[(size_t)MROWS * 2560];   // h0 [M,1280] | h1 [M,1280]
__device__ __half g_feat[(size_t)MROWS * 640];    // fs [M,256] | fv[d] [M,128]
__device__ float g_gate[(size_t)MROWS * 256];     // sigmoid gate values
__device__ float g_o[(size_t)MROWS * 640];        // planar L3 out: S[M,256]|V[d][M,128]
#define NPART 512
__device__ float g_psum[NPART * 256];
__device__ float g_psq[NPART * 640];
__device__ float g_scale[640];                    // planar-indexed
__device__ float g_shift[640];
#define WTOT 933888
__device__ __align__(256) __half g_wbuf[WTOT];

// --------------------------- helpers ---------------------------------------
__device__ __forceinline__ uint32_t smem_to_u32(const void* p) {
    uint32_t a;
    asm("{ .reg .u64 t; cvta.to.shared.u64 t, %1; cvt.u32.u64 %0, t; }" : "=r"(a) : "l"(p));
    return a;
}
__device__ __forceinline__ void ldm4(uint32_t& r0, uint32_t& r1, uint32_t& r2, uint32_t& r3,
                                     uint32_t addr) {
    asm volatile("ldmatrix.sync.aligned.m8n8.x4.shared.b16 {%0,%1,%2,%3}, [%4];"
                 : "=r"(r0), "=r"(r1), "=r"(r2), "=r"(r3) : "r"(addr));
}
__device__ __forceinline__ void mma16816(float* c, const uint32_t* a, const uint32_t* b) {
    asm volatile(
        "mma.sync.aligned.m16n8k16.row.col.f32.f16.f16.f32 "
        "{%0,%1,%2,%3}, {%4,%5,%6,%7}, {%8,%9}, {%0,%1,%2,%3};"
        : "+f"(c[0]), "+f"(c[1]), "+f"(c[2]), "+f"(c[3])
        : "r"(a[0]), "r"(a[1]), "r"(a[2]), "r"(a[3]), "r"(b[0]), "r"(b[1]));
}
#define CP_ASYNC16(dst, src, sz) \
    asm volatile("cp.async.cg.shared.global [%0], [%1], 16, %2;" \
                 :: "r"(dst), "l"(src), "r"(sz) : "memory")
#define CP_COMMIT asm volatile("cp.async.commit_group;" ::: "memory")
#define CP_WAIT1 asm volatile("cp.async.wait_group 1;" ::: "memory")
#define CP_WAIT0 asm volatile("cp.async.wait_group 0;" ::: "memory")

// ---------------------------------------------------------------------------
// Weight prep: W[K,N] fp32 -> fp16 [N,*] K-major (unscaled)
// ---------------------------------------------------------------------------
__global__ void conv_w_kernel(const float* __restrict__ W, int K, int N,
                              __half* __restrict__ hi, int ldout, int kOff) {
    int idx = blockIdx.x * blockDim.x + threadIdx.x;
    if (idx >= N * K) return;
    int n = idx / K, k = idx % K;
    hi[(size_t)n * ldout + kOff + k] = __float2half_rn(W[k * N + n]);
}

// ---------------------------------------------------------------------------
// Features -> plane-major fp16, scale folded (s: *s256, v: *s128)
// ---------------------------------------------------------------------------
__global__ void conv_feat_kernel(const float* __restrict__ F, __half* __restrict__ out,
                                 int M) {
    size_t idx = (size_t)blockIdx.x * blockDim.x + threadIdx.x;
    size_t total = (size_t)M * 640;
    if (idx >= total) return;
    int c = (int)(idx % 640);
    size_t r = idx / 640;
    const float s256 = 0.0625f;
    const float s128 = 0.08838834764831845f;
    float v;
    size_t off;
    if (c < 256) {
        v = F[r * 640 + c] * s256;
        off = r * 256 + c;
    } else {
        int t = c - 256;
        int d = t / 128, o = t % 128;
        v = F[r * 640 + 256 + o * 3 + d] * s128;
        off = (size_t)M * 256 + (size_t)d * M * 128 + r * 128 + o;
    }
    out[off] = __float2half_rn(v);
}

// ---------------------------------------------------------------------------
// HMMA GEMM: block 128x128, BK=64 (4 k16 steps), fp16 operands, fused epilogue.
// ---------------------------------------------------------------------------
#define SAA 72                      // smem row stride (halfs), 144 B
#define OPBY (128 * SAA * 2)        // 18432 per operand
#define STAGE_BYTES (2 * OPBY)      // 36864
#define SMEM_BYTES (2 * STAGE_BYTES)// 73728

__global__ __launch_bounds__(256) void tc_gemm(
    const __half* __restrict__ A, int lda, size_t aPlane,
    const __half* __restrict__ A2, int lda2, size_t aPlane2, int K1,
    const __half* __restrict__ B,
    float* __restrict__ C, int ldc, size_t cPlane,
    __half* __restrict__ Hout, size_t hPlane,
    float* __restrict__ G,
    int M, int K, int mode, float eScale)
{
    extern __shared__ char smem[];
    const uint32_t sb = smem_to_u32(smem);

    const int tid = threadIdx.x;
    const int wid = tid >> 5;
    const int lane = tid & 31;
    const int warp_m = wid & 3;
    const int warp_n = wid >> 2;
    const int bm = blockIdx.y * 128;
    const int bn = blockIdx.x * 128;
    const int z = blockIdx.z;
    A    += (size_t)z * aPlane;
    A2   += (size_t)z * aPlane2;
    C    += (size_t)z * cPlane;
    Hout += (size_t)z * hPlane;

    const int quad = lane >> 3;
    const int rsel = (lane & 7) + ((quad & 1) << 3);
    const int ksel = (quad >> 1) << 3;

    float acc[2][8][4];
#pragma unroll
    for (int mi = 0; mi < 2; mi++)
#pragma unroll
        for (int nj = 0; nj < 8; nj++)
#pragma unroll
            for (int r = 0; r < 4; r++) acc[mi][nj][r] = 0.f;

    const int nkt = K / 64;

    auto prefetch = [&](int kt, int st) {
        int k0 = kt * 64;
        const __half* pA;
        int plda, kk;
        if (k0 < K1) { pA = A;  plda = lda;  kk = k0; }
        else         { pA = A2; plda = lda2; kk = k0 - K1; }
        const uint32_t base = sb + st * STAGE_BYTES;
        // A: 128 rows x 8 chunks of 16B
#pragma unroll
        for (int i = 0; i < 4; i++) {
            int t = tid + i * 256;
            int row = t >> 3, c = t & 7;
            int gm = bm + row;
            const __half* src = pA + (size_t)gm * plda + kk + c * 8;
            uint32_t dst = base + (uint32_t)(row * SAA) * 2 + c * 16;
            int sz = (gm < M) ? 16 : 0;
            CP_ASYNC16(dst, src, sz);
        }
        // B: 128 n-rows x 8 chunks of 16B
#pragma unroll
        for (int i = 0; i < 4; i++) {
            int t = tid + i * 256;
            int row = t >> 3, c = t & 7;
            const __half* src = B + (size_t)(bn + row) * K + k0 + c * 8;
            uint32_t dst = base + OPBY + (uint32_t)(row * SAA) * 2 + c * 16;
            CP_ASYNC16(dst, src, 16);
        }
    };

    prefetch(0, 0);
    CP_COMMIT;

    for (int kt = 0; kt < nkt; kt++) {
        if (kt + 1 < nkt) { prefetch(kt + 1, (kt + 1) & 1); CP_COMMIT; }
        if (kt + 1 < nkt) { CP_WAIT1; } else { CP_WAIT0; }
        __syncthreads();

        const uint32_t sbase = sb + (kt & 1) * STAGE_BYTES;
        const uint32_t aAddr0 = sbase + (uint32_t)((warp_m * 32 + rsel) * SAA + ksel) * 2;
        const uint32_t aAddr1 = aAddr0 + 16 * SAA * 2;
        const uint32_t bAddr0 = sbase + OPBY + (uint32_t)((warp_n * 64 + rsel) * SAA + ksel) * 2;

#pragma unroll
        for (int ks = 0; ks < 4; ks++) {
            const uint32_t kof = ks * 32;
            uint32_t af0[4], af1[4];
            ldm4(af0[0], af0[1], af0[2], af0[3], aAddr0 + kof);
            ldm4(af1[0], af1[1], af1[2], af1[3], aAddr1 + kof);
            uint32_t bf[8][2];
#pragma unroll
            for (int j2 = 0; j2 < 4; j2++) {
                uint32_t r0, r1, r2, r3;
                ldm4(r0, r1, r2, r3, bAddr0 + (uint32_t)(j2 * 16 * SAA) * 2 + kof);
                bf[2 * j2][0] = r0; bf[2 * j2 + 1][0] = r1;
                bf[2 * j2][1] = r2; bf[2 * j2 + 1][1] = r3;
            }
#pragma unroll
            for (int mi = 0; mi < 2; mi++)
#pragma unroll
                for (int nj = 0; nj < 8; nj++)
                    mma16816(acc[mi][nj], mi ? af1 : af0, bf[nj]);
        }
        __syncthreads();
    }

    // ---- epilogue ----
    const int tq = lane >> 2;
    const int tr = lane & 3;
#pragma unroll
    for (int mi = 0; mi < 2; mi++) {
#pragma unroll
        for (int half = 0; half < 2; half++) {
            int gm = bm + warp_m * 32 + mi * 16 + tq + half * 8;
            if (gm >= M) continue;
            if (mode == 0) {
                float* Crow = C + (size_t)gm * ldc + bn + warp_n * 64;
#pragma unroll
                for (int nj = 0; nj < 8; nj++) {
                    int cn = nj * 8 + tr * 2;
                    *(float2*)&Crow[cn] =
                        make_float2(acc[mi][nj][half * 2], acc[mi][nj][half * 2 + 1]);
                }
            } else if (mode == 1) {
                // scalar gate: cols<512 silu*eScale -> Hout (ld 512); else sigmoid -> G
#pragma unroll
                for (int nj = 0; nj < 8; nj++) {
                    int gnc = bn + warp_n * 64 + nj * 8 + tr * 2;
                    float v0 = acc[mi][nj][half * 2];
                    float v1 = acc[mi][nj][half * 2 + 1];
                    if (gnc < 512) {
                        float s0 = v0 / (1.f + __expf(-v0)) * eScale;
                        float s1 = v1 / (1.f + __expf(-v1)) * eScale;
                        *(__half2*)&Hout[(size_t)gm * 512 + gnc] = __floats2half2_rn(s0, s1);
                    } else {
                        float g0 = 1.f / (1.f + __expf(-v0));
                        float g1 = 1.f / (1.f + __expf(-v1));
                        *(float2*)&G[(size_t)gm * 256 + (gnc - 512)] = make_float2(g0, g1);
                    }
                }
            } else {
                // vec gate: acc * G * eScale -> Hout plane (ld 256)
#pragma unroll
                for (int nj = 0; nj < 8; nj++) {
                    int gn = bn + warp_n * 64 + nj * 8 + tr * 2;
                    float2 gg = *(const float2*)&G[(size_t)gm * 256 + gn];
                    float v0 = acc[mi][nj][half * 2] * gg.x * eScale;
                    float v1 = acc[mi][nj][half * 2 + 1] * gg.y * eScale;
                    *(__half2*)&Hout[(size_t)gm * 256 + gn] = __floats2half2_rn(v0, v1);
                }
            }
        }
    }
}

// ---------------------------------------------------------------------------
// Batch-norm: planar column order p: [0,256) scalar; [256,640) vec d=(p-256)/128,
// o=(p-256)%128. Reads g_o planar (fully coalesced).
// ---------------------------------------------------------------------------
__global__ void bn_partial_kernel(const float* __restrict__ O,
                                  float* __restrict__ psum, float* __restrict__ psq, int M)
{
    int p = threadIdx.x; // 0..639 planar
    float s = 0.f, sq = 0.f;
    if (p < 256) {
        for (int r = blockIdx.x; r < M; r += gridDim.x) {
            float x = O[(size_t)r * 256 + p];
            s += x; sq += x * x;
        }
        psum[blockIdx.x * 256 + p] = s;
    } else {
        int d = (p - 256) >> 7, o = (p - 256) & 127;
        const float* V = O + (size_t)M * 256 + (size_t)d * M * 128;
        for (int r = blockIdx.x; r < M; r += gridDim.x) {
            float x = V[(size_t)r * 128 + o];
            sq += x * x;
        }
    }
    psq[blockIdx.x * 640 + p] = sq;
}

__global__ void bn_final_kernel(const float* __restrict__ psum, const float* __restrict__ psq,
                                const float* __restrict__ w, const float* __restrict__ b,
                                float* __restrict__ scale, float* __restrict__ shift, int M)
{
    __shared__ float ssq[640];
    __shared__ float ssum[256];
    int p = threadIdx.x;
    float sq = 0.f;
    for (int q = 0; q < NPART; q++) sq += psq[q * 640 + p];
    ssq[p] = sq;
    if (p < 256) {
        float s = 0.f;
        for (int q = 0; q < NPART; q++) s += psum[q * 256 + p];
        ssum[p] = s;
    }
    __syncthreads();
    float invN = 1.f / (float)M;
    if (p < 256) {
        float m = ssum[p] * invN;
        float var = ssq[p] * invN - m * m;
        float inv = rsqrtf(var + 1e-5f);
        float sc = inv * w[p];
        scale[p] = sc;
        shift[p] = b[p] - m * sc;
    } else if (p < 256 + 128) {
        int ch = p - 256;   // vec channel o
        float t = ssq[256 + ch] + ssq[256 + 128 + ch] + ssq[256 + 256 + ch];
        float mean = t * invN * (1.f / 3.f);
        float inv = rsqrtf(mean + 1e-5f);
        float sc = inv * w[256 + ch];
#pragma unroll
        for (int d = 0; d < 3; d++) {
            scale[256 + d * 128 + ch] = sc;   // planar index
            shift[256 + d * 128 + ch] = 0.f;
        }
    }
}

// Gather planar g_o, apply scale/shift, write interleaved out (contiguous f4).
__global__ void bn_apply_kernel(const float* __restrict__ O, float* __restrict__ out,
                                const float* __restrict__ scale,
                                const float* __restrict__ shift, int M)
{
    size_t idx = (size_t)blockIdx.x * blockDim.x + threadIdx.x;
    size_t total = (size_t)M * 160;
    if (idx >= total) return;
    int c4 = (int)(idx % 160) * 4;
    size_t r = idx / 160;
    float v[4];
#pragma unroll
    for (int j = 0; j < 4; j++) {
        int c = c4 + j;
        int p;
        float x;
        if (c < 256) {
            p = c;
            x = O[r * 256 + c];
        } else {
            int cc = c - 256;
            int o = cc / 3, d = cc % 3;
            p = 256 + d * 128 + o;
            x = O[(size_t)M * 256 + (size_t)d * M * 128 + r * 128 + o];
        }
        v[j] = x * scale[p] + shift[p];
    }
    *(float4*)&out[r * 640 + c4] = make_float4(v[0], v[1], v[2], v[3]);
}

// ---------------------------------------------------------------------------
extern "C" void kernel_launch(void* const* d_in, const int* in_sizes, int n_in,
                              void* d_out, int out_size)
{
    const float* features = (const float*)d_in[0];
    const float* W10 = (const float*)d_in[1];
    const float* W11 = (const float*)d_in[2];
    const float* W20 = (const float*)d_in[3];
    const float* W21 = (const float*)d_in[4];
    const float* W30 = (const float*)d_in[5];
    const float* W31 = (const float*)d_in[6];
    const float* B0  = (const float*)d_in[7];
    const float* B1  = (const float*)d_in[8];
    const float* bw  = (const float*)d_in[9];
    const float* bb  = (const float*)d_in[10];
    float* out = (float*)d_out;

    float *gg, *oo, *psum, *psq, *sc, *sh;
    __half *wb, *h, *ft;
    cudaGetSymbolAddress((void**)&gg, g_gate);
    cudaGetSymbolAddress((void**)&oo, g_o);
    cudaGetSymbolAddress((void**)&h, g_hbuf);
    cudaGetSymbolAddress((void**)&ft, g_feat);
    cudaGetSymbolAddress((void**)&psum, g_psum);
    cudaGetSymbolAddress((void**)&psq, g_psq);
    cudaGetSymbolAddress((void**)&sc, g_scale);
    cudaGetSymbolAddress((void**)&sh, g_shift);
    cudaGetSymbolAddress((void**)&wb, g_wbuf);

    const size_t M = MROWS;
    const float s512 = 0.04419417382415922f;
    const float s256 = 0.0625f;

    const int o10 = 0;           // [768,256]
    const int o11 = 196608;      // [256,128]
    const int o20 = 229376;      // [768,512]
    const int o21 = 622592;      // [256,256]
    const int oL3s = 688128;     // [256,768]
    const int oL3v = 884736;     // [128,384]

    // ---- preconvert weights (unscaled fp16) + features (scale folded) ----
    {
        struct { const float* W; int K, N, off, ld, kOff; } cw[8] = {
            {W10, 256, 768, o10,  256, 0},
            {W11, 128, 256, o11,  128, 0},
            {W20, 512, 768, o20,  512, 0},
            {W21, 256, 256, o21,  256, 0},
            {W30, 512, 256, oL3s, 768, 0},
            {B0,  256, 256, oL3s, 768, 512},
            {W31, 256, 128, oL3v, 384, 0},
            {B1,  128, 128, oL3v, 384, 256}};
        for (int i = 0; i < 8; i++) {
            int tot = cw[i].K * cw[i].N;
            conv_w_kernel<<<(tot + 255) / 256, 256>>>(cw[i].W, cw[i].K, cw[i].N,
                                                      wb + cw[i].off, cw[i].ld, cw[i].kOff);
        }
        size_t tot = M * 640;
        conv_feat_kernel<<<(unsigned)((tot + 255) / 256), 256>>>(features, ft, (int)M);
    }

    const int gy = (int)((M + 127) / 128);
    cudaFuncSetAttribute(tc_gemm, cudaFuncAttributeMaxDynamicSharedMemorySize, SMEM_BYTES);

    __half* fs = ft;                    // [M,256], *s256
    __half* fv = ft + M * 256;          // 3 planes [M,128], *s128
    // ping-pong h buffers
    __half* hs0 = h;                    // [M,512]
    __half* hv0 = h + M * 512;          // 3 planes [M,256]
    __half* hs1 = h + M * 1280;         // [M,512]
    __half* hv1 = h + M * 1792;         // 3 planes [M,256]
    float* oS = oo;                     // planar scalar out [M,256]
    float* oV = oo + M * 256;           // 3 planes [M,128]

    // ---- layer 1 (gate fused): ft -> h0 ----
    tc_gemm<<<dim3(6, gy, 1), 256, SMEM_BYTES>>>(
        fs, 256, 0, fs, 256, 0, 256, wb + o10,
        oo, 0, 0, hs0, 0, gg, (int)M, 256, 1, s512);
    tc_gemm<<<dim3(2, gy, 3), 256, SMEM_BYTES>>>(
        fv, 128, M * 128, fv, 128, M * 128, 128, wb + o11,
        oo, 0, 0, hv0, M * 256, gg, (int)M, 128, 2, s256);
    // ---- layer 2 (gate fused): h0 -> h1 ----
    tc_gemm<<<dim3(6, gy, 1), 256, SMEM_BYTES>>>(
        hs0, 512, 0, hs0, 512, 0, 512, wb + o20,
        oo, 0, 0, hs1, 0, gg, (int)M, 512, 1, s512);
    tc_gemm<<<dim3(2, gy, 3), 256, SMEM_BYTES>>>(
        hv0, 256, M * 256, hv0, 256, M * 256, 256, wb + o21,
        oo, 0, 0, hv1, M * 256, gg, (int)M, 256, 2, s256);
    // ---- layer 3 + bypass (merged via K-concat): h1 (+ft) -> planar g_o ----
    tc_gemm<<<dim3(2, gy, 1), 256, SMEM_BYTES>>>(
        hs1, 512, 0, fs, 256, 0, 512, wb + oL3s,
        oS, 256, 0, hs1, 0, gg, (int)M, 768, 0, 1.f);
    tc_gemm<<<dim3(1, gy, 3), 256, SMEM_BYTES>>>(
        hv1, 256, M * 256, fv, 128, M * 128, 256, wb + oL3v,
        oV, 128, M * 128, hv1, 0, gg, (int)M, 384, 0, 1.f);

    // ---- batch norm (planar) ----
    bn_partial_kernel<<<NPART, 640>>>(oo, psum, psq, (int)M);
    bn_final_kernel<<<1, 640>>>(psum, psq, bw, bb, sc, sh, (int)M);
    {
        size_t total = M * 160;
        bn_apply_kernel<<<(unsigned)((total + 255) / 256), 256>>>(oo, out, sc, sh, (int)M);
    }
}

// round 14
// speedup vs baseline: 3.9894x; 1.0012x over previous
#include <cuda_runtime.h>
#include <cuda_fp16.h>
#include <cstdint>
#include <cstddef>

// ===========================================================================
// FeedForward via pure fp16 mma.sync, gate fused into GEMM epilogue.
//   mode 0: C fp32 planar (layer3+bypass -> g_o scratch)
//   mode 1: scalar gate: cols<512 silu*scale -> hs fp16; cols>=512 sigmoid -> g
//   mode 2: vec gate: acc * g[gm,gn] * scale -> hv fp16 plane
// BK=64 mainloop, single __syncthreads per k-iteration. Planar BN.
// Segment table is a statically-initialized __constant__ (graph-safe).
// ===========================================================================

#define MROWS 100000

// ------------------------------- scratch -----------------------------------
__device__ __half g_hbuf[(size_t)MROWS * 2560];   // h0 [M,1280] | h1 [M,1280]
__device__ __half g_feat[(size_t)MROWS * 640];    // fs [M,256] | fv[d] [M,128]
__device__ float g_gate[(size_t)MROWS * 256];     // sigmoid gate values
__device__ float g_o[(size_t)MROWS * 640];        // planar L3 out: S[M,256]|V[d][M,128]
#define NPART 512
__device__ float g_psum[NPART * 256];
__device__ float g_psq[NPART * 640];
__device__ float g_scale[640];                    // planar-indexed
__device__ float g_shift[640];
#define WTOT 933888
__device__ __align__(256) __half g_wbuf[WTOT];

// weight block offsets (elements in g_wbuf)
#define O10  0        // [768,256]
#define O11  196608   // [256,128]
#define O20  229376   // [768,512]
#define O21  622592   // [256,256]
#define OL3S 688128   // [256,768]  = [W30 | B0] merged, ld 768
#define OL3V 884736   // [128,384]  = [W31 | B1] merged, ld 384

// conv_w segment table: {K, N, off, ld, kOff, startIdx} — compile-time constant
__constant__ int c_wseg[8][6] = {
    {256, 768, O10,  256, 0,   0},
    {128, 256, O11,  128, 0,   196608},
    {512, 768, O20,  512, 0,   229376},
    {256, 256, O21,  256, 0,   622592},
    {512, 256, OL3S, 768, 0,   688128},
    {256, 256, OL3S, 768, 512, 819200},
    {256, 128, OL3V, 384, 0,   884736},
    {128, 128, OL3V, 384, 256, 917504}};

// --------------------------- helpers ---------------------------------------
__device__ __forceinline__ uint32_t smem_to_u32(const void* p) {
    uint32_t a;
    asm("{ .reg .u64 t; cvta.to.shared.u64 t, %1; cvt.u32.u64 %0, t; }" : "=r"(a) : "l"(p));
    return a;
}
__device__ __forceinline__ void ldm4(uint32_t& r0, uint32_t& r1, uint32_t& r2, uint32_t& r3,
                                     uint32_t addr) {
    asm volatile("ldmatrix.sync.aligned.m8n8.x4.shared.b16 {%0,%1,%2,%3}, [%4];"
                 : "=r"(r0), "=r"(r1), "=r"(r2), "=r"(r3) : "r"(addr));
}
__device__ __forceinline__ void mma16816(float* c, const uint32_t* a, const uint32_t* b) {
    asm volatile(
        "mma.sync.aligned.m16n8k16.row.col.f32.f16.f16.f32 "
        "{%0,%1,%2,%3}, {%4,%5,%6,%7}, {%8,%9}, {%0,%1,%2,%3};"
        : "+f"(c[0]), "+f"(c[1]), "+f"(c[2]), "+f"(c[3])
        : "r"(a[0]), "r"(a[1]), "r"(a[2]), "r"(a[3]), "r"(b[0]), "r"(b[1]));
}
#define CP_ASYNC16(dst, src, sz) \
    asm volatile("cp.async.cg.shared.global [%0], [%1], 16, %2;" \
                 :: "r"(dst), "l"(src), "r"(sz) : "memory")
#define CP_COMMIT asm volatile("cp.async.commit_group;" ::: "memory")
#define CP_WAIT0 asm volatile("cp.async.wait_group 0;" ::: "memory")

// ---------------------------------------------------------------------------
// Weight prep (single launch): W[K,N] fp32 -> fp16 [N,*] K-major via segment tbl
// ---------------------------------------------------------------------------
__global__ void conv_w_all_kernel(const float* __restrict__ W10, const float* __restrict__ W11,
                                  const float* __restrict__ W20, const float* __restrict__ W21,
                                  const float* __restrict__ W30, const float* __restrict__ B0,
                                  const float* __restrict__ W31, const float* __restrict__ B1,
                                  __half* __restrict__ wb, int total) {
    int idx = blockIdx.x * blockDim.x + threadIdx.x;
    if (idx >= total) return;
    const float* srcs[8] = {W10, W11, W20, W21, W30, B0, W31, B1};
    int s = 0;
#pragma unroll
    for (int i = 1; i < 8; i++)
        if (idx >= c_wseg[i][5]) s = i;
    int K = c_wseg[s][0];
    int loc = idx - c_wseg[s][5];
    int n = loc / K, k = loc % K;
    int N = c_wseg[s][1];
    size_t dst = (size_t)n * c_wseg[s][3] + c_wseg[s][4] + k + c_wseg[s][2];
    wb[dst] = __float2half_rn(srcs[s][(size_t)k * N + n]);
}

// ---------------------------------------------------------------------------
// Features -> plane-major fp16, scale folded (s: *s256, v: *s128)
// ---------------------------------------------------------------------------
__global__ void conv_feat_kernel(const float* __restrict__ F, __half* __restrict__ out,
                                 int M) {
    size_t idx = (size_t)blockIdx.x * blockDim.x + threadIdx.x;
    size_t total = (size_t)M * 640;
    if (idx >= total) return;
    int c = (int)(idx % 640);
    size_t r = idx / 640;
    const float s256 = 0.0625f;
    const float s128 = 0.08838834764831845f;
    float v;
    size_t off;
    if (c < 256) {
        v = F[r * 640 + c] * s256;
        off = r * 256 + c;
    } else {
        int t = c - 256;
        int d = t / 128, o = t % 128;
        v = F[r * 640 + 256 + o * 3 + d] * s128;
        off = (size_t)M * 256 + (size_t)d * M * 128 + r * 128 + o;
    }
    out[off] = __float2half_rn(v);
}

// ---------------------------------------------------------------------------
// HMMA GEMM: block 128x128, BK=64 (4 k16 steps), single sync per iteration.
// ---------------------------------------------------------------------------
#define SAA 72                      // smem row stride (halfs), 144 B
#define OPBY (128 * SAA * 2)        // 18432 per operand
#define STAGE_BYTES (2 * OPBY)      // 36864
#define SMEM_BYTES (2 * STAGE_BYTES)// 73728

__global__ __launch_bounds__(256) void tc_gemm(
    const __half* __restrict__ A, int lda, size_t aPlane,
    const __half* __restrict__ A2, int lda2, size_t aPlane2, int K1,
    const __half* __restrict__ B,
    float* __restrict__ C, int ldc, size_t cPlane,
    __half* __restrict__ Hout, size_t hPlane,
    float* __restrict__ G,
    int M, int K, int mode, float eScale)
{
    extern __shared__ char smem[];
    const uint32_t sb = smem_to_u32(smem);

    const int tid = threadIdx.x;
    const int wid = tid >> 5;
    const int lane = tid & 31;
    const int warp_m = wid & 3;
    const int warp_n = wid >> 2;
    const int bm = blockIdx.y * 128;
    const int bn = blockIdx.x * 128;
    const int z = blockIdx.z;
    A    += (size_t)z * aPlane;
    A2   += (size_t)z * aPlane2;
    C    += (size_t)z * cPlane;
    Hout += (size_t)z * hPlane;

    const int quad = lane >> 3;
    const int rsel = (lane & 7) + ((quad & 1) << 3);
    const int ksel = (quad >> 1) << 3;

    float acc[2][8][4];
#pragma unroll
    for (int mi = 0; mi < 2; mi++)
#pragma unroll
        for (int nj = 0; nj < 8; nj++)
#pragma unroll
            for (int r = 0; r < 4; r++) acc[mi][nj][r] = 0.f;

    const int nkt = K / 64;

    auto prefetch = [&](int kt, int st) {
        int k0 = kt * 64;
        const __half* pA;
        int plda, kk;
        if (k0 < K1) { pA = A;  plda = lda;  kk = k0; }
        else         { pA = A2; plda = lda2; kk = k0 - K1; }
        const uint32_t base = sb + st * STAGE_BYTES;
#pragma unroll
        for (int i = 0; i < 4; i++) {
            int t = tid + i * 256;
            int row = t >> 3, c = t & 7;
            int gm = bm + row;
            const __half* src = pA + (size_t)gm * plda + kk + c * 8;
            uint32_t dst = base + (uint32_t)(row * SAA) * 2 + c * 16;
            int sz = (gm < M) ? 16 : 0;
            CP_ASYNC16(dst, src, sz);
        }
#pragma unroll
        for (int i = 0; i < 4; i++) {
            int t = tid + i * 256;
            int row = t >> 3, c = t & 7;
            const __half* src = B + (size_t)(bn + row) * K + k0 + c * 8;
            uint32_t dst = base + OPBY + (uint32_t)(row * SAA) * 2 + c * 16;
            CP_ASYNC16(dst, src, 16);
        }
    };

    prefetch(0, 0);
    CP_COMMIT;

    for (int kt = 0; kt < nkt; kt++) {
        CP_WAIT0;            // group kt landed (issued last iter; compute hid it)
        __syncthreads();     // visibility + stage-reuse protection
        if (kt + 1 < nkt) { prefetch(kt + 1, (kt + 1) & 1); CP_COMMIT; }

        const uint32_t sbase = sb + (kt & 1) * STAGE_BYTES;
        const uint32_t aAddr0 = sbase + (uint32_t)((warp_m * 32 + rsel) * SAA + ksel) * 2;
        const uint32_t aAddr1 = aAddr0 + 16 * SAA * 2;
        const uint32_t bAddr0 = sbase + OPBY + (uint32_t)((warp_n * 64 + rsel) * SAA + ksel) * 2;

#pragma unroll
        for (int ks = 0; ks < 4; ks++) {
            const uint32_t kof = ks * 32;
            uint32_t af0[4], af1[4];
            ldm4(af0[0], af0[1], af0[2], af0[3], aAddr0 + kof);
            ldm4(af1[0], af1[1], af1[2], af1[3], aAddr1 + kof);
            uint32_t bf[8][2];
#pragma unroll
            for (int j2 = 0; j2 < 4; j2++) {
                uint32_t r0, r1, r2, r3;
                ldm4(r0, r1, r2, r3, bAddr0 + (uint32_t)(j2 * 16 * SAA) * 2 + kof);
                bf[2 * j2][0] = r0; bf[2 * j2 + 1][0] = r1;
                bf[2 * j2][1] = r2; bf[2 * j2 + 1][1] = r3;
            }
#pragma unroll
            for (int mi = 0; mi < 2; mi++)
#pragma unroll
                for (int nj = 0; nj < 8; nj++)
                    mma16816(acc[mi][nj], mi ? af1 : af0, bf[nj]);
        }
    }

    // ---- epilogue ----
    const int tq = lane >> 2;
    const int tr = lane & 3;
#pragma unroll
    for (int mi = 0; mi < 2; mi++) {
#pragma unroll
        for (int half = 0; half < 2; half++) {
            int gm = bm + warp_m * 32 + mi * 16 + tq + half * 8;
            if (gm >= M) continue;
            if (mode == 0) {
                float* Crow = C + (size_t)gm * ldc + bn + warp_n * 64;
#pragma unroll
                for (int nj = 0; nj < 8; nj++) {
                    int cn = nj * 8 + tr * 2;
                    *(float2*)&Crow[cn] =
                        make_float2(acc[mi][nj][half * 2], acc[mi][nj][half * 2 + 1]);
                }
            } else if (mode == 1) {
#pragma unroll
                for (int nj = 0; nj < 8; nj++) {
                    int gnc = bn + warp_n * 64 + nj * 8 + tr * 2;
                    float v0 = acc[mi][nj][half * 2];
                    float v1 = acc[mi][nj][half * 2 + 1];
                    if (gnc < 512) {
                        float s0 = v0 / (1.f + __expf(-v0)) * eScale;
                        float s1 = v1 / (1.f + __expf(-v1)) * eScale;
                        *(__half2*)&Hout[(size_t)gm * 512 + gnc] = __floats2half2_rn(s0, s1);
                    } else {
                        float g0 = 1.f / (1.f + __expf(-v0));
                        float g1 = 1.f / (1.f + __expf(-v1));
                        *(float2*)&G[(size_t)gm * 256 + (gnc - 512)] = make_float2(g0, g1);
                    }
                }
            } else {
#pragma unroll
                for (int nj = 0; nj < 8; nj++) {
                    int gn = bn + warp_n * 64 + nj * 8 + tr * 2;
                    float2 gg = *(const float2*)&G[(size_t)gm * 256 + gn];
                    float v0 = acc[mi][nj][half * 2] * gg.x * eScale;
                    float v1 = acc[mi][nj][half * 2 + 1] * gg.y * eScale;
                    *(__half2*)&Hout[(size_t)gm * 256 + gn] = __floats2half2_rn(v0, v1);
                }
            }
        }
    }
}

// ---------------------------------------------------------------------------
// Batch-norm (planar)
// ---------------------------------------------------------------------------
__global__ void bn_partial_kernel(const float* __restrict__ O,
                                  float* __restrict__ psum, float* __restrict__ psq, int M)
{
    int p = threadIdx.x;
    float s = 0.f, sq = 0.f;
    if (p < 256) {
        for (int r = blockIdx.x; r < M; r += gridDim.x) {
            float x = O[(size_t)r * 256 + p];
            s += x; sq += x * x;
        }
        psum[blockIdx.x * 256 + p] = s;
    } else {
        int d = (p - 256) >> 7, o = (p - 256) & 127;
        const float* V = O + (size_t)M * 256 + (size_t)d * M * 128;
        for (int r = blockIdx.x; r < M; r += gridDim.x) {
            float x = V[(size_t)r * 128 + o];
            sq += x * x;
        }
    }
    psq[blockIdx.x * 640 + p] = sq;
}

__global__ void bn_final_kernel(const float* __restrict__ psum, const float* __restrict__ psq,
                                const float* __restrict__ w, const float* __restrict__ b,
                                float* __restrict__ scale, float* __restrict__ shift, int M)
{
    __shared__ float ssq[640];
    __shared__ float ssum[256];
    int p = threadIdx.x;
    float sq = 0.f;
    for (int q = 0; q < NPART; q++) sq += psq[q * 640 + p];
    ssq[p] = sq;
    if (p < 256) {
        float s = 0.f;
        for (int q = 0; q < NPART; q++) s += psum[q * 256 + p];
        ssum[p] = s;
    }
    __syncthreads();
    float invN = 1.f / (float)M;
    if (p < 256) {
        float m = ssum[p] * invN;
        float var = ssq[p] * invN - m * m;
        float inv = rsqrtf(var + 1e-5f);
        float sc = inv * w[p];
        scale[p] = sc;
        shift[p] = b[p] - m * sc;
    } else if (p < 256 + 128) {
        int ch = p - 256;
        float t = ssq[256 + ch] + ssq[256 + 128 + ch] + ssq[256 + 256 + ch];
        float mean = t * invN * (1.f / 3.f);
        float inv = rsqrtf(mean + 1e-5f);
        float sc = inv * w[256 + ch];
#pragma unroll
        for (int d = 0; d < 3; d++) {
            scale[256 + d * 128 + ch] = sc;
            shift[256 + d * 128 + ch] = 0.f;
        }
    }
}

__global__ void bn_apply_kernel(const float* __restrict__ O, float* __restrict__ out,
                                const float* __restrict__ scale,
                                const float* __restrict__ shift, int M)
{
    size_t idx = (size_t)blockIdx.x * blockDim.x + threadIdx.x;
    size_t total = (size_t)M * 160;
    if (idx >= total) return;
    int c4 = (int)(idx % 160) * 4;
    size_t r = idx / 160;
    float v[4];
#pragma unroll
    for (int j = 0; j < 4; j++) {
        int c = c4 + j;
        int p;
        float x;
        if (c < 256) {
            p = c;
            x = O[r * 256 + c];
        } else {
            int cc = c - 256;
            int o = cc / 3, d = cc % 3;
            p = 256 + d * 128 + o;
            x = O[(size_t)M * 256 + (size_t)d * M * 128 + r * 128 + o];
        }
        v[j] = x * scale[p] + shift[p];
    }
    *(float4*)&out[r * 640 + c4] = make_float4(v[0], v[1], v[2], v[3]);
}

// ---------------------------------------------------------------------------
extern "C" void kernel_launch(void* const* d_in, const int* in_sizes, int n_in,
                              void* d_out, int out_size)
{
    const float* features = (const float*)d_in[0];
    const float* W10 = (const float*)d_in[1];
    const float* W11 = (const float*)d_in[2];
    const float* W20 = (const float*)d_in[3];
    const float* W21 = (const float*)d_in[4];
    const float* W30 = (const float*)d_in[5];
    const float* W31 = (const float*)d_in[6];
    const float* B0  = (const float*)d_in[7];
    const float* B1  = (const float*)d_in[8];
    const float* bw  = (const float*)d_in[9];
    const float* bb  = (const float*)d_in[10];
    float* out = (float*)d_out;

    float *gg, *oo, *psum, *psq, *sc, *sh;
    __half *wb, *h, *ft;
    cudaGetSymbolAddress((void**)&gg, g_gate);
    cudaGetSymbolAddress((void**)&oo, g_o);
    cudaGetSymbolAddress((void**)&h, g_hbuf);
    cudaGetSymbolAddress((void**)&ft, g_feat);
    cudaGetSymbolAddress((void**)&psum, g_psum);
    cudaGetSymbolAddress((void**)&psq, g_psq);
    cudaGetSymbolAddress((void**)&sc, g_scale);
    cudaGetSymbolAddress((void**)&sh, g_shift);
    cudaGetSymbolAddress((void**)&wb, g_wbuf);

    const size_t M = MROWS;
    const float s512 = 0.04419417382415922f;
    const float s256 = 0.0625f;

    // ---- preconvert weights (single launch, static constant table) + features
    conv_w_all_kernel<<<(WTOT + 255) / 256, 256>>>(W10, W11, W20, W21, W30, B0, W31, B1,
                                                   wb, WTOT);
    {
        size_t tot = M * 640;
        conv_feat_kernel<<<(unsigned)((tot + 255) / 256), 256>>>(features, ft, (int)M);
    }

    const int gy = (int)((M + 127) / 128);
    cudaFuncSetAttribute(tc_gemm, cudaFuncAttributeMaxDynamicSharedMemorySize, SMEM_BYTES);

    __half* fs = ft;                    // [M,256], *s256
    __half* fv = ft + M * 256;          // 3 planes [M,128], *s128
    __half* hs0 = h;                    // [M,512]
    __half* hv0 = h + M * 512;          // 3 planes [M,256]
    __half* hs1 = h + M * 1280;         // [M,512]
    __half* hv1 = h + M * 1792;         // 3 planes [M,256]
    float* oS = oo;                     // planar scalar out [M,256]
    float* oV = oo + M * 256;           // 3 planes [M,128]

    // ---- layer 1 (gate fused): ft -> h0 ----
    tc_gemm<<<dim3(6, gy, 1), 256, SMEM_BYTES>>>(
        fs, 256, 0, fs, 256, 0, 256, wb + O10,
        oo, 0, 0, hs0, 0, gg, (int)M, 256, 1, s512);
    tc_gemm<<<dim3(2, gy, 3), 256, SMEM_BYTES>>>(
        fv, 128, M * 128, fv, 128, M * 128, 128, wb + O11,
        oo, 0, 0, hv0, M * 256, gg, (int)M, 128, 2, s256);
    // ---- layer 2 (gate fused): h0 -> h1 ----
    tc_gemm<<<dim3(6, gy, 1), 256, SMEM_BYTES>>>(
        hs0, 512, 0, hs0, 512, 0, 512, wb + O20,
        oo, 0, 0, hs1, 0, gg, (int)M, 512, 1, s512);
    tc_gemm<<<dim3(2, gy, 3), 256, SMEM_BYTES>>>(
        hv0, 256, M * 256, hv0, 256, M * 256, 256, wb + O21,
        oo, 0, 0, hv1, M * 256, gg, (int)M, 256, 2, s256);
    // ---- layer 3 + bypass (merged via K-concat): h1 (+ft) -> planar g_o ----
    tc_gemm<<<dim3(2, gy, 1), 256, SMEM_BYTES>>>(
        hs1, 512, 0, fs, 256, 0, 512, wb + OL3S,
        oS, 256, 0, hs1, 0, gg, (int)M, 768, 0, 1.f);
    tc_gemm<<<dim3(1, gy, 3), 256, SMEM_BYTES>>>(
        hv1, 256, M * 256, fv, 128, M * 128, 256, wb + OL3V,
        oV, 128, M * 128, hv1, 0, gg, (int)M, 384, 0, 1.f);

    // ---- batch norm (planar) ----
    bn_partial_kernel<<<NPART, 640>>>(oo, psum, psq, (int)M);
    bn_final_kernel<<<1, 640>>>(psum, psq, bw, bb, sc, sh, (int)M);
    {
        size_t total = M * 160;
        bn_apply_kernel<<<(unsigned)((total + 255) / 256), 256>>>(oo, out, sc, sh, (int)M);
    }
}

// round 15
// speedup vs baseline: 3.9941x; 1.0012x over previous
#include <cuda_runtime.h>
#include <cuda_fp16.h>
#include <cstdint>
#include <cstddef>

// ===========================================================================
// FeedForward via pure fp16 mma.sync, gate fused into GEMM epilogue.
// 3-stage cp.async pipeline (wait_group<=1), BK=64, single sync per iter.
// ===========================================================================

#define MROWS 100000

// ------------------------------- scratch -----------------------------------
__device__ __half g_hbuf[(size_t)MROWS * 2560];   // h0 [M,1280] | h1 [M,1280]
__device__ __half g_feat[(size_t)MROWS * 640];    // fs [M,256] | fv[d] [M,128]
__device__ float g_gate[(size_t)MROWS * 256];     // sigmoid gate values
__device__ float g_o[(size_t)MROWS * 640];        // planar L3 out: S[M,256]|V[d][M,128]
#define NPART 512
__device__ float g_psum[NPART * 256];
__device__ float g_psq[NPART * 640];
__device__ float g_scale[640];
__device__ float g_shift[640];
#define WTOT 933888
__device__ __align__(256) __half g_wbuf[WTOT];

// weight block offsets (elements in g_wbuf)
#define O10  0        // [768,256]
#define O11  196608   // [256,128]
#define O20  229376   // [768,512]
#define O21  622592   // [256,256]
#define OL3S 688128   // [256,768]  = [W30 | B0] merged, ld 768
#define OL3V 884736   // [128,384]  = [W31 | B1] merged, ld 384

// conv_w segment table: {K, N, off, ld, kOff, startIdx}
__constant__ int c_wseg[8][6] = {
    {256, 768, O10,  256, 0,   0},
    {128, 256, O11,  128, 0,   196608},
    {512, 768, O20,  512, 0,   229376},
    {256, 256, O21,  256, 0,   622592},
    {512, 256, OL3S, 768, 0,   688128},
    {256, 256, OL3S, 768, 512, 819200},
    {256, 128, OL3V, 384, 0,   884736},
    {128, 128, OL3V, 384, 256, 917504}};

// --------------------------- helpers ---------------------------------------
__device__ __forceinline__ uint32_t smem_to_u32(const void* p) {
    uint32_t a;
    asm("{ .reg .u64 t; cvta.to.shared.u64 t, %1; cvt.u32.u64 %0, t; }" : "=r"(a) : "l"(p));
    return a;
}
__device__ __forceinline__ void ldm4(uint32_t& r0, uint32_t& r1, uint32_t& r2, uint32_t& r3,
                                     uint32_t addr) {
    asm volatile("ldmatrix.sync.aligned.m8n8.x4.shared.b16 {%0,%1,%2,%3}, [%4];"
                 : "=r"(r0), "=r"(r1), "=r"(r2), "=r"(r3) : "r"(addr));
}
__device__ __forceinline__ void mma16816(float* c, const uint32_t* a, const uint32_t* b) {
    asm volatile(
        "mma.sync.aligned.m16n8k16.row.col.f32.f16.f16.f32 "
        "{%0,%1,%2,%3}, {%4,%5,%6,%7}, {%8,%9}, {%0,%1,%2,%3};"
        : "+f"(c[0]), "+f"(c[1]), "+f"(c[2]), "+f"(c[3])
        : "r"(a[0]), "r"(a[1]), "r"(a[2]), "r"(a[3]), "r"(b[0]), "r"(b[1]));
}
#define CP_ASYNC16(dst, src, sz) \
    asm volatile("cp.async.cg.shared.global [%0], [%1], 16, %2;" \
                 :: "r"(dst), "l"(src), "r"(sz) : "memory")
#define CP_COMMIT asm volatile("cp.async.commit_group;" ::: "memory")
#define CP_WAIT1 asm volatile("cp.async.wait_group 1;" ::: "memory")
#define CP_WAIT0 asm volatile("cp.async.wait_group 0;" ::: "memory")

// ---------------------------------------------------------------------------
// Weight prep (single launch)
// ---------------------------------------------------------------------------
__global__ void conv_w_all_kernel(const float* __restrict__ W10, const float* __restrict__ W11,
                                  const float* __restrict__ W20, const float* __restrict__ W21,
                                  const float* __restrict__ W30, const float* __restrict__ B0,
                                  const float* __restrict__ W31, const float* __restrict__ B1,
                                  __half* __restrict__ wb, int total) {
    int idx = blockIdx.x * blockDim.x + threadIdx.x;
    if (idx >= total) return;
    const float* srcs[8] = {W10, W11, W20, W21, W30, B0, W31, B1};
    int s = 0;
#pragma unroll
    for (int i = 1; i < 8; i++)
        if (idx >= c_wseg[i][5]) s = i;
    int K = c_wseg[s][0];
    int loc = idx - c_wseg[s][5];
    int n = loc / K, k = loc % K;
    int N = c_wseg[s][1];
    size_t dst = (size_t)n * c_wseg[s][3] + c_wseg[s][4] + k + c_wseg[s][2];
    wb[dst] = __float2half_rn(srcs[s][(size_t)k * N + n]);
}

// ---------------------------------------------------------------------------
// Features -> plane-major fp16, scale folded
// ---------------------------------------------------------------------------
__global__ void conv_feat_kernel(const float* __restrict__ F, __half* __restrict__ out,
                                 int M) {
    size_t idx = (size_t)blockIdx.x * blockDim.x + threadIdx.x;
    size_t total = (size_t)M * 640;
    if (idx >= total) return;
    int c = (int)(idx % 640);
    size_t r = idx / 640;
    const float s256 = 0.0625f;
    const float s128 = 0.08838834764831845f;
    float v;
    size_t off;
    if (c < 256) {
        v = F[r * 640 + c] * s256;
        off = r * 256 + c;
    } else {
        int t = c - 256;
        int d = t / 128, o = t % 128;
        v = F[r * 640 + 256 + o * 3 + d] * s128;
        off = (size_t)M * 256 + (size_t)d * M * 128 + r * 128 + o;
    }
    out[off] = __float2half_rn(v);
}

// ---------------------------------------------------------------------------
// HMMA GEMM: block 128x128, BK=64, 3-stage cp.async pipeline.
// ---------------------------------------------------------------------------
#define SAA 72                      // smem row stride (halfs), 144 B
#define OPBY (128 * SAA * 2)        // 18432 per operand
#define STAGE_BYTES (2 * OPBY)      // 36864
#define NSTAGE 3
#define SMEM_BYTES (NSTAGE * STAGE_BYTES)   // 110592

__global__ __launch_bounds__(256) void tc_gemm(
    const __half* __restrict__ A, int lda, size_t aPlane,
    const __half* __restrict__ A2, int lda2, size_t aPlane2, int K1,
    const __half* __restrict__ B,
    float* __restrict__ C, int ldc, size_t cPlane,
    __half* __restrict__ Hout, size_t hPlane,
    float* __restrict__ G,
    int M, int K, int mode, float eScale)
{
    extern __shared__ char smem[];
    const uint32_t sb = smem_to_u32(smem);

    const int tid = threadIdx.x;
    const int wid = tid >> 5;
    const int lane = tid & 31;
    const int warp_m = wid & 3;
    const int warp_n = wid >> 2;
    const int bm = blockIdx.y * 128;
    const int bn = blockIdx.x * 128;
    const int z = blockIdx.z;
    A    += (size_t)z * aPlane;
    A2   += (size_t)z * aPlane2;
    C    += (size_t)z * cPlane;
    Hout += (size_t)z * hPlane;

    const int quad = lane >> 3;
    const int rsel = (lane & 7) + ((quad & 1) << 3);
    const int ksel = (quad >> 1) << 3;

    float acc[2][8][4];
#pragma unroll
    for (int mi = 0; mi < 2; mi++)
#pragma unroll
        for (int nj = 0; nj < 8; nj++)
#pragma unroll
            for (int r = 0; r < 4; r++) acc[mi][nj][r] = 0.f;

    const int nkt = K / 64;

    auto prefetch = [&](int kt, int st) {
        int k0 = kt * 64;
        const __half* pA;
        int plda, kk;
        if (k0 < K1) { pA = A;  plda = lda;  kk = k0; }
        else         { pA = A2; plda = lda2; kk = k0 - K1; }
        const uint32_t base = sb + st * STAGE_BYTES;
#pragma unroll
        for (int i = 0; i < 4; i++) {
            int t = tid + i * 256;
            int row = t >> 3, c = t & 7;
            int gm = bm + row;
            const __half* src = pA + (size_t)gm * plda + kk + c * 8;
            uint32_t dst = base + (uint32_t)(row * SAA) * 2 + c * 16;
            int sz = (gm < M) ? 16 : 0;
            CP_ASYNC16(dst, src, sz);
        }
#pragma unroll
        for (int i = 0; i < 4; i++) {
            int t = tid + i * 256;
            int row = t >> 3, c = t & 7;
            const __half* src = B + (size_t)(bn + row) * K + k0 + c * 8;
            uint32_t dst = base + OPBY + (uint32_t)(row * SAA) * 2 + c * 16;
            CP_ASYNC16(dst, src, 16);
        }
    };

    // prime 2 stages
    prefetch(0, 0);
    CP_COMMIT;
    if (nkt > 1) { prefetch(1, 1); CP_COMMIT; }

    int st = 0;
    for (int kt = 0; kt < nkt; kt++) {
        if (kt + 1 < nkt) { CP_WAIT1; } else { CP_WAIT0; }  // group kt landed
        __syncthreads();   // all compute(kt-1) reads done before stage reuse
        if (kt + 2 < nkt) {
            int st2 = st + 2; if (st2 >= NSTAGE) st2 -= NSTAGE;
            prefetch(kt + 2, st2);
            CP_COMMIT;
        }

        const uint32_t sbase = sb + st * STAGE_BYTES;
        const uint32_t aAddr0 = sbase + (uint32_t)((warp_m * 32 + rsel) * SAA + ksel) * 2;
        const uint32_t aAddr1 = aAddr0 + 16 * SAA * 2;
        const uint32_t bAddr0 = sbase + OPBY + (uint32_t)((warp_n * 64 + rsel) * SAA + ksel) * 2;

#pragma unroll
        for (int ks = 0; ks < 4; ks++) {
            const uint32_t kof = ks * 32;
            uint32_t af0[4], af1[4];
            ldm4(af0[0], af0[1], af0[2], af0[3], aAddr0 + kof);
            ldm4(af1[0], af1[1], af1[2], af1[3], aAddr1 + kof);
            uint32_t bf[8][2];
#pragma unroll
            for (int j2 = 0; j2 < 4; j2++) {
                uint32_t r0, r1, r2, r3;
                ldm4(r0, r1, r2, r3, bAddr0 + (uint32_t)(j2 * 16 * SAA) * 2 + kof);
                bf[2 * j2][0] = r0; bf[2 * j2 + 1][0] = r1;
                bf[2 * j2][1] = r2; bf[2 * j2 + 1][1] = r3;
            }
#pragma unroll
            for (int mi = 0; mi < 2; mi++)
#pragma unroll
                for (int nj = 0; nj < 8; nj++)
                    mma16816(acc[mi][nj], mi ? af1 : af0, bf[nj]);
        }
        if (++st >= NSTAGE) st = 0;
    }

    // ---- epilogue ----
    const int tq = lane >> 2;
    const int tr = lane & 3;
#pragma unroll
    for (int mi = 0; mi < 2; mi++) {
#pragma unroll
        for (int half = 0; half < 2; half++) {
            int gm = bm + warp_m * 32 + mi * 16 + tq + half * 8;
            if (gm >= M) continue;
            if (mode == 0) {
                float* Crow = C + (size_t)gm * ldc + bn + warp_n * 64;
#pragma unroll
                for (int nj = 0; nj < 8; nj++) {
                    int cn = nj * 8 + tr * 2;
                    *(float2*)&Crow[cn] =
                        make_float2(acc[mi][nj][half * 2], acc[mi][nj][half * 2 + 1]);
                }
            } else if (mode == 1) {
#pragma unroll
                for (int nj = 0; nj < 8; nj++) {
                    int gnc = bn + warp_n * 64 + nj * 8 + tr * 2;
                    float v0 = acc[mi][nj][half * 2];
                    float v1 = acc[mi][nj][half * 2 + 1];
                    if (gnc < 512) {
                        float s0 = v0 / (1.f + __expf(-v0)) * eScale;
                        float s1 = v1 / (1.f + __expf(-v1)) * eScale;
                        *(__half2*)&Hout[(size_t)gm * 512 + gnc] = __floats2half2_rn(s0, s1);
                    } else {
                        float g0 = 1.f / (1.f + __expf(-v0));
                        float g1 = 1.f / (1.f + __expf(-v1));
                        *(float2*)&G[(size_t)gm * 256 + (gnc - 512)] = make_float2(g0, g1);
                    }
                }
            } else {
#pragma unroll
                for (int nj = 0; nj < 8; nj++) {
                    int gn = bn + warp_n * 64 + nj * 8 + tr * 2;
                    float2 gg = *(const float2*)&G[(size_t)gm * 256 + gn];
                    float v0 = acc[mi][nj][half * 2] * gg.x * eScale;
                    float v1 = acc[mi][nj][half * 2 + 1] * gg.y * eScale;
                    *(__half2*)&Hout[(size_t)gm * 256 + gn] = __floats2half2_rn(v0, v1);
                }
            }
        }
    }
}

// ---------------------------------------------------------------------------
// Batch-norm (planar)
// ---------------------------------------------------------------------------
__global__ void bn_partial_kernel(const float* __restrict__ O,
                                  float* __restrict__ psum, float* __restrict__ psq, int M)
{
    int p = threadIdx.x;
    float s = 0.f, sq = 0.f;
    if (p < 256) {
        for (int r = blockIdx.x; r < M; r += gridDim.x) {
            float x = O[(size_t)r * 256 + p];
            s += x; sq += x * x;
        }
        psum[blockIdx.x * 256 + p] = s;
    } else {
        int d = (p - 256) >> 7, o = (p - 256) & 127;
        const float* V = O + (size_t)M * 256 + (size_t)d * M * 128;
        for (int r = blockIdx.x; r < M; r += gridDim.x) {
            float x = V[(size_t)r * 128 + o];
            sq += x * x;
        }
    }
    psq[blockIdx.x * 640 + p] = sq;
}

__global__ void bn_final_kernel(const float* __restrict__ psum, const float* __restrict__ psq,
                                const float* __restrict__ w, const float* __restrict__ b,
                                float* __restrict__ scale, float* __restrict__ shift, int M)
{
    __shared__ float ssq[640];
    __shared__ float ssum[256];
    int p = threadIdx.x;
    float sq = 0.f;
    for (int q = 0; q < NPART; q++) sq += psq[q * 640 + p];
    ssq[p] = sq;
    if (p < 256) {
        float s = 0.f;
        for (int q = 0; q < NPART; q++) s += psum[q * 256 + p];
        ssum[p] = s;
    }
    __syncthreads();
    float invN = 1.f / (float)M;
    if (p < 256) {
        float m = ssum[p] * invN;
        float var = ssq[p] * invN - m * m;
        float inv = rsqrtf(var + 1e-5f);
        float sc = inv * w[p];
        scale[p] = sc;
        shift[p] = b[p] - m * sc;
    } else if (p < 256 + 128) {
        int ch = p - 256;
        float t = ssq[256 + ch] + ssq[256 + 128 + ch] + ssq[256 + 256 + ch];
        float mean = t * invN * (1.f / 3.f);
        float inv = rsqrtf(mean + 1e-5f);
        float sc = inv * w[256 + ch];
#pragma unroll
        for (int d = 0; d < 3; d++) {
            scale[256 + d * 128 + ch] = sc;
            shift[256 + d * 128 + ch] = 0.f;
        }
    }
}

__global__ void bn_apply_kernel(const float* __restrict__ O, float* __restrict__ out,
                                const float* __restrict__ scale,
                                const float* __restrict__ shift, int M)
{
    size_t idx = (size_t)blockIdx.x * blockDim.x + threadIdx.x;
    size_t total = (size_t)M * 160;
    if (idx >= total) return;
    int c4 = (int)(idx % 160) * 4;
    size_t r = idx / 160;
    float v[4];
#pragma unroll
    for (int j = 0; j < 4; j++) {
        int c = c4 + j;
        int p;
        float x;
        if (c < 256) {
            p = c;
            x = O[r * 256 + c];
        } else {
            int cc = c - 256;
            int o = cc / 3, d = cc % 3;
            p = 256 + d * 128 + o;
            x = O[(size_t)M * 256 + (size_t)d * M * 128 + r * 128 + o];
        }
        v[j] = x * scale[p] + shift[p];
    }
    *(float4*)&out[r * 640 + c4] = make_float4(v[0], v[1], v[2], v[3]);
}

// ---------------------------------------------------------------------------
extern "C" void kernel_launch(void* const* d_in, const int* in_sizes, int n_in,
                              void* d_out, int out_size)
{
    const float* features = (const float*)d_in[0];
    const float* W10 = (const float*)d_in[1];
    const float* W11 = (const float*)d_in[2];
    const float* W20 = (const float*)d_in[3];
    const float* W21 = (const float*)d_in[4];
    const float* W30 = (const float*)d_in[5];
    const float* W31 = (const float*)d_in[6];
    const float* B0  = (const float*)d_in[7];
    const float* B1  = (const float*)d_in[8];
    const float* bw  = (const float*)d_in[9];
    const float* bb  = (const float*)d_in[10];
    float* out = (float*)d_out;

    float *gg, *oo, *psum, *psq, *sc, *sh;
    __half *wb, *h, *ft;
    cudaGetSymbolAddress((void**)&gg, g_gate);
    cudaGetSymbolAddress((void**)&oo, g_o);
    cudaGetSymbolAddress((void**)&h, g_hbuf);
    cudaGetSymbolAddress((void**)&ft, g_feat);
    cudaGetSymbolAddress((void**)&psum, g_psum);
    cudaGetSymbolAddress((void**)&psq, g_psq);
    cudaGetSymbolAddress((void**)&sc, g_scale);
    cudaGetSymbolAddress((void**)&sh, g_shift);
    cudaGetSymbolAddress((void**)&wb, g_wbuf);

    const size_t M = MROWS;
    const float s512 = 0.04419417382415922f;
    const float s256 = 0.0625f;

    conv_w_all_kernel<<<(WTOT + 255) / 256, 256>>>(W10, W11, W20, W21, W30, B0, W31, B1,
                                                   wb, WTOT);
    {
        size_t tot = M * 640;
        conv_feat_kernel<<<(unsigned)((tot + 255) / 256), 256>>>(features, ft, (int)M);
    }

    const int gy = (int)((M + 127) / 128);
    cudaFuncSetAttribute(tc_gemm, cudaFuncAttributeMaxDynamicSharedMemorySize, SMEM_BYTES);

    __half* fs = ft;                    // [M,256], *s256
    __half* fv = ft + M * 256;          // 3 planes [M,128], *s128
    __half* hs0 = h;                    // [M,512]
    __half* hv0 = h + M * 512;          // 3 planes [M,256]
    __half* hs1 = h + M * 1280;         // [M,512]
    __half* hv1 = h + M * 1792;         // 3 planes [M,256]
    float* oS = oo;                     // planar scalar out [M,256]
    float* oV = oo + M * 256;           // 3 planes [M,128]

    // ---- layer 1 (gate fused): ft -> h0 ----
    tc_gemm<<<dim3(6, gy, 1), 256, SMEM_BYTES>>>(
        fs, 256, 0, fs, 256, 0, 256, wb + O10,
        oo, 0, 0, hs0, 0, gg, (int)M, 256, 1, s512);
    tc_gemm<<<dim3(2, gy, 3), 256, SMEM_BYTES>>>(
        fv, 128, M * 128, fv, 128, M * 128, 128, wb + O11,
        oo, 0, 0, hv0, M * 256, gg, (int)M, 128, 2, s256);
    // ---- layer 2 (gate fused): h0 -> h1 ----
    tc_gemm<<<dim3(6, gy, 1), 256, SMEM_BYTES>>>(
        hs0, 512, 0, hs0, 512, 0, 512, wb + O20,
        oo, 0, 0, hs1, 0, gg, (int)M, 512, 1, s512);
    tc_gemm<<<dim3(2, gy, 3), 256, SMEM_BYTES>>>(
        hv0, 256, M * 256, hv0, 256, M * 256, 256, wb + O21,
        oo, 0, 0, hv1, M * 256, gg, (int)M, 256, 2, s256);
    // ---- layer 3 + bypass (merged via K-concat): h1 (+ft) -> planar g_o ----
    tc_gemm<<<dim3(2, gy, 1), 256, SMEM_BYTES>>>(
        hs1, 512, 0, fs, 256, 0, 512, wb + OL3S,
        oS, 256, 0, hs1, 0, gg, (int)M, 768, 0, 1.f);
    tc_gemm<<<dim3(1, gy, 3), 256, SMEM_BYTES>>>(
        hv1, 256, M * 256, fv, 128, M * 128, 256, wb + OL3V,
        oV, 128, M * 128, hv1, 0, gg, (int)M, 384, 0, 1.f);

    // ---- batch norm (planar) ----
    bn_partial_kernel<<<NPART, 640>>>(oo, psum, psq, (int)M);
    bn_final_kernel<<<1, 640>>>(psum, psq, bw, bb, sc, sh, (int)M);
    {
        size_t total = M * 160;
        bn_apply_kernel<<<(unsigned)((total + 255) / 256), 256>>>(oo, out, sc, sh, (int)M);
    }
}

// round 16
// speedup vs baseline: 4.1837x; 1.0475x over previous
#include <cuda_runtime.h>
#include <cuda_fp16.h>
#include <cstdint>
#include <cstddef>

// ===========================================================================
// FeedForward via pure fp16 mma.sync, gate fused into GEMM epilogue.
// Block tile 128x64 (warp tile 32x32) for 3 CTAs/SM occupancy. BK=64.
// ===========================================================================

#define MROWS 100000

// ------------------------------- scratch -----------------------------------
__device__ __half g_hbuf[(size_t)MROWS * 2560];   // h0 [M,1280] | h1 [M,1280]
__device__ __half g_feat[(size_t)MROWS * 640];    // fs [M,256] | fv[d] [M,128]
__device__ float g_gate[(size_t)MROWS * 256];     // sigmoid gate values
__device__ float g_o[(size_t)MROWS * 640];        // planar L3 out: S[M,256]|V[d][M,128]
#define NPART 512
__device__ float g_psum[NPART * 256];
__device__ float g_psq[NPART * 640];
__device__ float g_scale[640];
__device__ float g_shift[640];
#define WTOT 933888
__device__ __align__(256) __half g_wbuf[WTOT];

// weight block offsets (elements in g_wbuf)
#define O10  0        // [768,256]
#define O11  196608   // [256,128]
#define O20  229376   // [768,512]
#define O21  622592   // [256,256]
#define OL3S 688128   // [256,768]  = [W30 | B0] merged, ld 768
#define OL3V 884736   // [128,384]  = [W31 | B1] merged, ld 384

__constant__ int c_wseg[8][6] = {
    {256, 768, O10,  256, 0,   0},
    {128, 256, O11,  128, 0,   196608},
    {512, 768, O20,  512, 0,   229376},
    {256, 256, O21,  256, 0,   622592},
    {512, 256, OL3S, 768, 0,   688128},
    {256, 256, OL3S, 768, 512, 819200},
    {256, 128, OL3V, 384, 0,   884736},
    {128, 128, OL3V, 384, 256, 917504}};

// --------------------------- helpers ---------------------------------------
__device__ __forceinline__ uint32_t smem_to_u32(const void* p) {
    uint32_t a;
    asm("{ .reg .u64 t; cvta.to.shared.u64 t, %1; cvt.u32.u64 %0, t; }" : "=r"(a) : "l"(p));
    return a;
}
__device__ __forceinline__ void ldm4(uint32_t& r0, uint32_t& r1, uint32_t& r2, uint32_t& r3,
                                     uint32_t addr) {
    asm volatile("ldmatrix.sync.aligned.m8n8.x4.shared.b16 {%0,%1,%2,%3}, [%4];"
                 : "=r"(r0), "=r"(r1), "=r"(r2), "=r"(r3) : "r"(addr));
}
__device__ __forceinline__ void mma16816(float* c, const uint32_t* a, const uint32_t* b) {
    asm volatile(
        "mma.sync.aligned.m16n8k16.row.col.f32.f16.f16.f32 "
        "{%0,%1,%2,%3}, {%4,%5,%6,%7}, {%8,%9}, {%0,%1,%2,%3};"
        : "+f"(c[0]), "+f"(c[1]), "+f"(c[2]), "+f"(c[3])
        : "r"(a[0]), "r"(a[1]), "r"(a[2]), "r"(a[3]), "r"(b[0]), "r"(b[1]));
}
#define CP_ASYNC16(dst, src, sz) \
    asm volatile("cp.async.cg.shared.global [%0], [%1], 16, %2;" \
                 :: "r"(dst), "l"(src), "r"(sz) : "memory")
#define CP_COMMIT asm volatile("cp.async.commit_group;" ::: "memory")
#define CP_WAIT1 asm volatile("cp.async.wait_group 1;" ::: "memory")
#define CP_WAIT0 asm volatile("cp.async.wait_group 0;" ::: "memory")

// ---------------------------------------------------------------------------
// Weight prep (single launch)
// ---------------------------------------------------------------------------
__global__ void conv_w_all_kernel(const float* __restrict__ W10, const float* __restrict__ W11,
                                  const float* __restrict__ W20, const float* __restrict__ W21,
                                  const float* __restrict__ W30, const float* __restrict__ B0,
                                  const float* __restrict__ W31, const float* __restrict__ B1,
                                  __half* __restrict__ wb, int total) {
    int idx = blockIdx.x * blockDim.x + threadIdx.x;
    if (idx >= total) return;
    const float* srcs[8] = {W10, W11, W20, W21, W30, B0, W31, B1};
    int s = 0;
#pragma unroll
    for (int i = 1; i < 8; i++)
        if (idx >= c_wseg[i][5]) s = i;
    int K = c_wseg[s][0];
    int loc = idx - c_wseg[s][5];
    int n = loc / K, k = loc % K;
    int N = c_wseg[s][1];
    size_t dst = (size_t)n * c_wseg[s][3] + c_wseg[s][4] + k + c_wseg[s][2];
    wb[dst] = __float2half_rn(srcs[s][(size_t)k * N + n]);
}

// ---------------------------------------------------------------------------
// Features -> plane-major fp16, scale folded
// ---------------------------------------------------------------------------
__global__ void conv_feat_kernel(const float* __restrict__ F, __half* __restrict__ out,
                                 int M) {
    size_t idx = (size_t)blockIdx.x * blockDim.x + threadIdx.x;
    size_t total = (size_t)M * 640;
    if (idx >= total) return;
    int c = (int)(idx % 640);
    size_t r = idx / 640;
    const float s256 = 0.0625f;
    const float s128 = 0.08838834764831845f;
    float v;
    size_t off;
    if (c < 256) {
        v = F[r * 640 + c] * s256;
        off = r * 256 + c;
    } else {
        int t = c - 256;
        int d = t / 128, o = t % 128;
        v = F[r * 640 + 256 + o * 3 + d] * s128;
        off = (size_t)M * 256 + (size_t)d * M * 128 + r * 128 + o;
    }
    out[off] = __float2half_rn(v);
}

// ---------------------------------------------------------------------------
// HMMA GEMM: block 128x64, BK=64, warp tile 32x32, 2-stage cp.async.
// ---------------------------------------------------------------------------
#define SAA 72                      // smem row stride (halfs), 144 B
#define A_BY (128 * SAA * 2)        // 18432
#define B_BY (64 * SAA * 2)         // 9216
#define STAGE_BYTES (A_BY + B_BY)   // 27648
#define SMEM_BYTES (2 * STAGE_BYTES)// 55296

__global__ __launch_bounds__(256, 3) void tc_gemm(
    const __half* __restrict__ A, int lda, size_t aPlane,
    const __half* __restrict__ A2, int lda2, size_t aPlane2, int K1,
    const __half* __restrict__ B,
    float* __restrict__ C, int ldc, size_t cPlane,
    __half* __restrict__ Hout, size_t hPlane,
    float* __restrict__ G,
    int M, int K, int mode, float eScale)
{
    extern __shared__ char smem[];
    const uint32_t sb = smem_to_u32(smem);

    const int tid = threadIdx.x;
    const int wid = tid >> 5;
    const int lane = tid & 31;
    const int warp_m = wid & 3;     // 4 x 32 rows
    const int warp_n = wid >> 2;    // 2 x 32 cols
    const int bm = blockIdx.y * 128;
    const int bn = blockIdx.x * 64;
    const int z = blockIdx.z;
    A    += (size_t)z * aPlane;
    A2   += (size_t)z * aPlane2;
    C    += (size_t)z * cPlane;
    Hout += (size_t)z * hPlane;

    const int quad = lane >> 3;
    const int rsel = (lane & 7) + ((quad & 1) << 3);
    const int ksel = (quad >> 1) << 3;

    float acc[2][4][4];
#pragma unroll
    for (int mi = 0; mi < 2; mi++)
#pragma unroll
        for (int nj = 0; nj < 4; nj++)
#pragma unroll
            for (int r = 0; r < 4; r++) acc[mi][nj][r] = 0.f;

    const int nkt = K / 64;

    auto prefetch = [&](int kt, int st) {
        int k0 = kt * 64;
        const __half* pA;
        int plda, kk;
        if (k0 < K1) { pA = A;  plda = lda;  kk = k0; }
        else         { pA = A2; plda = lda2; kk = k0 - K1; }
        const uint32_t base = sb + st * STAGE_BYTES;
        // A: 128 rows x 8 chunks of 16B
#pragma unroll
        for (int i = 0; i < 4; i++) {
            int t = tid + i * 256;
            int row = t >> 3, c = t & 7;
            int gm = bm + row;
            const __half* src = pA + (size_t)gm * plda + kk + c * 8;
            uint32_t dst = base + (uint32_t)(row * SAA) * 2 + c * 16;
            int sz = (gm < M) ? 16 : 0;
            CP_ASYNC16(dst, src, sz);
        }
        // B: 64 n-rows x 8 chunks of 16B
#pragma unroll
        for (int i = 0; i < 2; i++) {
            int t = tid + i * 256;
            int row = t >> 3, c = t & 7;
            const __half* src = B + (size_t)(bn + row) * K + k0 + c * 8;
            uint32_t dst = base + A_BY + (uint32_t)(row * SAA) * 2 + c * 16;
            CP_ASYNC16(dst, src, 16);
        }
    };

    prefetch(0, 0);
    CP_COMMIT;

    for (int kt = 0; kt < nkt; kt++) {
        CP_WAIT0;
        __syncthreads();
        if (kt + 1 < nkt) { prefetch(kt + 1, (kt + 1) & 1); CP_COMMIT; }

        const uint32_t sbase = sb + (kt & 1) * STAGE_BYTES;
        const uint32_t aAddr0 = sbase + (uint32_t)((warp_m * 32 + rsel) * SAA + ksel) * 2;
        const uint32_t aAddr1 = aAddr0 + 16 * SAA * 2;
        const uint32_t bAddr0 = sbase + A_BY + (uint32_t)((warp_n * 32 + rsel) * SAA + ksel) * 2;
        const uint32_t bAddr1 = bAddr0 + 16 * SAA * 2;

#pragma unroll
        for (int ks = 0; ks < 4; ks++) {
            const uint32_t kof = ks * 32;
            uint32_t af0[4], af1[4];
            ldm4(af0[0], af0[1], af0[2], af0[3], aAddr0 + kof);
            ldm4(af1[0], af1[1], af1[2], af1[3], aAddr1 + kof);
            uint32_t bf[4][2];
            {
                uint32_t r0, r1, r2, r3;
                ldm4(r0, r1, r2, r3, bAddr0 + kof);
                bf[0][0] = r0; bf[1][0] = r1; bf[0][1] = r2; bf[1][1] = r3;
                ldm4(r0, r1, r2, r3, bAddr1 + kof);
                bf[2][0] = r0; bf[3][0] = r1; bf[2][1] = r2; bf[3][1] = r3;
            }
#pragma unroll
            for (int mi = 0; mi < 2; mi++)
#pragma unroll
                for (int nj = 0; nj < 4; nj++)
                    mma16816(acc[mi][nj], mi ? af1 : af0, bf[nj]);
        }
    }

    // ---- epilogue ----
    const int tq = lane >> 2;
    const int tr = lane & 3;
#pragma unroll
    for (int mi = 0; mi < 2; mi++) {
#pragma unroll
        for (int half = 0; half < 2; half++) {
            int gm = bm + warp_m * 32 + mi * 16 + tq + half * 8;
            if (gm >= M) continue;
            if (mode == 0) {
                float* Crow = C + (size_t)gm * ldc + bn + warp_n * 32;
#pragma unroll
                for (int nj = 0; nj < 4; nj++) {
                    int cn = nj * 8 + tr * 2;
                    *(float2*)&Crow[cn] =
                        make_float2(acc[mi][nj][half * 2], acc[mi][nj][half * 2 + 1]);
                }
            } else if (mode == 1) {
#pragma unroll
                for (int nj = 0; nj < 4; nj++) {
                    int gnc = bn + warp_n * 32 + nj * 8 + tr * 2;
                    float v0 = acc[mi][nj][half * 2];
                    float v1 = acc[mi][nj][half * 2 + 1];
                    if (gnc < 512) {
                        float s0 = v0 / (1.f + __expf(-v0)) * eScale;
                        float s1 = v1 / (1.f + __expf(-v1)) * eScale;
                        *(__half2*)&Hout[(size_t)gm * 512 + gnc] = __floats2half2_rn(s0, s1);
                    } else {
                        float g0 = 1.f / (1.f + __expf(-v0));
                        float g1 = 1.f / (1.f + __expf(-v1));
                        *(float2*)&G[(size_t)gm * 256 + (gnc - 512)] = make_float2(g0, g1);
                    }
                }
            } else {
#pragma unroll
                for (int nj = 0; nj < 4; nj++) {
                    int gn = bn + warp_n * 32 + nj * 8 + tr * 2;
                    float2 gg = *(const float2*)&G[(size_t)gm * 256 + gn];
                    float v0 = acc[mi][nj][half * 2] * gg.x * eScale;
                    float v1 = acc[mi][nj][half * 2 + 1] * gg.y * eScale;
                    *(__half2*)&Hout[(size_t)gm * 256 + gn] = __floats2half2_rn(v0, v1);
                }
            }
        }
    }
}

// ---------------------------------------------------------------------------
// Batch-norm (planar)
// ---------------------------------------------------------------------------
__global__ void bn_partial_kernel(const float* __restrict__ O,
                                  float* __restrict__ psum, float* __restrict__ psq, int M)
{
    int p = threadIdx.x;
    float s = 0.f, sq = 0.f;
    if (p < 256) {
        for (int r = blockIdx.x; r < M; r += gridDim.x) {
            float x = O[(size_t)r * 256 + p];
            s += x; sq += x * x;
        }
        psum[blockIdx.x * 256 + p] = s;
    } else {
        int d = (p - 256) >> 7, o = (p - 256) & 127;
        const float* V = O + (size_t)M * 256 + (size_t)d * M * 128;
        for (int r = blockIdx.x; r < M; r += gridDim.x) {
            float x = V[(size_t)r * 128 + o];
            sq += x * x;
        }
    }
    psq[blockIdx.x * 640 + p] = sq;
}

__global__ void bn_final_kernel(const float* __restrict__ psum, const float* __restrict__ psq,
                                const float* __restrict__ w, const float* __restrict__ b,
                                float* __restrict__ scale, float* __restrict__ shift, int M)
{
    __shared__ float ssq[640];
    __shared__ float ssum[256];
    int p = threadIdx.x;
    float sq = 0.f;
    for (int q = 0; q < NPART; q++) sq += psq[q * 640 + p];
    ssq[p] = sq;
    if (p < 256) {
        float s = 0.f;
        for (int q = 0; q < NPART; q++) s += psum[q * 256 + p];
        ssum[p] = s;
    }
    __syncthreads();
    float invN = 1.f / (float)M;
    if (p < 256) {
        float m = ssum[p] * invN;
        float var = ssq[p] * invN - m * m;
        float inv = rsqrtf(var + 1e-5f);
        float sc = inv * w[p];
        scale[p] = sc;
        shift[p] = b[p] - m * sc;
    } else if (p < 256 + 128) {
        int ch = p - 256;
        float t = ssq[256 + ch] + ssq[256 + 128 + ch] + ssq[256 + 256 + ch];
        float mean = t * invN * (1.f / 3.f);
        float inv = rsqrtf(mean + 1e-5f);
        float sc = inv * w[256 + ch];
#pragma unroll
        for (int d = 0; d < 3; d++) {
            scale[256 + d * 128 + ch] = sc;
            shift[256 + d * 128 + ch] = 0.f;
        }
    }
}

__global__ void bn_apply_kernel(const float* __restrict__ O, float* __restrict__ out,
                                const float* __restrict__ scale,
                                const float* __restrict__ shift, int M)
{
    size_t idx = (size_t)blockIdx.x * blockDim.x + threadIdx.x;
    size_t total = (size_t)M * 160;
    if (idx >= total) return;
    int c4 = (int)(idx % 160) * 4;
    size_t r = idx / 160;
    float v[4];
#pragma unroll
    for (int j = 0; j < 4; j++) {
        int c = c4 + j;
        int p;
        float x;
        if (c < 256) {
            p = c;
            x = O[r * 256 + c];
        } else {
            int cc = c - 256;
            int o = cc / 3, d = cc % 3;
            p = 256 + d * 128 + o;
            x = O[(size_t)M * 256 + (size_t)d * M * 128 + r * 128 + o];
        }
        v[j] = x * scale[p] + shift[p];
    }
    *(float4*)&out[r * 640 + c4] = make_float4(v[0], v[1], v[2], v[3]);
}

// ---------------------------------------------------------------------------
extern "C" void kernel_launch(void* const* d_in, const int* in_sizes, int n_in,
                              void* d_out, int out_size)
{
    const float* features = (const float*)d_in[0];
    const float* W10 = (const float*)d_in[1];
    const float* W11 = (const float*)d_in[2];
    const float* W20 = (const float*)d_in[3];
    const float* W21 = (const float*)d_in[4];
    const float* W30 = (const float*)d_in[5];
    const float* W31 = (const float*)d_in[6];
    const float* B0  = (const float*)d_in[7];
    const float* B1  = (const float*)d_in[8];
    const float* bw  = (const float*)d_in[9];
    const float* bb  = (const float*)d_in[10];
    float* out = (float*)d_out;

    float *gg, *oo, *psum, *psq, *sc, *sh;
    __half *wb, *h, *ft;
    cudaGetSymbolAddress((void**)&gg, g_gate);
    cudaGetSymbolAddress((void**)&oo, g_o);
    cudaGetSymbolAddress((void**)&h, g_hbuf);
    cudaGetSymbolAddress((void**)&ft, g_feat);
    cudaGetSymbolAddress((void**)&psum, g_psum);
    cudaGetSymbolAddress((void**)&psq, g_psq);
    cudaGetSymbolAddress((void**)&sc, g_scale);
    cudaGetSymbolAddress((void**)&sh, g_shift);
    cudaGetSymbolAddress((void**)&wb, g_wbuf);

    const size_t M = MROWS;
    const float s512 = 0.04419417382415922f;
    const float s256 = 0.0625f;

    conv_w_all_kernel<<<(WTOT + 255) / 256, 256>>>(W10, W11, W20, W21, W30, B0, W31, B1,
                                                   wb, WTOT);
    {
        size_t tot = M * 640;
        conv_feat_kernel<<<(unsigned)((tot + 255) / 256), 256>>>(features, ft, (int)M);
    }

    const int gy = (int)((M + 127) / 128);
    cudaFuncSetAttribute(tc_gemm, cudaFuncAttributeMaxDynamicSharedMemorySize, SMEM_BYTES);

    __half* fs = ft;                    // [M,256], *s256
    __half* fv = ft + M * 256;          // 3 planes [M,128], *s128
    __half* hs0 = h;                    // [M,512]
    __half* hv0 = h + M * 512;          // 3 planes [M,256]
    __half* hs1 = h + M * 1280;         // [M,512]
    __half* hv1 = h + M * 1792;         // 3 planes [M,256]
    float* oS = oo;                     // planar scalar out [M,256]
    float* oV = oo + M * 256;           // 3 planes [M,128]

    // ---- layer 1 (gate fused): ft -> h0 ----
    tc_gemm<<<dim3(12, gy, 1), 256, SMEM_BYTES>>>(
        fs, 256, 0, fs, 256, 0, 256, wb + O10,
        oo, 0, 0, hs0, 0, gg, (int)M, 256, 1, s512);
    tc_gemm<<<dim3(4, gy, 3), 256, SMEM_BYTES>>>(
        fv, 128, M * 128, fv, 128, M * 128, 128, wb + O11,
        oo, 0, 0, hv0, M * 256, gg, (int)M, 128, 2, s256);
    // ---- layer 2 (gate fused): h0 -> h1 ----
    tc_gemm<<<dim3(12, gy, 1), 256, SMEM_BYTES>>>(
        hs0, 512, 0, hs0, 512, 0, 512, wb + O20,
        oo, 0, 0, hs1, 0, gg, (int)M, 512, 1, s512);
    tc_gemm<<<dim3(4, gy, 3), 256, SMEM_BYTES>>>(
        hv0, 256, M * 256, hv0, 256, M * 256, 256, wb + O21,
        oo, 0, 0, hv1, M * 256, gg, (int)M, 256, 2, s256);
    // ---- layer 3 + bypass (merged via K-concat): h1 (+ft) -> planar g_o ----
    tc_gemm<<<dim3(4, gy, 1), 256, SMEM_BYTES>>>(
        hs1, 512, 0, fs, 256, 0, 512, wb + OL3S,
        oS, 256, 0, hs1, 0, gg, (int)M, 768, 0, 1.f);
    tc_gemm<<<dim3(2, gy, 3), 256, SMEM_BYTES>>>(
        hv1, 256, M * 256, fv, 128, M * 128, 256, wb + OL3V,
        oV, 128, M * 128, hv1, 0, gg, (int)M, 384, 0, 1.f);

    // ---- batch norm (planar) ----
    bn_partial_kernel<<<NPART, 640>>>(oo, psum, psq, (int)M);
    bn_final_kernel<<<1, 640>>>(psum, psq, bw, bb, sc, sh, (int)M);
    {
        size_t total = M * 160;
        bn_apply_kernel<<<(unsigned)((total + 255) / 256), 256>>>(oo, out, sc, sh, (int)M);
    }
}

// round 17
// speedup vs baseline: 4.3378x; 1.0368x over previous
#include <cuda_runtime.h>
#include <cuda_fp16.h>
#include <cstdint>
#include <cstddef>

// ===========================================================================
// FeedForward via pure fp16 mma.sync, gate fused into GEMM epilogue.
// Block tile 128x64 (warp tile 32x32), BK=64, forced 4 CTAs/SM.
// ===========================================================================

#define MROWS 100000

// ------------------------------- scratch -----------------------------------
__device__ __half g_hbuf[(size_t)MROWS * 2560];   // h0 [M,1280] | h1 [M,1280]
__device__ __half g_feat[(size_t)MROWS * 640];    // fs [M,256] | fv[d] [M,128]
__device__ float g_gate[(size_t)MROWS * 256];     // sigmoid gate values
__device__ float g_o[(size_t)MROWS * 640];        // planar L3 out: S[M,256]|V[d][M,128]
#define NPART 512
__device__ float g_psum[NPART * 256];
__device__ float g_psq[NPART * 640];
__device__ float g_scale[640];
__device__ float g_shift[640];
#define WTOT 933888
__device__ __align__(256) __half g_wbuf[WTOT];

// weight block offsets (elements in g_wbuf)
#define O10  0        // [768,256]
#define O11  196608   // [256,128]
#define O20  229376   // [768,512]
#define O21  622592   // [256,256]
#define OL3S 688128   // [256,768]  = [W30 | B0] merged, ld 768
#define OL3V 884736   // [128,384]  = [W31 | B1] merged, ld 384

__constant__ int c_wseg[8][6] = {
    {256, 768, O10,  256, 0,   0},
    {128, 256, O11,  128, 0,   196608},
    {512, 768, O20,  512, 0,   229376},
    {256, 256, O21,  256, 0,   622592},
    {512, 256, OL3S, 768, 0,   688128},
    {256, 256, OL3S, 768, 512, 819200},
    {256, 128, OL3V, 384, 0,   884736},
    {128, 128, OL3V, 384, 256, 917504}};

// --------------------------- helpers ---------------------------------------
__device__ __forceinline__ uint32_t smem_to_u32(const void* p) {
    uint32_t a;
    asm("{ .reg .u64 t; cvta.to.shared.u64 t, %1; cvt.u32.u64 %0, t; }" : "=r"(a) : "l"(p));
    return a;
}
__device__ __forceinline__ void ldm4(uint32_t& r0, uint32_t& r1, uint32_t& r2, uint32_t& r3,
                                     uint32_t addr) {
    asm volatile("ldmatrix.sync.aligned.m8n8.x4.shared.b16 {%0,%1,%2,%3}, [%4];"
                 : "=r"(r0), "=r"(r1), "=r"(r2), "=r"(r3) : "r"(addr));
}
__device__ __forceinline__ void mma16816(float* c, const uint32_t* a, const uint32_t* b) {
    asm volatile(
        "mma.sync.aligned.m16n8k16.row.col.f32.f16.f16.f32 "
        "{%0,%1,%2,%3}, {%4,%5,%6,%7}, {%8,%9}, {%0,%1,%2,%3};"
        : "+f"(c[0]), "+f"(c[1]), "+f"(c[2]), "+f"(c[3])
        : "r"(a[0]), "r"(a[1]), "r"(a[2]), "r"(a[3]), "r"(b[0]), "r"(b[1]));
}
#define CP_ASYNC16(dst, src, sz) \
    asm volatile("cp.async.cg.shared.global [%0], [%1], 16, %2;" \
                 :: "r"(dst), "l"(src), "r"(sz) : "memory")
#define CP_COMMIT asm volatile("cp.async.commit_group;" ::: "memory")
#define CP_WAIT0 asm volatile("cp.async.wait_group 0;" ::: "memory")

// ---------------------------------------------------------------------------
// Weight prep (single launch)
// ---------------------------------------------------------------------------
__global__ void conv_w_all_kernel(const float* __restrict__ W10, const float* __restrict__ W11,
                                  const float* __restrict__ W20, const float* __restrict__ W21,
                                  const float* __restrict__ W30, const float* __restrict__ B0,
                                  const float* __restrict__ W31, const float* __restrict__ B1,
                                  __half* __restrict__ wb, int total) {
    int idx = blockIdx.x * blockDim.x + threadIdx.x;
    if (idx >= total) return;
    const float* srcs[8] = {W10, W11, W20, W21, W30, B0, W31, B1};
    int s = 0;
#pragma unroll
    for (int i = 1; i < 8; i++)
        if (idx >= c_wseg[i][5]) s = i;
    int K = c_wseg[s][0];
    int loc = idx - c_wseg[s][5];
    int n = loc / K, k = loc % K;
    int N = c_wseg[s][1];
    size_t dst = (size_t)n * c_wseg[s][3] + c_wseg[s][4] + k + c_wseg[s][2];
    wb[dst] = __float2half_rn(srcs[s][(size_t)k * N + n]);
}

// ---------------------------------------------------------------------------
// Features -> plane-major fp16, scale folded
// ---------------------------------------------------------------------------
__global__ void conv_feat_kernel(const float* __restrict__ F, __half* __restrict__ out,
                                 int M) {
    size_t idx = (size_t)blockIdx.x * blockDim.x + threadIdx.x;
    size_t total = (size_t)M * 640;
    if (idx >= total) return;
    int c = (int)(idx % 640);
    size_t r = idx / 640;
    const float s256 = 0.0625f;
    const float s128 = 0.08838834764831845f;
    float v;
    size_t off;
    if (c < 256) {
        v = F[r * 640 + c] * s256;
        off = r * 256 + c;
    } else {
        int t = c - 256;
        int d = t / 128, o = t % 128;
        v = F[r * 640 + 256 + o * 3 + d] * s128;
        off = (size_t)M * 256 + (size_t)d * M * 128 + r * 128 + o;
    }
    out[off] = __float2half_rn(v);
}

// ---------------------------------------------------------------------------
// HMMA GEMM: block 128x64, BK=64, warp tile 32x32, 2-stage cp.async, 4 CTA/SM.
// ---------------------------------------------------------------------------
#define SAA 72                      // smem row stride (halfs), 144 B
#define A_BY (128 * SAA * 2)        // 18432
#define B_BY (64 * SAA * 2)         // 9216
#define STAGE_BYTES (A_BY + B_BY)   // 27648
#define SMEM_BYTES (2 * STAGE_BYTES)// 55296

__global__ __launch_bounds__(256, 4) void tc_gemm(
    const __half* __restrict__ A, int lda, size_t aPlane,
    const __half* __restrict__ A2, int lda2, size_t aPlane2, int K1,
    const __half* __restrict__ B,
    float* __restrict__ C, int ldc, size_t cPlane,
    __half* __restrict__ Hout, size_t hPlane,
    float* __restrict__ G,
    int M, int K, int mode, float eScale)
{
    extern __shared__ char smem[];
    const uint32_t sb = smem_to_u32(smem);

    const int tid = threadIdx.x;
    const int wid = tid >> 5;
    const int lane = tid & 31;
    const int warp_m = wid & 3;     // 4 x 32 rows
    const int warp_n = wid >> 2;    // 2 x 32 cols
    const int bm = blockIdx.y * 128;
    const int bn = blockIdx.x * 64;
    const int z = blockIdx.z;
    A    += (size_t)z * aPlane;
    A2   += (size_t)z * aPlane2;
    C    += (size_t)z * cPlane;
    Hout += (size_t)z * hPlane;

    const int quad = lane >> 3;
    const int rsel = (lane & 7) + ((quad & 1) << 3);
    const int ksel = (quad >> 1) << 3;

    float acc[2][4][4];
#pragma unroll
    for (int mi = 0; mi < 2; mi++)
#pragma unroll
        for (int nj = 0; nj < 4; nj++)
#pragma unroll
            for (int r = 0; r < 4; r++) acc[mi][nj][r] = 0.f;

    const int nkt = K / 64;

    auto prefetch = [&](int kt, int st) {
        int k0 = kt * 64;
        const __half* pA;
        int plda, kk;
        if (k0 < K1) { pA = A;  plda = lda;  kk = k0; }
        else         { pA = A2; plda = lda2; kk = k0 - K1; }
        const uint32_t base = sb + st * STAGE_BYTES;
        // A: 128 rows x 8 chunks of 16B
#pragma unroll
        for (int i = 0; i < 4; i++) {
            int t = tid + i * 256;
            int row = t >> 3, c = t & 7;
            int gm = bm + row;
            const __half* src = pA + (size_t)gm * plda + kk + c * 8;
            uint32_t dst = base + (uint32_t)(row * SAA) * 2 + c * 16;
            int sz = (gm < M) ? 16 : 0;
            CP_ASYNC16(dst, src, sz);
        }
        // B: 64 n-rows x 8 chunks of 16B
#pragma unroll
        for (int i = 0; i < 2; i++) {
            int t = tid + i * 256;
            int row = t >> 3, c = t & 7;
            const __half* src = B + (size_t)(bn + row) * K + k0 + c * 8;
            uint32_t dst = base + A_BY + (uint32_t)(row * SAA) * 2 + c * 16;
            CP_ASYNC16(dst, src, 16);
        }
    };

    prefetch(0, 0);
    CP_COMMIT;

    for (int kt = 0; kt < nkt; kt++) {
        CP_WAIT0;
        __syncthreads();
        if (kt + 1 < nkt) { prefetch(kt + 1, (kt + 1) & 1); CP_COMMIT; }

        const uint32_t sbase = sb + (kt & 1) * STAGE_BYTES;
        const uint32_t aAddr0 = sbase + (uint32_t)((warp_m * 32 + rsel) * SAA + ksel) * 2;
        const uint32_t aAddr1 = aAddr0 + 16 * SAA * 2;
        const uint32_t bAddr0 = sbase + A_BY + (uint32_t)((warp_n * 32 + rsel) * SAA + ksel) * 2;
        const uint32_t bAddr1 = bAddr0 + 16 * SAA * 2;

#pragma unroll
        for (int ks = 0; ks < 4; ks++) {
            const uint32_t kof = ks * 32;
            uint32_t af0[4], af1[4];
            ldm4(af0[0], af0[1], af0[2], af0[3], aAddr0 + kof);
            ldm4(af1[0], af1[1], af1[2], af1[3], aAddr1 + kof);
            uint32_t bf[4][2];
            {
                uint32_t r0, r1, r2, r3;
                ldm4(r0, r1, r2, r3, bAddr0 + kof);
                bf[0][0] = r0; bf[1][0] = r1; bf[0][1] = r2; bf[1][1] = r3;
                ldm4(r0, r1, r2, r3, bAddr1 + kof);
                bf[2][0] = r0; bf[3][0] = r1; bf[2][1] = r2; bf[3][1] = r3;
            }
#pragma unroll
            for (int mi = 0; mi < 2; mi++)
#pragma unroll
                for (int nj = 0; nj < 4; nj++)
                    mma16816(acc[mi][nj], mi ? af1 : af0, bf[nj]);
        }
    }

    // ---- epilogue ----
    const int tq = lane >> 2;
    const int tr = lane & 3;
#pragma unroll
    for (int mi = 0; mi < 2; mi++) {
#pragma unroll
        for (int half = 0; half < 2; half++) {
            int gm = bm + warp_m * 32 + mi * 16 + tq + half * 8;
            if (gm >= M) continue;
            if (mode == 0) {
                float* Crow = C + (size_t)gm * ldc + bn + warp_n * 32;
#pragma unroll
                for (int nj = 0; nj < 4; nj++) {
                    int cn = nj * 8 + tr * 2;
                    *(float2*)&Crow[cn] =
                        make_float2(acc[mi][nj][half * 2], acc[mi][nj][half * 2 + 1]);
                }
            } else if (mode == 1) {
#pragma unroll
                for (int nj = 0; nj < 4; nj++) {
                    int gnc = bn + warp_n * 32 + nj * 8 + tr * 2;
                    float v0 = acc[mi][nj][half * 2];
                    float v1 = acc[mi][nj][half * 2 + 1];
                    if (gnc < 512) {
                        float s0 = v0 / (1.f + __expf(-v0)) * eScale;
                        float s1 = v1 / (1.f + __expf(-v1)) * eScale;
                        *(__half2*)&Hout[(size_t)gm * 512 + gnc] = __floats2half2_rn(s0, s1);
                    } else {
                        float g0 = 1.f / (1.f + __expf(-v0));
                        float g1 = 1.f / (1.f + __expf(-v1));
                        *(float2*)&G[(size_t)gm * 256 + (gnc - 512)] = make_float2(g0, g1);
                    }
                }
            } else {
#pragma unroll
                for (int nj = 0; nj < 4; nj++) {
                    int gn = bn + warp_n * 32 + nj * 8 + tr * 2;
                    float2 gg = *(const float2*)&G[(size_t)gm * 256 + gn];
                    float v0 = acc[mi][nj][half * 2] * gg.x * eScale;
                    float v1 = acc[mi][nj][half * 2 + 1] * gg.y * eScale;
                    *(__half2*)&Hout[(size_t)gm * 256 + gn] = __floats2half2_rn(v0, v1);
                }
            }
        }
    }
}

// ---------------------------------------------------------------------------
// Batch-norm (planar)
// ---------------------------------------------------------------------------
__global__ void bn_partial_kernel(const float* __restrict__ O,
                                  float* __restrict__ psum, float* __restrict__ psq, int M)
{
    int p = threadIdx.x;
    float s = 0.f, sq = 0.f;
    if (p < 256) {
        for (int r = blockIdx.x; r < M; r += gridDim.x) {
            float x = O[(size_t)r * 256 + p];
            s += x; sq += x * x;
        }
        psum[blockIdx.x * 256 + p] = s;
    } else {
        int d = (p - 256) >> 7, o = (p - 256) & 127;
        const float* V = O + (size_t)M * 256 + (size_t)d * M * 128;
        for (int r = blockIdx.x; r < M; r += gridDim.x) {
            float x = V[(size_t)r * 128 + o];
            sq += x * x;
        }
    }
    psq[blockIdx.x * 640 + p] = sq;
}

__global__ void bn_final_kernel(const float* __restrict__ psum, const float* __restrict__ psq,
                                const float* __restrict__ w, const float* __restrict__ b,
                                float* __restrict__ scale, float* __restrict__ shift, int M)
{
    __shared__ float ssq[640];
    __shared__ float ssum[256];
    int p = threadIdx.x;
    float sq = 0.f;
    for (int q = 0; q < NPART; q++) sq += psq[q * 640 + p];
    ssq[p] = sq;
    if (p < 256) {
        float s = 0.f;
        for (int q = 0; q < NPART; q++) s += psum[q * 256 + p];
        ssum[p] = s;
    }
    __syncthreads();
    float invN = 1.f / (float)M;
    if (p < 256) {
        float m = ssum[p] * invN;
        float var = ssq[p] * invN - m * m;
        float inv = rsqrtf(var + 1e-5f);
        float sc = inv * w[p];
        scale[p] = sc;
        shift[p] = b[p] - m * sc;
    } else if (p < 256 + 128) {
        int ch = p - 256;
        float t = ssq[256 + ch] + ssq[256 + 128 + ch] + ssq[256 + 256 + ch];
        float mean = t * invN * (1.f / 3.f);
        float inv = rsqrtf(mean + 1e-5f);
        float sc = inv * w[256 + ch];
#pragma unroll
        for (int d = 0; d < 3; d++) {
            scale[256 + d * 128 + ch] = sc;
            shift[256 + d * 128 + ch] = 0.f;
        }
    }
}

__global__ void bn_apply_kernel(const float* __restrict__ O, float* __restrict__ out,
                                const float* __restrict__ scale,
                                const float* __restrict__ shift, int M)
{
    size_t idx = (size_t)blockIdx.x * blockDim.x + threadIdx.x;
    size_t total = (size_t)M * 160;
    if (idx >= total) return;
    int c4 = (int)(idx % 160) * 4;
    size_t r = idx / 160;
    float v[4];
#pragma unroll
    for (int j = 0; j < 4; j++) {
        int c = c4 + j;
        int p;
        float x;
        if (c < 256) {
            p = c;
            x = O[r * 256 + c];
        } else {
            int cc = c - 256;
            int o = cc / 3, d = cc % 3;
            p = 256 + d * 128 + o;
            x = O[(size_t)M * 256 + (size_t)d * M * 128 + r * 128 + o];
        }
        v[j] = x * scale[p] + shift[p];
    }
    *(float4*)&out[r * 640 + c4] = make_float4(v[0], v[1], v[2], v[3]);
}

// ---------------------------------------------------------------------------
extern "C" void kernel_launch(void* const* d_in, const int* in_sizes, int n_in,
                              void* d_out, int out_size)
{
    const float* features = (const float*)d_in[0];
    const float* W10 = (const float*)d_in[1];
    const float* W11 = (const float*)d_in[2];
    const float* W20 = (const float*)d_in[3];
    const float* W21 = (const float*)d_in[4];
    const float* W30 = (const float*)d_in[5];
    const float* W31 = (const float*)d_in[6];
    const float* B0  = (const float*)d_in[7];
    const float* B1  = (const float*)d_in[8];
    const float* bw  = (const float*)d_in[9];
    const float* bb  = (const float*)d_in[10];
    float* out = (float*)d_out;

    float *gg, *oo, *psum, *psq, *sc, *sh;
    __half *wb, *h, *ft;
    cudaGetSymbolAddress((void**)&gg, g_gate);
    cudaGetSymbolAddress((void**)&oo, g_o);
    cudaGetSymbolAddress((void**)&h, g_hbuf);
    cudaGetSymbolAddress((void**)&ft, g_feat);
    cudaGetSymbolAddress((void**)&psum, g_psum);
    cudaGetSymbolAddress((void**)&psq, g_psq);
    cudaGetSymbolAddress((void**)&sc, g_scale);
    cudaGetSymbolAddress((void**)&sh, g_shift);
    cudaGetSymbolAddress((void**)&wb, g_wbuf);

    const size_t M = MROWS;
    const float s512 = 0.04419417382415922f;
    const float s256 = 0.0625f;

    conv_w_all_kernel<<<(WTOT + 255) / 256, 256>>>(W10, W11, W20, W21, W30, B0, W31, B1,
                                                   wb, WTOT);
    {
        size_t tot = M * 640;
        conv_feat_kernel<<<(unsigned)((tot + 255) / 256), 256>>>(features, ft, (int)M);
    }

    const int gy = (int)((M + 127) / 128);
    cudaFuncSetAttribute(tc_gemm, cudaFuncAttributeMaxDynamicSharedMemorySize, SMEM_BYTES);

    __half* fs = ft;                    // [M,256], *s256
    __half* fv = ft + M * 256;          // 3 planes [M,128], *s128
    __half* hs0 = h;                    // [M,512]
    __half* hv0 = h + M * 512;          // 3 planes [M,256]
    __half* hs1 = h + M * 1280;         // [M,512]
    __half* hv1 = h + M * 1792;         // 3 planes [M,256]
    float* oS = oo;                     // planar scalar out [M,256]
    float* oV = oo + M * 256;           // 3 planes [M,128]

    // ---- layer 1 (gate fused): ft -> h0 ----
    tc_gemm<<<dim3(12, gy, 1), 256, SMEM_BYTES>>>(
        fs, 256, 0, fs, 256, 0, 256, wb + O10,
        oo, 0, 0, hs0, 0, gg, (int)M, 256, 1, s512);
    tc_gemm<<<dim3(4, gy, 3), 256, SMEM_BYTES>>>(
        fv, 128, M * 128, fv, 128, M * 128, 128, wb + O11,
        oo, 0, 0, hv0, M * 256, gg, (int)M, 128, 2, s256);
    // ---- layer 2 (gate fused): h0 -> h1 ----
    tc_gemm<<<dim3(12, gy, 1), 256, SMEM_BYTES>>>(
        hs0, 512, 0, hs0, 512, 0, 512, wb + O20,
        oo, 0, 0, hs1, 0, gg, (int)M, 512, 1, s512);
    tc_gemm<<<dim3(4, gy, 3), 256, SMEM_BYTES>>>(
        hv0, 256, M * 256, hv0, 256, M * 256, 256, wb + O21,
        oo, 0, 0, hv1, M * 256, gg, (int)M, 256, 2, s256);
    // ---- layer 3 + bypass (merged via K-concat): h1 (+ft) -> planar g_o ----
    tc_gemm<<<dim3(4, gy, 1), 256, SMEM_BYTES>>>(
        hs1, 512, 0, fs, 256, 0, 512, wb + OL3S,
        oS, 256, 0, hs1, 0, gg, (int)M, 768, 0, 1.f);
    tc_gemm<<<dim3(2, gy, 3), 256, SMEM_BYTES>>>(
        hv1, 256, M * 256, fv, 128, M * 128, 256, wb + OL3V,
        oV, 128, M * 128, hv1, 0, gg, (int)M, 384, 0, 1.f);

    // ---- batch norm (planar) ----
    bn_partial_kernel<<<NPART, 640>>>(oo, psum, psq, (int)M);
    bn_final_kernel<<<1, 640>>>(psum, psq, bw, bb, sc, sh, (int)M);
    {
        size_t total = M * 160;
        bn_apply_kernel<<<(unsigned)((total + 255) / 256), 256>>>(oo, out, sc, sh, (int)M);
    }
}